// round 2
// baseline (speedup 1.0000x reference)
#include <cuda_runtime.h>
#include <math.h>

#define BB 4
#define TT 2048
#define HH 4
#define DD 1024
#define BT (BB*TT)

__device__ float g_Q[BT*DD], g_K[BT*DD], g_V[BT*DD], g_G[BT*DD];
__device__ float g_E[BT*DD], g_ACC[BT*DD], g_U[BT*DD], g_ACT[BT*DD];
__device__ float g_XSG[BT*HH], g_LAM[BB*HH*TT];

// C[M,N] = A[M,K] @ B[K,N], row-major, M%128==0, N%128==0, K%8==0
__global__ __launch_bounds__(256)
void sgemm_k(const float* __restrict__ A, const float* __restrict__ B,
             float* __restrict__ C, int M, int N, int K)
{
    __shared__ float As[8][128];
    __shared__ float Bs[8][128];
    const int tid = threadIdx.x;
    const float* Ab = A + (size_t)blockIdx.y * 128 * K;
    const float* Bb = B + (size_t)blockIdx.x * 128;
    float*       Cb = C + (size_t)blockIdx.y * 128 * N + (size_t)blockIdx.x * 128;
    const int aRow = tid >> 1, aCol = (tid & 1) * 4;
    const int bRow = tid >> 5, bCol = (tid & 31) * 4;
    const int tr = tid >> 4, tc = tid & 15;

    float acc[8][8];
#pragma unroll
    for (int i = 0; i < 8; i++)
#pragma unroll
        for (int j = 0; j < 8; j++) acc[i][j] = 0.f;

    for (int bk = 0; bk < K; bk += 8) {
        float4 a = *(const float4*)(Ab + (size_t)aRow * K + bk + aCol);
        As[aCol+0][aRow] = a.x; As[aCol+1][aRow] = a.y;
        As[aCol+2][aRow] = a.z; As[aCol+3][aRow] = a.w;
        *(float4*)&Bs[bRow][bCol] = *(const float4*)(Bb + (size_t)(bk + bRow) * N + bCol);
        __syncthreads();
#pragma unroll
        for (int k = 0; k < 8; k++) {
            float rm[8], rn[8];
            *(float4*)&rm[0] = *(float4*)&As[k][tr*8];
            *(float4*)&rm[4] = *(float4*)&As[k][tr*8+4];
            *(float4*)&rn[0] = *(float4*)&Bs[k][tc*8];
            *(float4*)&rn[4] = *(float4*)&Bs[k][tc*8+4];
#pragma unroll
            for (int i = 0; i < 8; i++)
#pragma unroll
                for (int j = 0; j < 8; j++) acc[i][j] += rm[i] * rn[j];
        }
        __syncthreads();
    }
#pragma unroll
    for (int i = 0; i < 8; i++) {
        int row = tr*8 + i;
        *(float4*)(Cb + (size_t)row*N + tc*8)   = make_float4(acc[i][0],acc[i][1],acc[i][2],acc[i][3]);
        *(float4*)(Cb + (size_t)row*N + tc*8+4) = make_float4(acc[i][4],acc[i][5],acc[i][6],acc[i][7]);
    }
}

// O[8192,4] = X[8192,1024] @ W[1024,4]; one warp per row
__global__ void sgemm_n4(const float* __restrict__ X, const float* __restrict__ W,
                         float* __restrict__ O)
{
    const int warp = threadIdx.x >> 5, lane = threadIdx.x & 31;
    const int row = blockIdx.x * 8 + warp;
    const float* x = X + (size_t)row * DD;
    float a0=0.f, a1=0.f, a2=0.f, a3=0.f;
    for (int k = lane; k < DD; k += 32) {
        float xv = x[k];
        float4 w = *(const float4*)(W + k*4);
        a0 += xv*w.x; a1 += xv*w.y; a2 += xv*w.z; a3 += xv*w.w;
    }
#pragma unroll
    for (int o = 16; o; o >>= 1) {
        a0 += __shfl_xor_sync(0xffffffffu, a0, o);
        a1 += __shfl_xor_sync(0xffffffffu, a1, o);
        a2 += __shfl_xor_sync(0xffffffffu, a2, o);
        a3 += __shfl_xor_sync(0xffffffffu, a3, o);
    }
    if (lane == 0) *(float4*)(O + row*4) = make_float4(a0,a1,a2,a3);
}

// LAM[b,h,t] = exp(inclusive_cumsum_t(log_sigmoid(XSG[b,t,h]) / 16))
__global__ void lam_kernel(const float* __restrict__ XSG, float* __restrict__ LAM)
{
    const int b = blockIdx.x >> 2, h = blockIdx.x & 3;
    const int tid = threadIdx.x;
    __shared__ float ssum[256];
    float loc[8], run = 0.f;
    const int t0 = tid * 8;
#pragma unroll
    for (int u = 0; u < 8; u++) {
        float x = XSG[(size_t)(b*TT + t0 + u) * HH + h];
        float lg = (x >= 0.f) ? -log1pf(expf(-x)) : (x - log1pf(expf(x)));
        run += lg * (1.f/16.f);
        loc[u] = run;
    }
    ssum[tid] = run;
    __syncthreads();
    for (int off = 1; off < 256; off <<= 1) {
        float v = (tid >= off) ? ssum[tid-off] : 0.f;
        __syncthreads();
        ssum[tid] += v;
        __syncthreads();
    }
    float excl = ssum[tid] - run;
#pragma unroll
    for (int u = 0; u < 8; u++)
        LAM[(size_t)(b*HH + h)*TT + t0 + u] = expf(excl + loc[u]);
}

// in-place RoPE: Q scaled by 1/16 (dk^-0.5), K scaled by LAM
__global__ void rope_decay_kernel(float* __restrict__ Q, float* __restrict__ K,
                                  const float* __restrict__ LAM)
{
    const int idx = blockIdx.x * 256 + threadIdx.x;
    const int i = idx & 127;
    const int h = (idx >> 7) & 3;
    const int t = (idx >> 9) & 2047;
    const int b = idx >> 20;
    float inv = powf(10000.f, -(float)i * (1.f/128.f));
    float sn, cs;
    sincosf((float)t * inv, &sn, &cs);
    const size_t base = ((size_t)(b*TT + t)*HH + h) * 256;
    float q1 = Q[base+i], q2 = Q[base+i+128];
    Q[base+i]     = (q1*cs - q2*sn) * 0.0625f;
    Q[base+i+128] = (q2*cs + q1*sn) * 0.0625f;
    float lam = LAM[(size_t)(b*HH + h)*TT + t];
    float k1 = K[base+i], k2 = K[base+i+128];
    K[base+i]     = (k1*cs - k2*sn) * lam;
    K[base+i+128] = (k2*cs + k1*sn) * lam;
}

// E = exp(clip(s)) in place; ACC = inclusive cumsum over t
__global__ void scan_s_kernel(float* __restrict__ E, float* __restrict__ ACC)
{
    const int b = blockIdx.x >> 2, h = blockIdx.x & 3;
    const int ml = threadIdx.x & 31;
    const int tc = threadIdx.x >> 5;
    const int m = blockIdx.y * 32 + ml;
    __shared__ float sums[8][33];
    const size_t base = (size_t)b * TT * DD + h * 256 + m;
    float acc = 0.f;
    for (int tt = 0; tt < 256; tt++) {
        const size_t idx = base + (size_t)(tc*256 + tt) * DD;
        float s = fminf(fmaxf(E[idx], -32.f), 32.f);
        float e = expf(s);
        E[idx] = e;
        acc += e;
    }
    sums[tc][ml] = acc;
    __syncthreads();
    float a = 0.f;
    for (int p = 0; p < tc; p++) a += sums[p][ml];
    for (int tt = 0; tt < 256; tt++) {
        const size_t idx = base + (size_t)(tc*256 + tt) * DD;
        a += E[idx];
        ACC[idx] = a;
    }
}

// Causal pass. PASS0: A=Q.K^T, out = softmax_m(A.E/ACC)/ACC -> U
// PASS1: A=U.E^T, o=A.V, out = rms(o)*gn*g*sigmoid(g) -> ACT
#define SM_QS 0
#define SM_KS (16*68)
#define SM_AS (2*16*68)
#define SM_ES (2*16*68 + 64*68)
#define ATTN_SMEM_FLOATS (2*16*68 + 64*68 + 64*260)
#define ATTN_SMEM_BYTES  (ATTN_SMEM_FLOATS * 4)

template <int PASS>
__global__ __launch_bounds__(256)
void attn_pass_kernel(const float* __restrict__ Qp, const float* __restrict__ Kp,
                      const float* __restrict__ Ep, const float* __restrict__ ACCp,
                      const float* __restrict__ Gp, const float* __restrict__ gnw,
                      float* __restrict__ Outp)
{
    extern __shared__ float sm[];
    float* Qs = sm + SM_QS;
    float* Ks = sm + SM_KS;
    float* As = sm + SM_AS;
    float* Es = sm + SM_ES;

    const int tid = threadIdx.x;
    const int qi = gridDim.x - 1 - blockIdx.x;   // longest tiles first
    const int b = blockIdx.y >> 2, h = blockIdx.y & 3;
    const int qBase = qi * 64;
    const size_t baseBT = (size_t)b * TT * DD + h * 256;

    const int trA = tid >> 4, tcA = tid & 15;
    const int trE = tid >> 5, tcE = tid & 31;
    const int lr = tid >> 2, lc4 = (tid & 3) * 4;

    float ok[8][8];
#pragma unroll
    for (int i = 0; i < 8; i++)
#pragma unroll
        for (int j = 0; j < 8; j++) ok[i][j] = 0.f;

    for (int kc = 0; kc <= qi; kc++) {
        const int kBase = kc * 64;
        float aa[4][4];
#pragma unroll
        for (int i = 0; i < 4; i++)
#pragma unroll
            for (int j = 0; j < 4; j++) aa[i][j] = 0.f;

        for (int ds = 0; ds < 256; ds += 16) {
            __syncthreads();
            float4 qv = *(const float4*)(Qp + baseBT + (size_t)(qBase+lr)*DD + ds + lc4);
            float4 kv = *(const float4*)(Kp + baseBT + (size_t)(kBase+lr)*DD + ds + lc4);
            Qs[(lc4+0)*68 + lr] = qv.x; Qs[(lc4+1)*68 + lr] = qv.y;
            Qs[(lc4+2)*68 + lr] = qv.z; Qs[(lc4+3)*68 + lr] = qv.w;
            Ks[(lc4+0)*68 + lr] = kv.x; Ks[(lc4+1)*68 + lr] = kv.y;
            Ks[(lc4+2)*68 + lr] = kv.z; Ks[(lc4+3)*68 + lr] = kv.w;
            __syncthreads();
#pragma unroll
            for (int k = 0; k < 16; k++) {
                float4 q4 = *(const float4*)&Qs[k*68 + trA*4];
                float4 k4 = *(const float4*)&Ks[k*68 + tcA*4];
                aa[0][0] += q4.x*k4.x; aa[0][1] += q4.x*k4.y; aa[0][2] += q4.x*k4.z; aa[0][3] += q4.x*k4.w;
                aa[1][0] += q4.y*k4.x; aa[1][1] += q4.y*k4.y; aa[1][2] += q4.y*k4.z; aa[1][3] += q4.y*k4.w;
                aa[2][0] += q4.z*k4.x; aa[2][1] += q4.z*k4.y; aa[2][2] += q4.z*k4.z; aa[2][3] += q4.z*k4.w;
                aa[3][0] += q4.w*k4.x; aa[3][1] += q4.w*k4.y; aa[3][2] += q4.w*k4.z; aa[3][3] += q4.w*k4.w;
            }
        }
        __syncthreads();

        const bool diag = (kc == qi);
#pragma unroll
        for (int i = 0; i < 4; i++)
#pragma unroll
            for (int j = 0; j < 4; j++) {
                float v = aa[i][j];
                if (diag && (tcA*4 + j) > (trA*4 + i)) v = 0.f;
                As[(tcA*4 + j)*68 + trA*4 + i] = v;   // A^T
            }
        {
            const int ec = (tid & 63) * 4;
            const int er0 = (tid >> 6) * 16;
#pragma unroll
            for (int it = 0; it < 16; it++)
                *(float4*)&Es[(er0+it)*260 + ec] =
                    *(const float4*)(Ep + baseBT + (size_t)(kBase+er0+it)*DD + ec);
        }
        __syncthreads();

#pragma unroll 2
        for (int kk = 0; kk < 64; kk++) {
            float a8[8], e8[8];
            *(float4*)&a8[0] = *(float4*)&As[kk*68 + trE*8];
            *(float4*)&a8[4] = *(float4*)&As[kk*68 + trE*8 + 4];
            *(float4*)&e8[0] = *(float4*)&Es[kk*260 + tcE*8];
            *(float4*)&e8[4] = *(float4*)&Es[kk*260 + tcE*8 + 4];
#pragma unroll
            for (int i = 0; i < 8; i++)
#pragma unroll
                for (int j = 0; j < 8; j++) ok[i][j] += a8[i] * e8[j];
        }
    }

    // epilogue: warp trE owns rows qBase+trE*8 .. +7, lanes cover 256 cols
#pragma unroll
    for (int i = 0; i < 8; i++) {
        const int t = qBase + trE*8 + i;
        const size_t rb = baseBT + (size_t)t * DD;
        if (PASS == 0) {
            float acr[8], v[8];
            float mx = -3.4e38f;
#pragma unroll
            for (int j = 0; j < 8; j++) {
                acr[j] = ACCp[rb + tcE*8 + j];
                v[j] = ok[i][j] / acr[j];
                mx = fmaxf(mx, v[j]);
            }
#pragma unroll
            for (int o = 16; o; o >>= 1) mx = fmaxf(mx, __shfl_xor_sync(0xffffffffu, mx, o));
            float e[8], s = 0.f;
#pragma unroll
            for (int j = 0; j < 8; j++) { e[j] = expf(v[j] - mx); s += e[j]; }
#pragma unroll
            for (int o = 16; o; o >>= 1) s += __shfl_xor_sync(0xffffffffu, s, o);
            const float inv = 1.f / s;
#pragma unroll
            for (int j = 0; j < 8; j++)
                Outp[rb + tcE*8 + j] = e[j] * inv / acr[j];
        } else {
            float ss = 0.f;
#pragma unroll
            for (int j = 0; j < 8; j++) ss += ok[i][j] * ok[i][j];
#pragma unroll
            for (int o = 16; o; o >>= 1) ss += __shfl_xor_sync(0xffffffffu, ss, o);
            const float rn = rsqrtf(ss * (1.f/256.f) + 1e-5f);
#pragma unroll
            for (int j = 0; j < 8; j++) {
                const int dv = tcE*8 + j;
                float gg = Gp[rb + dv];
                float sig = 1.f / (1.f + expf(-gg));
                Outp[rb + dv] = ok[i][j] * rn * gnw[dv] * gg * sig;
            }
        }
    }
}

extern "C" void kernel_launch(void* const* d_in, const int* in_sizes, int n_in,
                              void* d_out, int out_size)
{
    const float* x   = (const float*)d_in[0];
    const float* qw  = (const float*)d_in[1];
    const float* kw  = (const float*)d_in[2];
    const float* vw  = (const float*)d_in[3];
    const float* gw  = (const float*)d_in[4];
    const float* sw  = (const float*)d_in[5];
    const float* sgw = (const float*)d_in[6];
    const float* gnw = (const float*)d_in[7];
    const float* ow  = (const float*)d_in[8];
    float* out = (float*)d_out;

    float *Q, *K, *V, *G, *E, *ACC, *U, *ACT, *XSG, *LAM;
    cudaGetSymbolAddress((void**)&Q,   g_Q);
    cudaGetSymbolAddress((void**)&K,   g_K);
    cudaGetSymbolAddress((void**)&V,   g_V);
    cudaGetSymbolAddress((void**)&G,   g_G);
    cudaGetSymbolAddress((void**)&E,   g_E);
    cudaGetSymbolAddress((void**)&ACC, g_ACC);
    cudaGetSymbolAddress((void**)&U,   g_U);
    cudaGetSymbolAddress((void**)&ACT, g_ACT);
    cudaGetSymbolAddress((void**)&XSG, g_XSG);
    cudaGetSymbolAddress((void**)&LAM, g_LAM);

    static int attr_done = 0;
    if (!attr_done) {
        cudaFuncSetAttribute(attn_pass_kernel<0>,
            cudaFuncAttributeMaxDynamicSharedMemorySize, ATTN_SMEM_BYTES);
        cudaFuncSetAttribute(attn_pass_kernel<1>,
            cudaFuncAttributeMaxDynamicSharedMemorySize, ATTN_SMEM_BYTES);
        attr_done = 1;
    }

    dim3 gg(DD/128, BT/128);
    sgemm_k<<<gg, 256>>>(x, qw, Q, BT, DD, DD);
    sgemm_k<<<gg, 256>>>(x, kw, K, BT, DD, DD);
    sgemm_k<<<gg, 256>>>(x, vw, V, BT, DD, DD);
    sgemm_k<<<gg, 256>>>(x, gw, G, BT, DD, DD);
    sgemm_k<<<gg, 256>>>(x, sw, E, BT, DD, DD);
    sgemm_n4<<<BT/8, 256>>>(x, sgw, XSG);
    lam_kernel<<<BB*HH, 256>>>(XSG, LAM);
    rope_decay_kernel<<<(BB*TT*HH*128)/256, 256>>>(Q, K, LAM);
    scan_s_kernel<<<dim3(BB*HH, 8), 256>>>(E, ACC);
    attn_pass_kernel<0><<<dim3(TT/64, BB*HH), 256, ATTN_SMEM_BYTES>>>(
        Q, K, E, ACC, nullptr, nullptr, U);
    attn_pass_kernel<1><<<dim3(TT/64, BB*HH), 256, ATTN_SMEM_BYTES>>>(
        U, E, V, nullptr, G, gnw, ACT);
    sgemm_k<<<gg, 256>>>(ACT, ow, out, BT, DD, DD);
}

// round 4
// speedup vs baseline: 1.4461x; 1.4461x over previous
#include <cuda_runtime.h>
#include <cuda_bf16.h>
#include <math.h>
#include <stdint.h>

#define BB 4
#define TT 2048
#define HH 4
#define DD 1024
#define BT (BB*TT)

__device__ float g_Q[BT*DD], g_K[BT*DD], g_V[BT*DD], g_G[BT*DD];
__device__ float g_E[BT*DD], g_ACC[BT*DD], g_U[BT*DD], g_ACT[BT*DD];
__device__ float g_XSG[BT*HH], g_LAM[BB*HH*TT];
__device__ __nv_bfloat16 g_XHI[BT*DD], g_XLO[BT*DD];
__device__ __nv_bfloat16 g_WHI[DD*DD], g_WLO[DD*DD];

__device__ __forceinline__ uint32_t smem_to_u32(const void* p) {
    uint32_t a;
    asm("{ .reg .u64 t; cvta.to.shared.u64 t, %1; cvt.u32.u64 %0, t; }" : "=r"(a) : "l"(p));
    return a;
}
#define CP_ASYNC16(d, s) \
    asm volatile("cp.async.cg.shared.global [%0], [%1], 16;" :: "r"(d), "l"(s))
#define CP_COMMIT() asm volatile("cp.async.commit_group;" ::: "memory")
#define CP_WAIT0()  asm volatile("cp.async.wait_group 0;" ::: "memory")
#define LDSM_X4(r, a) \
    asm volatile("ldmatrix.sync.aligned.m8n8.x4.shared.b16 {%0,%1,%2,%3}, [%4];" \
        : "=r"((r)[0]),"=r"((r)[1]),"=r"((r)[2]),"=r"((r)[3]) : "r"(a))
#define MMA_B16(c, a, b0, b1) \
    asm volatile("mma.sync.aligned.m16n8k16.row.col.f32.bf16.bf16.f32 " \
        "{%0,%1,%2,%3},{%4,%5,%6,%7},{%8,%9},{%0,%1,%2,%3};" \
        : "+f"((c)[0]),"+f"((c)[1]),"+f"((c)[2]),"+f"((c)[3]) \
        : "r"((a)[0]),"r"((a)[1]),"r"((a)[2]),"r"((a)[3]), "r"(b0),"r"(b1))

// ---------------- split / transpose preps ----------------
__global__ void splitx(const float* __restrict__ X, __nv_bfloat16* __restrict__ hi,
                       __nv_bfloat16* __restrict__ lo)
{
    const int i = blockIdx.x * 256 + threadIdx.x;
    float4 v = *(const float4*)(X + (size_t)i * 4);
    __nv_bfloat16 h[4], l[4];
    float vv[4] = {v.x, v.y, v.z, v.w};
#pragma unroll
    for (int j = 0; j < 4; j++) {
        h[j] = __float2bfloat16(vv[j]);
        l[j] = __float2bfloat16(vv[j] - __bfloat162float(h[j]));
    }
    *(uint2*)(hi + (size_t)i * 4) = *(uint2*)h;
    *(uint2*)(lo + (size_t)i * 4) = *(uint2*)l;
}

// W[k][n] row-major -> Whi/Wlo[n][k]
__global__ void wsplit(const float* __restrict__ W, __nv_bfloat16* __restrict__ Whi,
                       __nv_bfloat16* __restrict__ Wlo)
{
    __shared__ float t[32][33];
    const int n0 = blockIdx.x * 32, k0 = blockIdx.y * 32;
    const int tx = threadIdx.x & 31, ty = threadIdx.x >> 5;
#pragma unroll
    for (int i = 0; i < 32; i += 8)
        t[ty + i][tx] = W[(size_t)(k0 + ty + i) * DD + n0 + tx];
    __syncthreads();
#pragma unroll
    for (int i = 0; i < 32; i += 8) {
        float x = t[tx][ty + i];
        __nv_bfloat16 h = __float2bfloat16(x);
        Whi[(size_t)(n0 + ty + i) * DD + k0 + tx] = h;
        Wlo[(size_t)(n0 + ty + i) * DD + k0 + tx] = __float2bfloat16(x - __bfloat162float(h));
    }
}

// ---------------- mma.sync bf16x2 GEMM: C[8192,1024] = A . B^T ----------------
#define KC 32
#define ASTRIDE 40                    // bf16 elems per smem row (80 B, ldmatrix conflict-free)
#define MAT_B (128*ASTRIDE*2)         // 10240 B per matrix tile
#define STG_B (4*MAT_B)               // Ahi, Alo, Bhi, Blo
#define GSM_TOTAL (2*STG_B)           // 81920 B

__global__ __launch_bounds__(256)
void mmagemm(const __nv_bfloat16* __restrict__ Ahi, const __nv_bfloat16* __restrict__ Alo,
             const __nv_bfloat16* __restrict__ Bhi, const __nv_bfloat16* __restrict__ Blo,
             float* __restrict__ C)
{
    extern __shared__ char smem[];
    const uint32_t sb = smem_to_u32(smem);
    const int tid = threadIdx.x, l = tid & 31, wid = tid >> 5;
    const int wm = wid >> 2, wn = wid & 3;            // 2 x 4 warp grid
    const int m0 = blockIdx.y * 128, n0 = blockIdx.x * 128;

    float c[4][4][4];
#pragma unroll
    for (int i = 0; i < 4; i++)
#pragma unroll
        for (int j = 0; j < 4; j++)
#pragma unroll
            for (int k = 0; k < 4; k++) c[i][j][k] = 0.f;

    const __nv_bfloat16* gsrc[4] = {Ahi + (size_t)m0 * DD, Alo + (size_t)m0 * DD,
                                    Bhi + (size_t)n0 * DD, Blo + (size_t)n0 * DD};
    const int prow = tid >> 2, pseg = tid & 3;

    // prefetch chunk 0
    {
        const int koff = 0;
#pragma unroll
        for (int u = 0; u < 2; u++) {
            const int row = prow + u * 64;
#pragma unroll
            for (int mt = 0; mt < 4; mt++)
                CP_ASYNC16(sb + mt * MAT_B + row * 80 + pseg * 16,
                           gsrc[mt] + (size_t)row * DD + koff + pseg * 8);
        }
        CP_COMMIT();
    }

    // lane addressing (bytes within a matrix tile)
    const int arow = (l & 7) + ((l >> 3) & 1) * 8;
    const int acolh = (l >> 4) * 8;
    const int brow = (l & 7) + ((l >> 4) & 1) * 8;
    const int bcolh = ((l >> 3) & 1) * 8;

    for (int ch = 0; ch < DD / KC; ch++) {
        CP_WAIT0();
        __syncthreads();
        if (ch + 1 < DD / KC) {
            const int koff = (ch + 1) * KC;
            const uint32_t dbase = sb + ((ch + 1) & 1) * STG_B;
#pragma unroll
            for (int u = 0; u < 2; u++) {
                const int row = prow + u * 64;
#pragma unroll
                for (int mt = 0; mt < 4; mt++)
                    CP_ASYNC16(dbase + mt * MAT_B + row * 80 + pseg * 16,
                               gsrc[mt] + (size_t)row * DD + koff + pseg * 8);
            }
            CP_COMMIT();
        }

        const uint32_t sA  = sb + (ch & 1) * STG_B;
        const uint32_t sAl = sA + MAT_B;
        const uint32_t sBh = sA + 2 * MAT_B;
        const uint32_t sBl = sA + 3 * MAT_B;
#pragma unroll
        for (int ks = 0; ks < 2; ks++) {
            uint32_t ah[4][4], al[4][4], bh[2][4], bl[2][4];
            const int acol = ks * 16 + acolh;
            const int bcol = ks * 16 + bcolh;
#pragma unroll
            for (int mi = 0; mi < 4; mi++) {
                const uint32_t off = (uint32_t)((wm * 64 + mi * 16 + arow) * ASTRIDE + acol) * 2;
                LDSM_X4(ah[mi], sA + off);
                LDSM_X4(al[mi], sAl + off);
            }
#pragma unroll
            for (int np = 0; np < 2; np++) {
                const uint32_t off = (uint32_t)((wn * 32 + np * 16 + brow) * ASTRIDE + bcol) * 2;
                LDSM_X4(bh[np], sBh + off);
                LDSM_X4(bl[np], sBl + off);
            }
#pragma unroll
            for (int mi = 0; mi < 4; mi++)
#pragma unroll
                for (int nj = 0; nj < 4; nj++) {
                    const uint32_t* bhp = &bh[nj >> 1][(nj & 1) * 2];
                    const uint32_t* blp = &bl[nj >> 1][(nj & 1) * 2];
                    MMA_B16(c[mi][nj], ah[mi], bhp[0], bhp[1]);
                    MMA_B16(c[mi][nj], ah[mi], blp[0], blp[1]);
                    MMA_B16(c[mi][nj], al[mi], bhp[0], bhp[1]);
                }
        }
    }

#pragma unroll
    for (int mi = 0; mi < 4; mi++)
#pragma unroll
        for (int nj = 0; nj < 4; nj++) {
            const int r0 = m0 + wm * 64 + mi * 16 + (l >> 2);
            const int cb = n0 + wn * 32 + nj * 8 + (l & 3) * 2;
            *(float2*)(C + (size_t)r0 * DD + cb)       = make_float2(c[mi][nj][0], c[mi][nj][1]);
            *(float2*)(C + (size_t)(r0 + 8) * DD + cb) = make_float2(c[mi][nj][2], c[mi][nj][3]);
        }
}

// ---------------- small kernels (unchanged from passing R1) ----------------
__global__ void sgemm_n4(const float* __restrict__ X, const float* __restrict__ W,
                         float* __restrict__ O)
{
    const int warp = threadIdx.x >> 5, lane = threadIdx.x & 31;
    const int row = blockIdx.x * 8 + warp;
    const float* x = X + (size_t)row * DD;
    float a0=0.f, a1=0.f, a2=0.f, a3=0.f;
    for (int k = lane; k < DD; k += 32) {
        float xv = x[k];
        float4 w = *(const float4*)(W + k*4);
        a0 += xv*w.x; a1 += xv*w.y; a2 += xv*w.z; a3 += xv*w.w;
    }
#pragma unroll
    for (int o = 16; o; o >>= 1) {
        a0 += __shfl_xor_sync(0xffffffffu, a0, o);
        a1 += __shfl_xor_sync(0xffffffffu, a1, o);
        a2 += __shfl_xor_sync(0xffffffffu, a2, o);
        a3 += __shfl_xor_sync(0xffffffffu, a3, o);
    }
    if (lane == 0) *(float4*)(O + row*4) = make_float4(a0,a1,a2,a3);
}

__global__ void lam_kernel(const float* __restrict__ XSG, float* __restrict__ LAM)
{
    const int b = blockIdx.x >> 2, h = blockIdx.x & 3;
    const int tid = threadIdx.x;
    __shared__ float ssum[256];
    float loc[8], run = 0.f;
    const int t0 = tid * 8;
#pragma unroll
    for (int u = 0; u < 8; u++) {
        float x = XSG[(size_t)(b*TT + t0 + u) * HH + h];
        float lg = (x >= 0.f) ? -log1pf(expf(-x)) : (x - log1pf(expf(x)));
        run += lg * (1.f/16.f);
        loc[u] = run;
    }
    ssum[tid] = run;
    __syncthreads();
    for (int off = 1; off < 256; off <<= 1) {
        float v = (tid >= off) ? ssum[tid-off] : 0.f;
        __syncthreads();
        ssum[tid] += v;
        __syncthreads();
    }
    float excl = ssum[tid] - run;
#pragma unroll
    for (int u = 0; u < 8; u++)
        LAM[(size_t)(b*HH + h)*TT + t0 + u] = expf(excl + loc[u]);
}

__global__ void rope_decay_kernel(float* __restrict__ Q, float* __restrict__ K,
                                  const float* __restrict__ LAM)
{
    const int idx = blockIdx.x * 256 + threadIdx.x;
    const int i = idx & 127;
    const int h = (idx >> 7) & 3;
    const int t = (idx >> 9) & 2047;
    const int b = idx >> 20;
    float inv = powf(10000.f, -(float)i * (1.f/128.f));
    float sn, cs;
    sincosf((float)t * inv, &sn, &cs);
    const size_t base = ((size_t)(b*TT + t)*HH + h) * 256;
    float q1 = Q[base+i], q2 = Q[base+i+128];
    Q[base+i]     = (q1*cs - q2*sn) * 0.0625f;
    Q[base+i+128] = (q2*cs + q1*sn) * 0.0625f;
    float lam = LAM[(size_t)(b*HH + h)*TT + t];
    float k1 = K[base+i], k2 = K[base+i+128];
    K[base+i]     = (k1*cs - k2*sn) * lam;
    K[base+i+128] = (k2*cs + k1*sn) * lam;
}

__global__ void scan_s_kernel(float* __restrict__ E, float* __restrict__ ACC)
{
    const int b = blockIdx.x >> 2, h = blockIdx.x & 3;
    const int ml = threadIdx.x & 31;
    const int tc = threadIdx.x >> 5;
    const int m = blockIdx.y * 32 + ml;
    __shared__ float sums[8][33];
    const size_t base = (size_t)b * TT * DD + h * 256 + m;
    float acc = 0.f;
    for (int tt = 0; tt < 256; tt++) {
        const size_t idx = base + (size_t)(tc*256 + tt) * DD;
        float s = fminf(fmaxf(E[idx], -32.f), 32.f);
        float e = expf(s);
        E[idx] = e;
        acc += e;
    }
    sums[tc][ml] = acc;
    __syncthreads();
    float a = 0.f;
    for (int p = 0; p < tc; p++) a += sums[p][ml];
    for (int tt = 0; tt < 256; tt++) {
        const size_t idx = base + (size_t)(tc*256 + tt) * DD;
        a += E[idx];
        ACC[idx] = a;
    }
}

// ---------------- attention passes (fp32, unchanged) ----------------
#define SM_QS 0
#define SM_KS (16*68)
#define SM_AS (2*16*68)
#define SM_ES (2*16*68 + 64*68)
#define ATTN_SMEM_BYTES ((2*16*68 + 64*68 + 64*260) * 4)

template <int PASS>
__global__ __launch_bounds__(256)
void attn_pass_kernel(const float* __restrict__ Qp, const float* __restrict__ Kp,
                      const float* __restrict__ Ep, const float* __restrict__ ACCp,
                      const float* __restrict__ Gp, const float* __restrict__ gnw,
                      float* __restrict__ Outp)
{
    extern __shared__ float sm[];
    float* Qs = sm + SM_QS;
    float* Ks = sm + SM_KS;
    float* As = sm + SM_AS;
    float* Es = sm + SM_ES;

    const int tid = threadIdx.x;
    const int qi = gridDim.x - 1 - blockIdx.x;
    const int b = blockIdx.y >> 2, h = blockIdx.y & 3;
    const int qBase = qi * 64;
    const size_t baseBT = (size_t)b * TT * DD + h * 256;

    const int trA = tid >> 4, tcA = tid & 15;
    const int trE = tid >> 5, tcE = tid & 31;
    const int lr = tid >> 2, lc4 = (tid & 3) * 4;

    float ok[8][8];
#pragma unroll
    for (int i = 0; i < 8; i++)
#pragma unroll
        for (int j = 0; j < 8; j++) ok[i][j] = 0.f;

    for (int kc = 0; kc <= qi; kc++) {
        const int kBase = kc * 64;
        float aa[4][4];
#pragma unroll
        for (int i = 0; i < 4; i++)
#pragma unroll
            for (int j = 0; j < 4; j++) aa[i][j] = 0.f;

        for (int ds = 0; ds < 256; ds += 16) {
            __syncthreads();
            float4 qv = *(const float4*)(Qp + baseBT + (size_t)(qBase+lr)*DD + ds + lc4);
            float4 kv = *(const float4*)(Kp + baseBT + (size_t)(kBase+lr)*DD + ds + lc4);
            Qs[(lc4+0)*68 + lr] = qv.x; Qs[(lc4+1)*68 + lr] = qv.y;
            Qs[(lc4+2)*68 + lr] = qv.z; Qs[(lc4+3)*68 + lr] = qv.w;
            Ks[(lc4+0)*68 + lr] = kv.x; Ks[(lc4+1)*68 + lr] = kv.y;
            Ks[(lc4+2)*68 + lr] = kv.z; Ks[(lc4+3)*68 + lr] = kv.w;
            __syncthreads();
#pragma unroll
            for (int k = 0; k < 16; k++) {
                float4 q4 = *(const float4*)&Qs[k*68 + trA*4];
                float4 k4 = *(const float4*)&Ks[k*68 + tcA*4];
                aa[0][0] += q4.x*k4.x; aa[0][1] += q4.x*k4.y; aa[0][2] += q4.x*k4.z; aa[0][3] += q4.x*k4.w;
                aa[1][0] += q4.y*k4.x; aa[1][1] += q4.y*k4.y; aa[1][2] += q4.y*k4.z; aa[1][3] += q4.y*k4.w;
                aa[2][0] += q4.z*k4.x; aa[2][1] += q4.z*k4.y; aa[2][2] += q4.z*k4.z; aa[2][3] += q4.z*k4.w;
                aa[3][0] += q4.w*k4.x; aa[3][1] += q4.w*k4.y; aa[3][2] += q4.w*k4.z; aa[3][3] += q4.w*k4.w;
            }
        }
        __syncthreads();

        const bool diag = (kc == qi);
#pragma unroll
        for (int i = 0; i < 4; i++)
#pragma unroll
            for (int j = 0; j < 4; j++) {
                float v = aa[i][j];
                if (diag && (tcA*4 + j) > (trA*4 + i)) v = 0.f;
                As[(tcA*4 + j)*68 + trA*4 + i] = v;
            }
        {
            const int ec = (tid & 63) * 4;
            const int er0 = (tid >> 6) * 16;
#pragma unroll
            for (int it = 0; it < 16; it++)
                *(float4*)&Es[(er0+it)*260 + ec] =
                    *(const float4*)(Ep + baseBT + (size_t)(kBase+er0+it)*DD + ec);
        }
        __syncthreads();

#pragma unroll 2
        for (int kk = 0; kk < 64; kk++) {
            float a8[8], e8[8];
            *(float4*)&a8[0] = *(float4*)&As[kk*68 + trE*8];
            *(float4*)&a8[4] = *(float4*)&As[kk*68 + trE*8 + 4];
            *(float4*)&e8[0] = *(float4*)&Es[kk*260 + tcE*8];
            *(float4*)&e8[4] = *(float4*)&Es[kk*260 + tcE*8 + 4];
#pragma unroll
            for (int i = 0; i < 8; i++)
#pragma unroll
                for (int j = 0; j < 8; j++) ok[i][j] += a8[i] * e8[j];
        }
    }

#pragma unroll
    for (int i = 0; i < 8; i++) {
        const int t = qBase + trE*8 + i;
        const size_t rb = baseBT + (size_t)t * DD;
        if (PASS == 0) {
            float acr[8], v[8];
            float mx = -3.4e38f;
#pragma unroll
            for (int j = 0; j < 8; j++) {
                acr[j] = ACCp[rb + tcE*8 + j];
                v[j] = ok[i][j] / acr[j];
                mx = fmaxf(mx, v[j]);
            }
#pragma unroll
            for (int o = 16; o; o >>= 1) mx = fmaxf(mx, __shfl_xor_sync(0xffffffffu, mx, o));
            float e[8], s = 0.f;
#pragma unroll
            for (int j = 0; j < 8; j++) { e[j] = expf(v[j] - mx); s += e[j]; }
#pragma unroll
            for (int o = 16; o; o >>= 1) s += __shfl_xor_sync(0xffffffffu, s, o);
            const float inv = 1.f / s;
#pragma unroll
            for (int j = 0; j < 8; j++)
                Outp[rb + tcE*8 + j] = e[j] * inv / acr[j];
        } else {
            float ss = 0.f;
#pragma unroll
            for (int j = 0; j < 8; j++) ss += ok[i][j] * ok[i][j];
#pragma unroll
            for (int o = 16; o; o >>= 1) ss += __shfl_xor_sync(0xffffffffu, ss, o);
            const float rn = rsqrtf(ss * (1.f/256.f) + 1e-5f);
#pragma unroll
            for (int j = 0; j < 8; j++) {
                const int dv = tcE*8 + j;
                float gg = Gp[rb + dv];
                float sig = 1.f / (1.f + expf(-gg));
                Outp[rb + dv] = ok[i][j] * rn * gnw[dv] * gg * sig;
            }
        }
    }
}

extern "C" void kernel_launch(void* const* d_in, const int* in_sizes, int n_in,
                              void* d_out, int out_size)
{
    const float* x   = (const float*)d_in[0];
    const float* qw  = (const float*)d_in[1];
    const float* kw  = (const float*)d_in[2];
    const float* vw  = (const float*)d_in[3];
    const float* gw  = (const float*)d_in[4];
    const float* sw  = (const float*)d_in[5];
    const float* sgw = (const float*)d_in[6];
    const float* gnw = (const float*)d_in[7];
    const float* ow  = (const float*)d_in[8];
    float* out = (float*)d_out;

    float *Q, *K, *V, *G, *E, *ACC, *U, *ACT, *XSG, *LAM;
    __nv_bfloat16 *XHI, *XLO, *WHI, *WLO;
    cudaGetSymbolAddress((void**)&Q,   g_Q);
    cudaGetSymbolAddress((void**)&K,   g_K);
    cudaGetSymbolAddress((void**)&V,   g_V);
    cudaGetSymbolAddress((void**)&G,   g_G);
    cudaGetSymbolAddress((void**)&E,   g_E);
    cudaGetSymbolAddress((void**)&ACC, g_ACC);
    cudaGetSymbolAddress((void**)&U,   g_U);
    cudaGetSymbolAddress((void**)&ACT, g_ACT);
    cudaGetSymbolAddress((void**)&XSG, g_XSG);
    cudaGetSymbolAddress((void**)&LAM, g_LAM);
    cudaGetSymbolAddress((void**)&XHI, g_XHI);
    cudaGetSymbolAddress((void**)&XLO, g_XLO);
    cudaGetSymbolAddress((void**)&WHI, g_WHI);
    cudaGetSymbolAddress((void**)&WLO, g_WLO);

    static int attr_done = 0;
    if (!attr_done) {
        cudaFuncSetAttribute(attn_pass_kernel<0>, cudaFuncAttributeMaxDynamicSharedMemorySize, ATTN_SMEM_BYTES);
        cudaFuncSetAttribute(attn_pass_kernel<1>, cudaFuncAttributeMaxDynamicSharedMemorySize, ATTN_SMEM_BYTES);
        cudaFuncSetAttribute(mmagemm, cudaFuncAttributeMaxDynamicSharedMemorySize, GSM_TOTAL);
        attr_done = 1;
    }

    const dim3 wgrid(32, 32);
    const dim3 ggrid(DD/128, BT/128);          // (8, 64)
    const int  sxg = (BT*DD/4)/256;

    splitx<<<sxg, 256>>>(x, XHI, XLO);
    sgemm_n4<<<BT/8, 256>>>(x, sgw, XSG);

    wsplit<<<wgrid, 256>>>(qw, WHI, WLO);
    mmagemm<<<ggrid, 256, GSM_TOTAL>>>(XHI, XLO, WHI, WLO, Q);
    wsplit<<<wgrid, 256>>>(kw, WHI, WLO);
    mmagemm<<<ggrid, 256, GSM_TOTAL>>>(XHI, XLO, WHI, WLO, K);
    wsplit<<<wgrid, 256>>>(vw, WHI, WLO);
    mmagemm<<<ggrid, 256, GSM_TOTAL>>>(XHI, XLO, WHI, WLO, V);
    wsplit<<<wgrid, 256>>>(gw, WHI, WLO);
    mmagemm<<<ggrid, 256, GSM_TOTAL>>>(XHI, XLO, WHI, WLO, G);
    wsplit<<<wgrid, 256>>>(sw, WHI, WLO);
    mmagemm<<<ggrid, 256, GSM_TOTAL>>>(XHI, XLO, WHI, WLO, E);

    lam_kernel<<<BB*HH, 256>>>(XSG, LAM);
    rope_decay_kernel<<<(BB*TT*HH*128)/256, 256>>>(Q, K, LAM);
    scan_s_kernel<<<dim3(BB*HH, 8), 256>>>(E, ACC);
    attn_pass_kernel<0><<<dim3(TT/64, BB*HH), 256, ATTN_SMEM_BYTES>>>(Q, K, E, ACC, nullptr, nullptr, U);
    attn_pass_kernel<1><<<dim3(TT/64, BB*HH), 256, ATTN_SMEM_BYTES>>>(U, E, V, nullptr, G, gnw, ACT);

    splitx<<<sxg, 256>>>(ACT, XHI, XLO);
    wsplit<<<wgrid, 256>>>(ow, WHI, WLO);
    mmagemm<<<ggrid, 256, GSM_TOTAL>>>(XHI, XLO, WHI, WLO, out);
}

// round 5
// speedup vs baseline: 1.4509x; 1.0034x over previous
#include <cuda_runtime.h>
#include <cuda_bf16.h>
#include <math.h>
#include <stdint.h>

#define BB 4
#define TT 2048
#define HH 4
#define DD 1024
#define BT (BB*TT)

__device__ float g_Q[BT*DD], g_K[BT*DD], g_V[BT*DD], g_G[BT*DD];
__device__ float g_E[BT*DD], g_ACC[BT*DD], g_U[BT*DD], g_ACT[BT*DD];
__device__ float g_XSG[BT*HH], g_LAM[BB*HH*TT];
__device__ __nv_bfloat16 g_XHI[BT*DD], g_XLO[BT*DD];
__device__ __nv_bfloat16 g_WHI[DD*DD], g_WLO[DD*DD];

__device__ __forceinline__ uint32_t smem_to_u32(const void* p) {
    uint32_t a;
    asm("{ .reg .u64 t; cvta.to.shared.u64 t, %1; cvt.u32.u64 %0, t; }" : "=r"(a) : "l"(p));
    return a;
}
#define CP_ASYNC16(d, s) \
    asm volatile("cp.async.cg.shared.global [%0], [%1], 16;" :: "r"(d), "l"(s))
#define CP_COMMIT() asm volatile("cp.async.commit_group;" ::: "memory")
#define CP_WAIT0()  asm volatile("cp.async.wait_group 0;" ::: "memory")
#define LDSM_X4(r, a) \
    asm volatile("ldmatrix.sync.aligned.m8n8.x4.shared.b16 {%0,%1,%2,%3}, [%4];" \
        : "=r"((r)[0]),"=r"((r)[1]),"=r"((r)[2]),"=r"((r)[3]) : "r"(a))
#define MMA_B16(c, a, b0, b1) \
    asm volatile("mma.sync.aligned.m16n8k16.row.col.f32.bf16.bf16.f32 " \
        "{%0,%1,%2,%3},{%4,%5,%6,%7},{%8,%9},{%0,%1,%2,%3};" \
        : "+f"((c)[0]),"+f"((c)[1]),"+f"((c)[2]),"+f"((c)[3]) \
        : "r"((a)[0]),"r"((a)[1]),"r"((a)[2]),"r"((a)[3]), "r"(b0),"r"(b1))

// ---------------- split / transpose preps ----------------
__global__ void splitx(const float* __restrict__ X, __nv_bfloat16* __restrict__ hi,
                       __nv_bfloat16* __restrict__ lo)
{
    const int i = blockIdx.x * 256 + threadIdx.x;
    float4 v = *(const float4*)(X + (size_t)i * 4);
    __nv_bfloat16 h[4], l[4];
    float vv[4] = {v.x, v.y, v.z, v.w};
#pragma unroll
    for (int j = 0; j < 4; j++) {
        h[j] = __float2bfloat16(vv[j]);
        l[j] = __float2bfloat16(vv[j] - __bfloat162float(h[j]));
    }
    *(uint2*)(hi + (size_t)i * 4) = *(uint2*)h;
    *(uint2*)(lo + (size_t)i * 4) = *(uint2*)l;
}

// W[k][n] row-major -> Whi/Wlo[n][k]
__global__ void wsplit(const float* __restrict__ W, __nv_bfloat16* __restrict__ Whi,
                       __nv_bfloat16* __restrict__ Wlo)
{
    __shared__ float t[32][33];
    const int n0 = blockIdx.x * 32, k0 = blockIdx.y * 32;
    const int tx = threadIdx.x & 31, ty = threadIdx.x >> 5;
#pragma unroll
    for (int i = 0; i < 32; i += 8)
        t[ty + i][tx] = W[(size_t)(k0 + ty + i) * DD + n0 + tx];
    __syncthreads();
#pragma unroll
    for (int i = 0; i < 32; i += 8) {
        float x = t[tx][ty + i];
        __nv_bfloat16 h = __float2bfloat16(x);
        Whi[(size_t)(n0 + ty + i) * DD + k0 + tx] = h;
        Wlo[(size_t)(n0 + ty + i) * DD + k0 + tx] = __float2bfloat16(x - __bfloat162float(h));
    }
}

// ---------------- mma.sync bf16x2 GEMM: C[8192,1024] = A . B^T ----------------
#define KC 32
#define ASTRIDE 40                    // bf16 elems per smem row (80 B, ldmatrix conflict-free)
#define MAT_B (128*ASTRIDE*2)         // 10240 B per matrix tile
#define STG_B (4*MAT_B)               // Ahi, Alo, Bhi, Blo
#define GSM_TOTAL (2*STG_B)           // 81920 B

__global__ __launch_bounds__(256)
void mmagemm(const __nv_bfloat16* __restrict__ Ahi, const __nv_bfloat16* __restrict__ Alo,
             const __nv_bfloat16* __restrict__ Bhi, const __nv_bfloat16* __restrict__ Blo,
             float* __restrict__ C)
{
    extern __shared__ char smem[];
    const uint32_t sb = smem_to_u32(smem);
    const int tid = threadIdx.x, l = tid & 31, wid = tid >> 5;
    const int wm = wid >> 2, wn = wid & 3;            // 2 x 4 warp grid
    const int m0 = blockIdx.y * 128, n0 = blockIdx.x * 128;

    float c[4][4][4];
#pragma unroll
    for (int i = 0; i < 4; i++)
#pragma unroll
        for (int j = 0; j < 4; j++)
#pragma unroll
            for (int k = 0; k < 4; k++) c[i][j][k] = 0.f;

    const __nv_bfloat16* gsrc[4] = {Ahi + (size_t)m0 * DD, Alo + (size_t)m0 * DD,
                                    Bhi + (size_t)n0 * DD, Blo + (size_t)n0 * DD};
    const int prow = tid >> 2, pseg = tid & 3;

    // prefetch chunk 0
    {
        const int koff = 0;
#pragma unroll
        for (int u = 0; u < 2; u++) {
            const int row = prow + u * 64;
#pragma unroll
            for (int mt = 0; mt < 4; mt++)
                CP_ASYNC16(sb + mt * MAT_B + row * 80 + pseg * 16,
                           gsrc[mt] + (size_t)row * DD + koff + pseg * 8);
        }
        CP_COMMIT();
    }

    // lane addressing (bytes within a matrix tile)
    const int arow = (l & 7) + ((l >> 3) & 1) * 8;
    const int acolh = (l >> 4) * 8;
    const int brow = (l & 7) + ((l >> 4) & 1) * 8;
    const int bcolh = ((l >> 3) & 1) * 8;

    for (int ch = 0; ch < DD / KC; ch++) {
        CP_WAIT0();
        __syncthreads();
        if (ch + 1 < DD / KC) {
            const int koff = (ch + 1) * KC;
            const uint32_t dbase = sb + ((ch + 1) & 1) * STG_B;
#pragma unroll
            for (int u = 0; u < 2; u++) {
                const int row = prow + u * 64;
#pragma unroll
                for (int mt = 0; mt < 4; mt++)
                    CP_ASYNC16(dbase + mt * MAT_B + row * 80 + pseg * 16,
                               gsrc[mt] + (size_t)row * DD + koff + pseg * 8);
            }
            CP_COMMIT();
        }

        const uint32_t sA  = sb + (ch & 1) * STG_B;
        const uint32_t sAl = sA + MAT_B;
        const uint32_t sBh = sA + 2 * MAT_B;
        const uint32_t sBl = sA + 3 * MAT_B;
#pragma unroll
        for (int ks = 0; ks < 2; ks++) {
            uint32_t ah[4][4], al[4][4], bh[2][4], bl[2][4];
            const int acol = ks * 16 + acolh;
            const int bcol = ks * 16 + bcolh;
#pragma unroll
            for (int mi = 0; mi < 4; mi++) {
                const uint32_t off = (uint32_t)((wm * 64 + mi * 16 + arow) * ASTRIDE + acol) * 2;
                LDSM_X4(ah[mi], sA + off);
                LDSM_X4(al[mi], sAl + off);
            }
#pragma unroll
            for (int np = 0; np < 2; np++) {
                const uint32_t off = (uint32_t)((wn * 32 + np * 16 + brow) * ASTRIDE + bcol) * 2;
                LDSM_X4(bh[np], sBh + off);
                LDSM_X4(bl[np], sBl + off);
            }
#pragma unroll
            for (int mi = 0; mi < 4; mi++)
#pragma unroll
                for (int nj = 0; nj < 4; nj++) {
                    const uint32_t* bhp = &bh[nj >> 1][(nj & 1) * 2];
                    const uint32_t* blp = &bl[nj >> 1][(nj & 1) * 2];
                    MMA_B16(c[mi][nj], ah[mi], bhp[0], bhp[1]);
                    MMA_B16(c[mi][nj], ah[mi], blp[0], blp[1]);
                    MMA_B16(c[mi][nj], al[mi], bhp[0], bhp[1]);
                }
        }
    }

#pragma unroll
    for (int mi = 0; mi < 4; mi++)
#pragma unroll
        for (int nj = 0; nj < 4; nj++) {
            const int r0 = m0 + wm * 64 + mi * 16 + (l >> 2);
            const int cb = n0 + wn * 32 + nj * 8 + (l & 3) * 2;
            *(float2*)(C + (size_t)r0 * DD + cb)       = make_float2(c[mi][nj][0], c[mi][nj][1]);
            *(float2*)(C + (size_t)(r0 + 8) * DD + cb) = make_float2(c[mi][nj][2], c[mi][nj][3]);
        }
}

// ---------------- small kernels (unchanged from passing R1) ----------------
__global__ void sgemm_n4(const float* __restrict__ X, const float* __restrict__ W,
                         float* __restrict__ O)
{
    const int warp = threadIdx.x >> 5, lane = threadIdx.x & 31;
    const int row = blockIdx.x * 8 + warp;
    const float* x = X + (size_t)row * DD;
    float a0=0.f, a1=0.f, a2=0.f, a3=0.f;
    for (int k = lane; k < DD; k += 32) {
        float xv = x[k];
        float4 w = *(const float4*)(W + k*4);
        a0 += xv*w.x; a1 += xv*w.y; a2 += xv*w.z; a3 += xv*w.w;
    }
#pragma unroll
    for (int o = 16; o; o >>= 1) {
        a0 += __shfl_xor_sync(0xffffffffu, a0, o);
        a1 += __shfl_xor_sync(0xffffffffu, a1, o);
        a2 += __shfl_xor_sync(0xffffffffu, a2, o);
        a3 += __shfl_xor_sync(0xffffffffu, a3, o);
    }
    if (lane == 0) *(float4*)(O + row*4) = make_float4(a0,a1,a2,a3);
}

__global__ void lam_kernel(const float* __restrict__ XSG, float* __restrict__ LAM)
{
    const int b = blockIdx.x >> 2, h = blockIdx.x & 3;
    const int tid = threadIdx.x;
    __shared__ float ssum[256];
    float loc[8], run = 0.f;
    const int t0 = tid * 8;
#pragma unroll
    for (int u = 0; u < 8; u++) {
        float x = XSG[(size_t)(b*TT + t0 + u) * HH + h];
        float lg = (x >= 0.f) ? -log1pf(expf(-x)) : (x - log1pf(expf(x)));
        run += lg * (1.f/16.f);
        loc[u] = run;
    }
    ssum[tid] = run;
    __syncthreads();
    for (int off = 1; off < 256; off <<= 1) {
        float v = (tid >= off) ? ssum[tid-off] : 0.f;
        __syncthreads();
        ssum[tid] += v;
        __syncthreads();
    }
    float excl = ssum[tid] - run;
#pragma unroll
    for (int u = 0; u < 8; u++)
        LAM[(size_t)(b*HH + h)*TT + t0 + u] = expf(excl + loc[u]);
}

__global__ void rope_decay_kernel(float* __restrict__ Q, float* __restrict__ K,
                                  const float* __restrict__ LAM)
{
    const int idx = blockIdx.x * 256 + threadIdx.x;
    const int i = idx & 127;
    const int h = (idx >> 7) & 3;
    const int t = (idx >> 9) & 2047;
    const int b = idx >> 20;
    float inv = powf(10000.f, -(float)i * (1.f/128.f));
    float sn, cs;
    sincosf((float)t * inv, &sn, &cs);
    const size_t base = ((size_t)(b*TT + t)*HH + h) * 256;
    float q1 = Q[base+i], q2 = Q[base+i+128];
    Q[base+i]     = (q1*cs - q2*sn) * 0.0625f;
    Q[base+i+128] = (q2*cs + q1*sn) * 0.0625f;
    float lam = LAM[(size_t)(b*HH + h)*TT + t];
    float k1 = K[base+i], k2 = K[base+i+128];
    K[base+i]     = (k1*cs - k2*sn) * lam;
    K[base+i+128] = (k2*cs + k1*sn) * lam;
}

__global__ void scan_s_kernel(float* __restrict__ E, float* __restrict__ ACC)
{
    const int b = blockIdx.x >> 2, h = blockIdx.x & 3;
    const int ml = threadIdx.x & 31;
    const int tc = threadIdx.x >> 5;
    const int m = blockIdx.y * 32 + ml;
    __shared__ float sums[8][33];
    const size_t base = (size_t)b * TT * DD + h * 256 + m;
    float acc = 0.f;
    for (int tt = 0; tt < 256; tt++) {
        const size_t idx = base + (size_t)(tc*256 + tt) * DD;
        float s = fminf(fmaxf(E[idx], -32.f), 32.f);
        float e = expf(s);
        E[idx] = e;
        acc += e;
    }
    sums[tc][ml] = acc;
    __syncthreads();
    float a = 0.f;
    for (int p = 0; p < tc; p++) a += sums[p][ml];
    for (int tt = 0; tt < 256; tt++) {
        const size_t idx = base + (size_t)(tc*256 + tt) * DD;
        a += E[idx];
        ACC[idx] = a;
    }
}

// ---------------- attention passes (fp32, unchanged) ----------------
#define SM_QS 0
#define SM_KS (16*68)
#define SM_AS (2*16*68)
#define SM_ES (2*16*68 + 64*68)
#define ATTN_SMEM_BYTES ((2*16*68 + 64*68 + 64*260) * 4)

template <int PASS>
__global__ __launch_bounds__(256)
void attn_pass_kernel(const float* __restrict__ Qp, const float* __restrict__ Kp,
                      const float* __restrict__ Ep, const float* __restrict__ ACCp,
                      const float* __restrict__ Gp, const float* __restrict__ gnw,
                      float* __restrict__ Outp)
{
    extern __shared__ float sm[];
    float* Qs = sm + SM_QS;
    float* Ks = sm + SM_KS;
    float* As = sm + SM_AS;
    float* Es = sm + SM_ES;

    const int tid = threadIdx.x;
    const int qi = gridDim.x - 1 - blockIdx.x;
    const int b = blockIdx.y >> 2, h = blockIdx.y & 3;
    const int qBase = qi * 64;
    const size_t baseBT = (size_t)b * TT * DD + h * 256;

    const int trA = tid >> 4, tcA = tid & 15;
    const int trE = tid >> 5, tcE = tid & 31;
    const int lr = tid >> 2, lc4 = (tid & 3) * 4;

    float ok[8][8];
#pragma unroll
    for (int i = 0; i < 8; i++)
#pragma unroll
        for (int j = 0; j < 8; j++) ok[i][j] = 0.f;

    for (int kc = 0; kc <= qi; kc++) {
        const int kBase = kc * 64;
        float aa[4][4];
#pragma unroll
        for (int i = 0; i < 4; i++)
#pragma unroll
            for (int j = 0; j < 4; j++) aa[i][j] = 0.f;

        for (int ds = 0; ds < 256; ds += 16) {
            __syncthreads();
            float4 qv = *(const float4*)(Qp + baseBT + (size_t)(qBase+lr)*DD + ds + lc4);
            float4 kv = *(const float4*)(Kp + baseBT + (size_t)(kBase+lr)*DD + ds + lc4);
            Qs[(lc4+0)*68 + lr] = qv.x; Qs[(lc4+1)*68 + lr] = qv.y;
            Qs[(lc4+2)*68 + lr] = qv.z; Qs[(lc4+3)*68 + lr] = qv.w;
            Ks[(lc4+0)*68 + lr] = kv.x; Ks[(lc4+1)*68 + lr] = kv.y;
            Ks[(lc4+2)*68 + lr] = kv.z; Ks[(lc4+3)*68 + lr] = kv.w;
            __syncthreads();
#pragma unroll
            for (int k = 0; k < 16; k++) {
                float4 q4 = *(const float4*)&Qs[k*68 + trA*4];
                float4 k4 = *(const float4*)&Ks[k*68 + tcA*4];
                aa[0][0] += q4.x*k4.x; aa[0][1] += q4.x*k4.y; aa[0][2] += q4.x*k4.z; aa[0][3] += q4.x*k4.w;
                aa[1][0] += q4.y*k4.x; aa[1][1] += q4.y*k4.y; aa[1][2] += q4.y*k4.z; aa[1][3] += q4.y*k4.w;
                aa[2][0] += q4.z*k4.x; aa[2][1] += q4.z*k4.y; aa[2][2] += q4.z*k4.z; aa[2][3] += q4.z*k4.w;
                aa[3][0] += q4.w*k4.x; aa[3][1] += q4.w*k4.y; aa[3][2] += q4.w*k4.z; aa[3][3] += q4.w*k4.w;
            }
        }
        __syncthreads();

        const bool diag = (kc == qi);
#pragma unroll
        for (int i = 0; i < 4; i++)
#pragma unroll
            for (int j = 0; j < 4; j++) {
                float v = aa[i][j];
                if (diag && (tcA*4 + j) > (trA*4 + i)) v = 0.f;
                As[(tcA*4 + j)*68 + trA*4 + i] = v;
            }
        {
            const int ec = (tid & 63) * 4;
            const int er0 = (tid >> 6) * 16;
#pragma unroll
            for (int it = 0; it < 16; it++)
                *(float4*)&Es[(er0+it)*260 + ec] =
                    *(const float4*)(Ep + baseBT + (size_t)(kBase+er0+it)*DD + ec);
        }
        __syncthreads();

#pragma unroll 2
        for (int kk = 0; kk < 64; kk++) {
            float a8[8], e8[8];
            *(float4*)&a8[0] = *(float4*)&As[kk*68 + trE*8];
            *(float4*)&a8[4] = *(float4*)&As[kk*68 + trE*8 + 4];
            *(float4*)&e8[0] = *(float4*)&Es[kk*260 + tcE*8];
            *(float4*)&e8[4] = *(float4*)&Es[kk*260 + tcE*8 + 4];
#pragma unroll
            for (int i = 0; i < 8; i++)
#pragma unroll
                for (int j = 0; j < 8; j++) ok[i][j] += a8[i] * e8[j];
        }
    }

#pragma unroll
    for (int i = 0; i < 8; i++) {
        const int t = qBase + trE*8 + i;
        const size_t rb = baseBT + (size_t)t * DD;
        if (PASS == 0) {
            float acr[8], v[8];
            float mx = -3.4e38f;
#pragma unroll
            for (int j = 0; j < 8; j++) {
                acr[j] = ACCp[rb + tcE*8 + j];
                v[j] = ok[i][j] / acr[j];
                mx = fmaxf(mx, v[j]);
            }
#pragma unroll
            for (int o = 16; o; o >>= 1) mx = fmaxf(mx, __shfl_xor_sync(0xffffffffu, mx, o));
            float e[8], s = 0.f;
#pragma unroll
            for (int j = 0; j < 8; j++) { e[j] = expf(v[j] - mx); s += e[j]; }
#pragma unroll
            for (int o = 16; o; o >>= 1) s += __shfl_xor_sync(0xffffffffu, s, o);
            const float inv = 1.f / s;
#pragma unroll
            for (int j = 0; j < 8; j++)
                Outp[rb + tcE*8 + j] = e[j] * inv / acr[j];
        } else {
            float ss = 0.f;
#pragma unroll
            for (int j = 0; j < 8; j++) ss += ok[i][j] * ok[i][j];
#pragma unroll
            for (int o = 16; o; o >>= 1) ss += __shfl_xor_sync(0xffffffffu, ss, o);
            const float rn = rsqrtf(ss * (1.f/256.f) + 1e-5f);
#pragma unroll
            for (int j = 0; j < 8; j++) {
                const int dv = tcE*8 + j;
                float gg = Gp[rb + dv];
                float sig = 1.f / (1.f + expf(-gg));
                Outp[rb + dv] = ok[i][j] * rn * gnw[dv] * gg * sig;
            }
        }
    }
}

extern "C" void kernel_launch(void* const* d_in, const int* in_sizes, int n_in,
                              void* d_out, int out_size)
{
    const float* x   = (const float*)d_in[0];
    const float* qw  = (const float*)d_in[1];
    const float* kw  = (const float*)d_in[2];
    const float* vw  = (const float*)d_in[3];
    const float* gw  = (const float*)d_in[4];
    const float* sw  = (const float*)d_in[5];
    const float* sgw = (const float*)d_in[6];
    const float* gnw = (const float*)d_in[7];
    const float* ow  = (const float*)d_in[8];
    float* out = (float*)d_out;

    float *Q, *K, *V, *G, *E, *ACC, *U, *ACT, *XSG, *LAM;
    __nv_bfloat16 *XHI, *XLO, *WHI, *WLO;
    cudaGetSymbolAddress((void**)&Q,   g_Q);
    cudaGetSymbolAddress((void**)&K,   g_K);
    cudaGetSymbolAddress((void**)&V,   g_V);
    cudaGetSymbolAddress((void**)&G,   g_G);
    cudaGetSymbolAddress((void**)&E,   g_E);
    cudaGetSymbolAddress((void**)&ACC, g_ACC);
    cudaGetSymbolAddress((void**)&U,   g_U);
    cudaGetSymbolAddress((void**)&ACT, g_ACT);
    cudaGetSymbolAddress((void**)&XSG, g_XSG);
    cudaGetSymbolAddress((void**)&LAM, g_LAM);
    cudaGetSymbolAddress((void**)&XHI, g_XHI);
    cudaGetSymbolAddress((void**)&XLO, g_XLO);
    cudaGetSymbolAddress((void**)&WHI, g_WHI);
    cudaGetSymbolAddress((void**)&WLO, g_WLO);

    static int attr_done = 0;
    if (!attr_done) {
        cudaFuncSetAttribute(attn_pass_kernel<0>, cudaFuncAttributeMaxDynamicSharedMemorySize, ATTN_SMEM_BYTES);
        cudaFuncSetAttribute(attn_pass_kernel<1>, cudaFuncAttributeMaxDynamicSharedMemorySize, ATTN_SMEM_BYTES);
        cudaFuncSetAttribute(mmagemm, cudaFuncAttributeMaxDynamicSharedMemorySize, GSM_TOTAL);
        attr_done = 1;
    }

    const dim3 wgrid(32, 32);
    const dim3 ggrid(DD/128, BT/128);          // (8, 64)
    const int  sxg = (BT*DD/4)/256;

    splitx<<<sxg, 256>>>(x, XHI, XLO);
    sgemm_n4<<<BT/8, 256>>>(x, sgw, XSG);

    wsplit<<<wgrid, 256>>>(qw, WHI, WLO);
    mmagemm<<<ggrid, 256, GSM_TOTAL>>>(XHI, XLO, WHI, WLO, Q);
    wsplit<<<wgrid, 256>>>(kw, WHI, WLO);
    mmagemm<<<ggrid, 256, GSM_TOTAL>>>(XHI, XLO, WHI, WLO, K);
    wsplit<<<wgrid, 256>>>(vw, WHI, WLO);
    mmagemm<<<ggrid, 256, GSM_TOTAL>>>(XHI, XLO, WHI, WLO, V);
    wsplit<<<wgrid, 256>>>(gw, WHI, WLO);
    mmagemm<<<ggrid, 256, GSM_TOTAL>>>(XHI, XLO, WHI, WLO, G);
    wsplit<<<wgrid, 256>>>(sw, WHI, WLO);
    mmagemm<<<ggrid, 256, GSM_TOTAL>>>(XHI, XLO, WHI, WLO, E);

    lam_kernel<<<BB*HH, 256>>>(XSG, LAM);
    rope_decay_kernel<<<(BB*TT*HH*128)/256, 256>>>(Q, K, LAM);
    scan_s_kernel<<<dim3(BB*HH, 8), 256>>>(E, ACC);
    attn_pass_kernel<0><<<dim3(TT/64, BB*HH), 256, ATTN_SMEM_BYTES>>>(Q, K, E, ACC, nullptr, nullptr, U);
    attn_pass_kernel<1><<<dim3(TT/64, BB*HH), 256, ATTN_SMEM_BYTES>>>(U, E, V, nullptr, G, gnw, ACT);

    splitx<<<sxg, 256>>>(ACT, XHI, XLO);
    wsplit<<<wgrid, 256>>>(ow, WHI, WLO);
    mmagemm<<<ggrid, 256, GSM_TOTAL>>>(XHI, XLO, WHI, WLO, out);
}

// round 6
// speedup vs baseline: 2.3016x; 1.5862x over previous
#include <cuda_runtime.h>
#include <cuda_bf16.h>
#include <math.h>
#include <stdint.h>

#define BB 4
#define TT 2048
#define HH 4
#define DD 1024
#define BT (BB*TT)
#define BH 16

__device__ float g_Q[BT*DD], g_K[BT*DD], g_V[BT*DD], g_G[BT*DD], g_S[BT*DD];
__device__ float g_ACC[BT*DD], g_ACT[BT*DD], g_XSG[BT*HH], g_LAM[BH*TT];
__device__ __nv_bfloat16 g_XHI[BT*DD], g_XLO[BT*DD], g_WHI[DD*DD], g_WLO[DD*DD];
__device__ __nv_bfloat16 g_QHI[BT*DD], g_QLO[BT*DD], g_KHI[BT*DD], g_KLO[BT*DD];
__device__ __nv_bfloat16 g_EHI[BT*DD], g_ELO[BT*DD], g_ETHI[BT*DD], g_ETLO[BT*DD];
__device__ __nv_bfloat16 g_UHI[BT*DD], g_ULO[BT*DD], g_VTHI[BT*DD], g_VTLO[BT*DD];

__device__ __forceinline__ uint32_t smem_to_u32(const void* p) {
    uint32_t a;
    asm("{ .reg .u64 t; cvta.to.shared.u64 t, %1; cvt.u32.u64 %0, t; }" : "=r"(a) : "l"(p));
    return a;
}
#define CP_ASYNC16(d, s) asm volatile("cp.async.cg.shared.global [%0], [%1], 16;" :: "r"(d), "l"(s))
#define CP_COMMIT() asm volatile("cp.async.commit_group;" ::: "memory")
#define LDSM_X4(r, a) \
    asm volatile("ldmatrix.sync.aligned.m8n8.x4.shared.b16 {%0,%1,%2,%3}, [%4];" \
        : "=r"((r)[0]),"=r"((r)[1]),"=r"((r)[2]),"=r"((r)[3]) : "r"(a))
#define MMA_B16(c, a, b0, b1) \
    asm volatile("mma.sync.aligned.m16n8k16.row.col.f32.bf16.bf16.f32 " \
        "{%0,%1,%2,%3},{%4,%5,%6,%7},{%8,%9},{%0,%1,%2,%3};" \
        : "+f"((c)[0]),"+f"((c)[1]),"+f"((c)[2]),"+f"((c)[3]) \
        : "r"((a)[0]),"r"((a)[1]),"r"((a)[2]),"r"((a)[3]), "r"(b0),"r"(b1))
__device__ __forceinline__ void spl(float x, __nv_bfloat16& h, __nv_bfloat16& l) {
    h = __float2bfloat16(x); l = __float2bfloat16(x - __bfloat162float(h));
}
__device__ __forceinline__ uint32_t pkbf(__nv_bfloat16 a, __nv_bfloat16 b) {
    return (uint32_t)*(uint16_t*)&a | ((uint32_t)*(uint16_t*)&b << 16);
}

__global__ void splitx(const float* __restrict__ X, __nv_bfloat16* __restrict__ hi,
                       __nv_bfloat16* __restrict__ lo)
{
    const int i = blockIdx.x * 256 + threadIdx.x;
    float4 v = *(const float4*)(X + (size_t)i * 4);
    __nv_bfloat16 h[4], l[4];
    float vv[4] = {v.x, v.y, v.z, v.w};
#pragma unroll
    for (int j = 0; j < 4; j++) spl(vv[j], h[j], l[j]);
    *(uint2*)(hi + (size_t)i * 4) = *(uint2*)h;
    *(uint2*)(lo + (size_t)i * 4) = *(uint2*)l;
}

__global__ void wsplit(const float* __restrict__ W, __nv_bfloat16* __restrict__ Whi,
                       __nv_bfloat16* __restrict__ Wlo)
{
    __shared__ float t[32][33];
    const int n0 = blockIdx.x * 32, k0 = blockIdx.y * 32;
    const int tx = threadIdx.x & 31, ty = threadIdx.x >> 5;
#pragma unroll
    for (int i = 0; i < 32; i += 8)
        t[ty + i][tx] = W[(size_t)(k0 + ty + i) * DD + n0 + tx];
    __syncthreads();
#pragma unroll
    for (int i = 0; i < 32; i += 8) {
        __nv_bfloat16 h, l;
        spl(t[tx][ty + i], h, l);
        Whi[(size_t)(n0 + ty + i) * DD + k0 + tx] = h;
        Wlo[(size_t)(n0 + ty + i) * DD + k0 + tx] = l;
    }
}

#define KC 32
#define ASTRIDE 40
#define MAT_B (128*ASTRIDE*2)
#define STG_B (4*MAT_B)
#define GSM_TOTAL (2*STG_B)

__global__ __launch_bounds__(256)
void mmagemm(const __nv_bfloat16* __restrict__ Ahi, const __nv_bfloat16* __restrict__ Alo,
             const __nv_bfloat16* __restrict__ Bhi, const __nv_bfloat16* __restrict__ Blo,
             float* __restrict__ C)
{
    extern __shared__ char smem[];
    const uint32_t sb = smem_to_u32(smem);
    const int tid = threadIdx.x, l = tid & 31, wid = tid >> 5;
    const int wm = wid >> 2, wn = wid & 3;
    const int m0 = blockIdx.y * 128, n0 = blockIdx.x * 128;
    float c[4][4][4];
#pragma unroll
    for (int i = 0; i < 4; i++)
#pragma unroll
        for (int j = 0; j < 4; j++)
#pragma unroll
            for (int k = 0; k < 4; k++) c[i][j][k] = 0.f;
    const __nv_bfloat16* gsrc[4] = {Ahi + (size_t)m0 * DD, Alo + (size_t)m0 * DD,
                                    Bhi + (size_t)n0 * DD, Blo + (size_t)n0 * DD};
    const int prow = tid >> 2, pseg = tid & 3;
    {
#pragma unroll
        for (int u = 0; u < 2; u++)
#pragma unroll
            for (int mt = 0; mt < 4; mt++)
                CP_ASYNC16(sb + mt * MAT_B + (prow + u * 64) * 80 + pseg * 16,
                           gsrc[mt] + (size_t)(prow + u * 64) * DD + pseg * 8);
        CP_COMMIT();
    }
    const int arow = (l & 7) + ((l >> 3) & 1) * 8;
    const int acolh = (l >> 4) * 8;
    const int brow = (l & 7) + ((l >> 4) & 1) * 8;
    const int bcolh = ((l >> 3) & 1) * 8;
    for (int ch = 0; ch < DD / KC; ch++) {
        asm volatile("cp.async.wait_group 0;" ::: "memory");
        __syncthreads();
        if (ch + 1 < DD / KC) {
            const int koff = (ch + 1) * KC;
            const uint32_t dbase = sb + ((ch + 1) & 1) * STG_B;
#pragma unroll
            for (int u = 0; u < 2; u++)
#pragma unroll
                for (int mt = 0; mt < 4; mt++)
                    CP_ASYNC16(dbase + mt * MAT_B + (prow + u * 64) * 80 + pseg * 16,
                               gsrc[mt] + (size_t)(prow + u * 64) * DD + koff + pseg * 8);
            CP_COMMIT();
        }
        const uint32_t sA = sb + (ch & 1) * STG_B;
#pragma unroll
        for (int ks = 0; ks < 2; ks++) {
            uint32_t ah[4][4], al[4][4], bh[2][4], bl[2][4];
#pragma unroll
            for (int mi = 0; mi < 4; mi++) {
                const uint32_t off = (uint32_t)((wm * 64 + mi * 16 + arow) * ASTRIDE + ks * 16 + acolh) * 2;
                LDSM_X4(ah[mi], sA + off);
                LDSM_X4(al[mi], sA + MAT_B + off);
            }
#pragma unroll
            for (int np = 0; np < 2; np++) {
                const uint32_t off = (uint32_t)((wn * 32 + np * 16 + brow) * ASTRIDE + ks * 16 + bcolh) * 2;
                LDSM_X4(bh[np], sA + 2 * MAT_B + off);
                LDSM_X4(bl[np], sA + 3 * MAT_B + off);
            }
#pragma unroll
            for (int mi = 0; mi < 4; mi++)
#pragma unroll
                for (int nj = 0; nj < 4; nj++) {
                    const uint32_t* bhp = &bh[nj >> 1][(nj & 1) * 2];
                    const uint32_t* blp = &bl[nj >> 1][(nj & 1) * 2];
                    MMA_B16(c[mi][nj], ah[mi], bhp[0], bhp[1]);
                    MMA_B16(c[mi][nj], ah[mi], blp[0], blp[1]);
                    MMA_B16(c[mi][nj], al[mi], bhp[0], bhp[1]);
                }
        }
    }
#pragma unroll
    for (int mi = 0; mi < 4; mi++)
#pragma unroll
        for (int nj = 0; nj < 4; nj++) {
            const int r0 = m0 + wm * 64 + mi * 16 + (l >> 2);
            const int cb = n0 + wn * 32 + nj * 8 + (l & 3) * 2;
            *(float2*)(C + (size_t)r0 * DD + cb)       = make_float2(c[mi][nj][0], c[mi][nj][1]);
            *(float2*)(C + (size_t)(r0 + 8) * DD + cb) = make_float2(c[mi][nj][2], c[mi][nj][3]);
        }
}

__global__ void sgemm_n4(const float* __restrict__ X, const float* __restrict__ W,
                         float* __restrict__ O)
{
    const int warp = threadIdx.x >> 5, lane = threadIdx.x & 31;
    const int row = blockIdx.x * 8 + warp;
    const float* x = X + (size_t)row * DD;
    float a0 = 0.f, a1 = 0.f, a2 = 0.f, a3 = 0.f;
    for (int k = lane; k < DD; k += 32) {
        float xv = x[k];
        float4 w = *(const float4*)(W + k * 4);
        a0 += xv * w.x; a1 += xv * w.y; a2 += xv * w.z; a3 += xv * w.w;
    }
#pragma unroll
    for (int o = 16; o; o >>= 1) {
        a0 += __shfl_xor_sync(~0u, a0, o); a1 += __shfl_xor_sync(~0u, a1, o);
        a2 += __shfl_xor_sync(~0u, a2, o); a3 += __shfl_xor_sync(~0u, a3, o);
    }
    if (lane == 0) *(float4*)(O + row * 4) = make_float4(a0, a1, a2, a3);
}

__global__ void lam_kernel(const float* __restrict__ XSG, float* __restrict__ LAM)
{
    const int b = blockIdx.x >> 2, h = blockIdx.x & 3;
    const int tid = threadIdx.x;
    __shared__ float ssum[256];
    float loc[8], run = 0.f;
    const int t0 = tid * 8;
#pragma unroll
    for (int u = 0; u < 8; u++) {
        float x = XSG[(size_t)(b * TT + t0 + u) * HH + h];
        float lg = (x >= 0.f) ? -log1pf(expf(-x)) : (x - log1pf(expf(x)));
        run += lg * (1.f / 16.f);
        loc[u] = run;
    }
    ssum[tid] = run;
    __syncthreads();
    for (int off = 1; off < 256; off <<= 1) {
        float v = (tid >= off) ? ssum[tid - off] : 0.f;
        __syncthreads();
        ssum[tid] += v;
        __syncthreads();
    }
    float excl = ssum[tid] - run;
#pragma unroll
    for (int u = 0; u < 8; u++)
        LAM[(size_t)(b * HH + h) * TT + t0 + u] = expf(excl + loc[u]);
}

// RoPE+decay, fp32 in (orig layout) -> bf16 hi/lo out (bh-major)
__global__ void rope_split(const float* __restrict__ Q, const float* __restrict__ K,
                           const float* __restrict__ LAM,
                           __nv_bfloat16* QH, __nv_bfloat16* QL,
                           __nv_bfloat16* KH, __nv_bfloat16* KL)
{
    const int idx = blockIdx.x * 256 + threadIdx.x;
    const int i = idx & 127, h = (idx >> 7) & 3, t = (idx >> 9) & 2047, b = idx >> 20;
    float inv = powf(10000.f, -(float)i * (1.f / 128.f));
    float sn, cs; sincosf((float)t * inv, &sn, &cs);
    const size_t src = ((size_t)(b * TT + t) * HH + h) * 256;
    const size_t dst = ((size_t)(b * HH + h) * TT + t) * 256;
    float lam = LAM[(size_t)(b * HH + h) * TT + t];
    float q1 = Q[src + i], q2 = Q[src + i + 128], k1 = K[src + i], k2 = K[src + i + 128];
    float o0 = (q1 * cs - q2 * sn) * 0.0625f, o1 = (q2 * cs + q1 * sn) * 0.0625f;
    float o2 = (k1 * cs - k2 * sn) * lam,     o3 = (k2 * cs + k1 * sn) * lam;
    __nv_bfloat16 hh, ll;
    spl(o0, hh, ll); QH[dst + i] = hh;       QL[dst + i] = ll;
    spl(o1, hh, ll); QH[dst + i + 128] = hh; QL[dst + i + 128] = ll;
    spl(o2, hh, ll); KH[dst + i] = hh;       KL[dst + i] = ll;
    spl(o3, hh, ll); KH[dst + i + 128] = hh; KL[dst + i + 128] = ll;
}

// E=exp(clip(s)); ACC cumsum (bh-major); E splits row-major + transposed
__global__ void scan_split(const float* __restrict__ S, float* __restrict__ ACC,
                           __nv_bfloat16* EH, __nv_bfloat16* EL,
                           __nv_bfloat16* ETH, __nv_bfloat16* ETL)
{
    const int bh = blockIdx.x, b = bh >> 2, h = bh & 3;
    const int ml = threadIdx.x & 31, tc = threadIdx.x >> 5;
    const int m = blockIdx.y * 32 + ml;
    __shared__ float sums[8][33];
    const size_t src = (size_t)b * TT * DD + h * 256 + m;
    const size_t dR = (size_t)bh * TT * 256 + m;
    const size_t dT = (size_t)bh * TT * 256 + (size_t)m * TT;
    float a = 0.f;
    for (int t = tc * 256; t < tc * 256 + 256; t++)
        a += expf(fminf(fmaxf(S[src + (size_t)t * DD], -32.f), 32.f));
    sums[tc][ml] = a;
    __syncthreads();
    a = 0.f;
    for (int p = 0; p < tc; p++) a += sums[p][ml];
    for (int t = tc * 256; t < tc * 256 + 256; t++) {
        float e = expf(fminf(fmaxf(S[src + (size_t)t * DD], -32.f), 32.f));
        a += e;
        ACC[dR + (size_t)t * 256] = a;
        __nv_bfloat16 hh, ll;
        spl(e, hh, ll);
        EH[dR + (size_t)t * 256] = hh; EL[dR + (size_t)t * 256] = ll;
        ETH[dT + t] = hh; ETL[dT + t] = ll;
    }
}

// V (orig layout) -> VT hi/lo (bh-major [v][t])
__global__ void vtsplit(const float* __restrict__ V, __nv_bfloat16* VTH, __nv_bfloat16* VTL)
{
    __shared__ float tile[32][33];
    const int bh = blockIdx.z, b = bh >> 2, h = bh & 3;
    const int t0 = blockIdx.x * 32, v0 = blockIdx.y * 32;
    const int tx = threadIdx.x & 31, ty = threadIdx.x >> 5;
#pragma unroll
    for (int i = 0; i < 32; i += 8)
        tile[ty + i][tx] = V[(size_t)(b * TT + t0 + ty + i) * DD + h * 256 + v0 + tx];
    __syncthreads();
#pragma unroll
    for (int i = 0; i < 32; i += 8) {
        __nv_bfloat16 hh, ll;
        spl(tile[tx][ty + i], hh, ll);
        const size_t d = (size_t)bh * TT * 256 + (size_t)(v0 + ty + i) * TT + t0 + tx;
        VTH[d] = hh; VTL[d] = ll;
    }
}

// ---- MMA attention: PASS0 softmax epilogue -> U splits; PASS1 rms/silu -> ACT ----
#define QSH 0
#define QSL 33792
#define YSH 67584
#define YSL 101376
#define ZSH 135168
#define ZSL 172032
#define SSH 208896
#define SSL 218112
#define ASMEM 227328
#define XSTR 264
#define ZSTR 72

template <int PASS>
__global__ __launch_bounds__(256)
void attn_mma(const __nv_bfloat16* __restrict__ XH, const __nv_bfloat16* __restrict__ XL,
              const __nv_bfloat16* __restrict__ YH, const __nv_bfloat16* __restrict__ YL,
              const __nv_bfloat16* __restrict__ ZH, const __nv_bfloat16* __restrict__ ZL,
              const float* __restrict__ ACC, const float* __restrict__ G,
              const float* __restrict__ gnw, float* __restrict__ OutF,
              __nv_bfloat16* __restrict__ OutH, __nv_bfloat16* __restrict__ OutL)
{
    extern __shared__ char sm[];
    const uint32_t sb = smem_to_u32(sm);
    const int tid = threadIdx.x, l = tid & 31, wid = tid >> 5;
    const int wm = wid >> 2, wn = wid & 3;
    const int qi = gridDim.x - 1 - blockIdx.x;
    const int bh = blockIdx.y;
    const int qBase = qi * 64;
    const size_t base = (size_t)bh * TT * 256;
    const int pr = tid >> 2, ps = tid & 3;

#define LOADXY(dH, dL, sH, sL, rb) do { \
    const __nv_bfloat16* _h = (sH) + base + (size_t)((rb) + pr) * 256; \
    const __nv_bfloat16* _l = (sL) + base + (size_t)((rb) + pr) * 256; \
    _Pragma("unroll") \
    for (int s = ps; s < 32; s += 4) { \
        CP_ASYNC16((dH) + pr * XSTR * 2 + s * 16, _h + s * 8); \
        CP_ASYNC16((dL) + pr * XSTR * 2 + s * 16, _l + s * 8); \
    } } while (0)
#define LOADZ(kb) do { \
    const __nv_bfloat16* _h = ZH + base + (size_t)tid * TT + (kb); \
    const __nv_bfloat16* _l = ZL + base + (size_t)tid * TT + (kb); \
    _Pragma("unroll") \
    for (int s = 0; s < 8; s++) { \
        CP_ASYNC16(sb + ZSH + tid * ZSTR * 2 + s * 16, _h + s * 8); \
        CP_ASYNC16(sb + ZSL + tid * ZSTR * 2 + s * 16, _l + s * 8); \
    } } while (0)

    LOADXY(sb + QSH, sb + QSL, XH, XL, qBase);
    LOADXY(sb + YSH, sb + YSL, YH, YL, 0);
    CP_COMMIT();
    LOADZ(0);
    CP_COMMIT();

    const int arow = (l & 7) + ((l >> 3) & 1) * 8;
    const int acolh = (l >> 4) * 8;
    const int brow = (l & 7) + ((l >> 4) & 1) * 8;
    const int bcolh = ((l >> 3) & 1) * 8;

    float ok[2][8][4];
#pragma unroll
    for (int i = 0; i < 2; i++)
#pragma unroll
        for (int j = 0; j < 8; j++)
#pragma unroll
            for (int k = 0; k < 4; k++) ok[i][j][k] = 0.f;

    for (int kc = 0; kc <= qi; kc++) {
        asm volatile("cp.async.wait_group 1;" ::: "memory");
        __syncthreads();
        // phase A: S = X(64x256) . Y(64x256)^T
        float s4[2][2][4];
#pragma unroll
        for (int i = 0; i < 2; i++)
#pragma unroll
            for (int j = 0; j < 2; j++)
#pragma unroll
                for (int k = 0; k < 4; k++) s4[i][j][k] = 0.f;
#pragma unroll 4
        for (int ks = 0; ks < 16; ks++) {
            uint32_t ah[2][4], al[2][4], bhf[4], blf[4];
#pragma unroll
            for (int mi = 0; mi < 2; mi++) {
                const uint32_t off = (uint32_t)((wm * 32 + mi * 16 + arow) * XSTR + ks * 16 + acolh) * 2;
                LDSM_X4(ah[mi], sb + QSH + off);
                LDSM_X4(al[mi], sb + QSL + off);
            }
            const uint32_t bo = (uint32_t)((wn * 16 + brow) * XSTR + ks * 16 + bcolh) * 2;
            LDSM_X4(bhf, sb + YSH + bo);
            LDSM_X4(blf, sb + YSL + bo);
#pragma unroll
            for (int mi = 0; mi < 2; mi++)
#pragma unroll
                for (int nj = 0; nj < 2; nj++) {
                    MMA_B16(s4[mi][nj], ah[mi], bhf[nj * 2], bhf[nj * 2 + 1]);
                    MMA_B16(s4[mi][nj], ah[mi], blf[nj * 2], blf[nj * 2 + 1]);
                    MMA_B16(s4[mi][nj], al[mi], bhf[nj * 2], bhf[nj * 2 + 1]);
                }
        }
        __syncthreads();
        const bool diag = (kc == qi);
#pragma unroll
        for (int mi = 0; mi < 2; mi++)
#pragma unroll
            for (int nj = 0; nj < 2; nj++)
#pragma unroll
                for (int hf = 0; hf < 2; hf++) {
                    const int r = wm * 32 + mi * 16 + (l >> 2) + hf * 8;
                    const int c = wn * 16 + nj * 8 + (l & 3) * 2;
                    float v0 = s4[mi][nj][hf * 2], v1 = s4[mi][nj][hf * 2 + 1];
                    if (diag) { if (c > r) v0 = 0.f; if (c + 1 > r) v1 = 0.f; }
                    __nv_bfloat16 h0, l0, h1, l1;
                    spl(v0, h0, l0); spl(v1, h1, l1);
                    *(uint32_t*)(sm + SSH + (r * ZSTR + c) * 2) = pkbf(h0, h1);
                    *(uint32_t*)(sm + SSL + (r * ZSTR + c) * 2) = pkbf(l0, l1);
                }
        if (kc < qi) { LOADXY(sb + YSH, sb + YSL, YH, YL, (kc + 1) * 64); CP_COMMIT(); }
        if (kc == qi) asm volatile("cp.async.wait_group 0;" ::: "memory");
        else          asm volatile("cp.async.wait_group 1;" ::: "memory");
        __syncthreads();
        // phase B: ok(64x256) += S(64x64) . Z(256x64)^T
#pragma unroll
        for (int ks = 0; ks < 4; ks++) {
            uint32_t ah[2][4], al[2][4];
#pragma unroll
            for (int mi = 0; mi < 2; mi++) {
                const uint32_t off = (uint32_t)((wm * 32 + mi * 16 + arow) * ZSTR + ks * 16 + acolh) * 2;
                LDSM_X4(ah[mi], sb + SSH + off);
                LDSM_X4(al[mi], sb + SSL + off);
            }
#pragma unroll
            for (int np = 0; np < 4; np++) {
                uint32_t bhf[4], blf[4];
                const uint32_t bo = (uint32_t)((wn * 64 + np * 16 + brow) * ZSTR + ks * 16 + bcolh) * 2;
                LDSM_X4(bhf, sb + ZSH + bo);
                LDSM_X4(blf, sb + ZSL + bo);
#pragma unroll
                for (int mi = 0; mi < 2; mi++)
#pragma unroll
                    for (int nj = 0; nj < 2; nj++) {
                        MMA_B16(ok[mi][np * 2 + nj], ah[mi], bhf[nj * 2], bhf[nj * 2 + 1]);
                        MMA_B16(ok[mi][np * 2 + nj], ah[mi], blf[nj * 2], blf[nj * 2 + 1]);
                        MMA_B16(ok[mi][np * 2 + nj], al[mi], bhf[nj * 2], bhf[nj * 2 + 1]);
                    }
            }
        }
        __syncthreads();
        if (kc < qi) { LOADZ((kc + 1) * 64); CP_COMMIT(); }
    }

    // dump ok to smem fp32 [64][258] (overlays Z buffers)
    float* OKS = (float*)(sm + ZSH);
#pragma unroll
    for (int mi = 0; mi < 2; mi++)
#pragma unroll
        for (int nj = 0; nj < 8; nj++)
#pragma unroll
            for (int hf = 0; hf < 2; hf++) {
                const int r = wm * 32 + mi * 16 + (l >> 2) + hf * 8;
                const int c = wn * 64 + nj * 8 + (l & 3) * 2;
                *(float2*)&OKS[r * 258 + c] = make_float2(ok[mi][nj][hf * 2], ok[mi][nj][hf * 2 + 1]);
            }
    __syncthreads();
#pragma unroll
    for (int i = 0; i < 8; i++) {
        const int r = wid * 8 + i, t = qBase + r;
        if (PASS == 0) {
            float v[8], acr[8], mx = -3.4e38f;
#pragma unroll
            for (int j = 0; j < 8; j++) {
                const int c = j * 32 + l;
                acr[j] = ACC[base + (size_t)t * 256 + c];
                v[j] = OKS[r * 258 + c] / acr[j];
                mx = fmaxf(mx, v[j]);
            }
#pragma unroll
            for (int o = 16; o; o >>= 1) mx = fmaxf(mx, __shfl_xor_sync(~0u, mx, o));
            float e[8], s = 0.f;
#pragma unroll
            for (int j = 0; j < 8; j++) { e[j] = expf(v[j] - mx); s += e[j]; }
#pragma unroll
            for (int o = 16; o; o >>= 1) s += __shfl_xor_sync(~0u, s, o);
            const float inv = 1.f / s;
#pragma unroll
            for (int j = 0; j < 8; j++) {
                const int c = j * 32 + l;
                float u = e[j] * inv / acr[j];
                __nv_bfloat16 hh, ll;
                spl(u, hh, ll);
                OutH[base + (size_t)t * 256 + c] = hh;
                OutL[base + (size_t)t * 256 + c] = ll;
            }
        } else {
            float vv[8], ss = 0.f;
#pragma unroll
            for (int j = 0; j < 8; j++) { vv[j] = OKS[r * 258 + j * 32 + l]; ss += vv[j] * vv[j]; }
#pragma unroll
            for (int o = 16; o; o >>= 1) ss += __shfl_xor_sync(~0u, ss, o);
            const float rn = rsqrtf(ss * (1.f / 256.f) + 1e-5f);
            const int b = bh >> 2, h = bh & 3;
#pragma unroll
            for (int j = 0; j < 8; j++) {
                const int c = j * 32 + l;
                const size_t gi = (size_t)(b * TT + t) * DD + h * 256 + c;
                float gg = G[gi], sig = 1.f / (1.f + expf(-gg));
                OutF[gi] = vv[j] * rn * gnw[c] * gg * sig;
            }
        }
    }
}

extern "C" void kernel_launch(void* const* d_in, const int* in_sizes, int n_in,
                              void* d_out, int out_size)
{
    const float* x   = (const float*)d_in[0];
    const float* qw  = (const float*)d_in[1];
    const float* kw  = (const float*)d_in[2];
    const float* vw  = (const float*)d_in[3];
    const float* gw  = (const float*)d_in[4];
    const float* sw  = (const float*)d_in[5];
    const float* sgw = (const float*)d_in[6];
    const float* gnw = (const float*)d_in[7];
    const float* ow  = (const float*)d_in[8];
    float* out = (float*)d_out;

    float *Q, *K, *V, *G, *S, *ACC, *ACT, *XSG, *LAM;
    __nv_bfloat16 *XHI, *XLO, *WHI, *WLO, *QHI, *QLO, *KHI, *KLO;
    __nv_bfloat16 *EHI, *ELO, *ETHI, *ETLO, *UHI, *ULO, *VTHI, *VTLO;
    cudaGetSymbolAddress((void**)&Q, g_Q);     cudaGetSymbolAddress((void**)&K, g_K);
    cudaGetSymbolAddress((void**)&V, g_V);     cudaGetSymbolAddress((void**)&G, g_G);
    cudaGetSymbolAddress((void**)&S, g_S);     cudaGetSymbolAddress((void**)&ACC, g_ACC);
    cudaGetSymbolAddress((void**)&ACT, g_ACT); cudaGetSymbolAddress((void**)&XSG, g_XSG);
    cudaGetSymbolAddress((void**)&LAM, g_LAM);
    cudaGetSymbolAddress((void**)&XHI, g_XHI); cudaGetSymbolAddress((void**)&XLO, g_XLO);
    cudaGetSymbolAddress((void**)&WHI, g_WHI); cudaGetSymbolAddress((void**)&WLO, g_WLO);
    cudaGetSymbolAddress((void**)&QHI, g_QHI); cudaGetSymbolAddress((void**)&QLO, g_QLO);
    cudaGetSymbolAddress((void**)&KHI, g_KHI); cudaGetSymbolAddress((void**)&KLO, g_KLO);
    cudaGetSymbolAddress((void**)&EHI, g_EHI); cudaGetSymbolAddress((void**)&ELO, g_ELO);
    cudaGetSymbolAddress((void**)&ETHI, g_ETHI); cudaGetSymbolAddress((void**)&ETLO, g_ETLO);
    cudaGetSymbolAddress((void**)&UHI, g_UHI); cudaGetSymbolAddress((void**)&ULO, g_ULO);
    cudaGetSymbolAddress((void**)&VTHI, g_VTHI); cudaGetSymbolAddress((void**)&VTLO, g_VTLO);

    static int done = 0;
    if (!done) {
        cudaFuncSetAttribute(mmagemm, cudaFuncAttributeMaxDynamicSharedMemorySize, GSM_TOTAL);
        cudaFuncSetAttribute(attn_mma<0>, cudaFuncAttributeMaxDynamicSharedMemorySize, ASMEM);
        cudaFuncSetAttribute(attn_mma<1>, cudaFuncAttributeMaxDynamicSharedMemorySize, ASMEM);
        done = 1;
    }

    const dim3 wgrid(32, 32);
    const dim3 ggrid(DD / 128, BT / 128);
    const int sxg = (BT * DD / 4) / 256;

    splitx<<<sxg, 256>>>(x, XHI, XLO);
    sgemm_n4<<<BT / 8, 256>>>(x, sgw, XSG);
    wsplit<<<wgrid, 256>>>(qw, WHI, WLO);
    mmagemm<<<ggrid, 256, GSM_TOTAL>>>(XHI, XLO, WHI, WLO, Q);
    wsplit<<<wgrid, 256>>>(kw, WHI, WLO);
    mmagemm<<<ggrid, 256, GSM_TOTAL>>>(XHI, XLO, WHI, WLO, K);
    wsplit<<<wgrid, 256>>>(vw, WHI, WLO);
    mmagemm<<<ggrid, 256, GSM_TOTAL>>>(XHI, XLO, WHI, WLO, V);
    wsplit<<<wgrid, 256>>>(gw, WHI, WLO);
    mmagemm<<<ggrid, 256, GSM_TOTAL>>>(XHI, XLO, WHI, WLO, G);
    wsplit<<<wgrid, 256>>>(sw, WHI, WLO);
    mmagemm<<<ggrid, 256, GSM_TOTAL>>>(XHI, XLO, WHI, WLO, S);

    lam_kernel<<<BH, 256>>>(XSG, LAM);
    rope_split<<<(BB * TT * HH * 128) / 256, 256>>>(Q, K, LAM, QHI, QLO, KHI, KLO);
    scan_split<<<dim3(BH, 8), 256>>>(S, ACC, EHI, ELO, ETHI, ETLO);
    vtsplit<<<dim3(TT / 32, 8, BH), 256>>>(V, VTHI, VTLO);

    attn_mma<0><<<dim3(TT / 64, BH), 256, ASMEM>>>(QHI, QLO, KHI, KLO, ETHI, ETLO,
                                                   ACC, nullptr, nullptr, nullptr, UHI, ULO);
    attn_mma<1><<<dim3(TT / 64, BH), 256, ASMEM>>>(UHI, ULO, EHI, ELO, VTHI, VTLO,
                                                   nullptr, G, gnw, ACT, nullptr, nullptr);

    splitx<<<sxg, 256>>>(ACT, XHI, XLO);
    wsplit<<<wgrid, 256>>>(ow, WHI, WLO);
    mmagemm<<<ggrid, 256, GSM_TOTAL>>>(XHI, XLO, WHI, WLO, out);
}

// round 7
// speedup vs baseline: 2.4282x; 1.0550x over previous
#include <cuda_runtime.h>
#include <cuda_bf16.h>
#include <math.h>
#include <stdint.h>

#define BB 4
#define TT 2048
#define HH 4
#define DD 1024
#define PD 5120
#define BT (BB*TT)
#define BH 16

__device__ float g_P[(size_t)BT*PD], g_ACC[BT*DD], g_ACT[BT*DD], g_XSG[BT*HH], g_LAM[BH*TT];
__device__ __nv_bfloat16 g_XHI[BT*DD], g_XLO[BT*DD], g_WHI[(size_t)PD*DD], g_WLO[(size_t)PD*DD];
__device__ __nv_bfloat16 g_QHI[BT*DD], g_QLO[BT*DD], g_KHI[BT*DD], g_KLO[BT*DD];
__device__ __nv_bfloat16 g_EHI[BT*DD], g_ELO[BT*DD], g_ETHI[BT*DD], g_ETLO[BT*DD];
__device__ __nv_bfloat16 g_VTHI[BT*DD], g_VTLO[BT*DD];

__device__ __forceinline__ uint32_t smem_to_u32(const void* p) {
    uint32_t a;
    asm("{ .reg .u64 t; cvta.to.shared.u64 t, %1; cvt.u32.u64 %0, t; }" : "=r"(a) : "l"(p));
    return a;
}
#define CP_ASYNC16(d, s) asm volatile("cp.async.cg.shared.global [%0], [%1], 16;" :: "r"(d), "l"(s))
#define CP_COMMIT() asm volatile("cp.async.commit_group;" ::: "memory")
#define LDSM_X4(r, a) \
    asm volatile("ldmatrix.sync.aligned.m8n8.x4.shared.b16 {%0,%1,%2,%3}, [%4];" \
        : "=r"((r)[0]),"=r"((r)[1]),"=r"((r)[2]),"=r"((r)[3]) : "r"(a))
#define MMA_B16(c, a, b0, b1) \
    asm volatile("mma.sync.aligned.m16n8k16.row.col.f32.bf16.bf16.f32 " \
        "{%0,%1,%2,%3},{%4,%5,%6,%7},{%8,%9},{%0,%1,%2,%3};" \
        : "+f"((c)[0]),"+f"((c)[1]),"+f"((c)[2]),"+f"((c)[3]) \
        : "r"((a)[0]),"r"((a)[1]),"r"((a)[2]),"r"((a)[3]), "r"(b0),"r"(b1))
__device__ __forceinline__ void spl(float x, __nv_bfloat16& h, __nv_bfloat16& l) {
    h = __float2bfloat16(x); l = __float2bfloat16(x - __bfloat162float(h));
}
__device__ __forceinline__ uint32_t pkbf(__nv_bfloat16 a, __nv_bfloat16 b) {
    return (uint32_t)*(uint16_t*)&a | ((uint32_t)*(uint16_t*)&b << 16);
}

__global__ void splitx(const float* __restrict__ X, __nv_bfloat16* __restrict__ hi,
                       __nv_bfloat16* __restrict__ lo)
{
    const int i = blockIdx.x * 256 + threadIdx.x;
    float4 v = *(const float4*)(X + (size_t)i * 4);
    __nv_bfloat16 h[4], l[4];
    float vv[4] = {v.x, v.y, v.z, v.w};
#pragma unroll
    for (int j = 0; j < 4; j++) spl(vv[j], h[j], l[j]);
    *(uint2*)(hi + (size_t)i * 4) = *(uint2*)h;
    *(uint2*)(lo + (size_t)i * 4) = *(uint2*)l;
}

// W[k][n] (row-major 1024x1024) -> Whi/Wlo[noff+n][k]
__global__ void wsplit(const float* __restrict__ W, __nv_bfloat16* __restrict__ Whi,
                       __nv_bfloat16* __restrict__ Wlo, int noff)
{
    __shared__ float t[32][33];
    const int n0 = blockIdx.x * 32, k0 = blockIdx.y * 32;
    const int tx = threadIdx.x & 31, ty = threadIdx.x >> 5;
#pragma unroll
    for (int i = 0; i < 32; i += 8)
        t[ty + i][tx] = W[(size_t)(k0 + ty + i) * DD + n0 + tx];
    __syncthreads();
#pragma unroll
    for (int i = 0; i < 32; i += 8) {
        __nv_bfloat16 h, l;
        spl(t[tx][ty + i], h, l);
        Whi[(size_t)(noff + n0 + ty + i) * DD + k0 + tx] = h;
        Wlo[(size_t)(noff + n0 + ty + i) * DD + k0 + tx] = l;
    }
}

#define KC 32
#define ASTRIDE 40
#define MAT_B (128*ASTRIDE*2)
#define STG_B (4*MAT_B)
#define GSM_TOTAL (2*STG_B)

__global__ __launch_bounds__(256)
void mmagemm(const __nv_bfloat16* __restrict__ Ahi, const __nv_bfloat16* __restrict__ Alo,
             const __nv_bfloat16* __restrict__ Bhi, const __nv_bfloat16* __restrict__ Blo,
             float* __restrict__ C, int cs)
{
    extern __shared__ char smem[];
    const uint32_t sb = smem_to_u32(smem);
    const int tid = threadIdx.x, l = tid & 31, wid = tid >> 5;
    const int wm = wid >> 2, wn = wid & 3;
    const int m0 = blockIdx.y * 128, n0 = blockIdx.x * 128;
    float c[4][4][4];
#pragma unroll
    for (int i = 0; i < 4; i++)
#pragma unroll
        for (int j = 0; j < 4; j++)
#pragma unroll
            for (int k = 0; k < 4; k++) c[i][j][k] = 0.f;
    const __nv_bfloat16* gsrc[4] = {Ahi + (size_t)m0 * DD, Alo + (size_t)m0 * DD,
                                    Bhi + (size_t)n0 * DD, Blo + (size_t)n0 * DD};
    const int prow = tid >> 2, pseg = tid & 3;
    {
#pragma unroll
        for (int u = 0; u < 2; u++)
#pragma unroll
            for (int mt = 0; mt < 4; mt++)
                CP_ASYNC16(sb + mt * MAT_B + (prow + u * 64) * 80 + pseg * 16,
                           gsrc[mt] + (size_t)(prow + u * 64) * DD + pseg * 8);
        CP_COMMIT();
    }
    const int arow = (l & 7) + ((l >> 3) & 1) * 8;
    const int acolh = (l >> 4) * 8;
    const int brow = (l & 7) + ((l >> 4) & 1) * 8;
    const int bcolh = ((l >> 3) & 1) * 8;
    for (int ch = 0; ch < DD / KC; ch++) {
        asm volatile("cp.async.wait_group 0;" ::: "memory");
        __syncthreads();
        if (ch + 1 < DD / KC) {
            const int koff = (ch + 1) * KC;
            const uint32_t dbase = sb + ((ch + 1) & 1) * STG_B;
#pragma unroll
            for (int u = 0; u < 2; u++)
#pragma unroll
                for (int mt = 0; mt < 4; mt++)
                    CP_ASYNC16(dbase + mt * MAT_B + (prow + u * 64) * 80 + pseg * 16,
                               gsrc[mt] + (size_t)(prow + u * 64) * DD + koff + pseg * 8);
            CP_COMMIT();
        }
        const uint32_t sA = sb + (ch & 1) * STG_B;
#pragma unroll
        for (int ks = 0; ks < 2; ks++) {
            uint32_t ah[4][4], al[4][4], bh[2][4], bl[2][4];
#pragma unroll
            for (int mi = 0; mi < 4; mi++) {
                const uint32_t off = (uint32_t)((wm * 64 + mi * 16 + arow) * ASTRIDE + ks * 16 + acolh) * 2;
                LDSM_X4(ah[mi], sA + off);
                LDSM_X4(al[mi], sA + MAT_B + off);
            }
#pragma unroll
            for (int np = 0; np < 2; np++) {
                const uint32_t off = (uint32_t)((wn * 32 + np * 16 + brow) * ASTRIDE + ks * 16 + bcolh) * 2;
                LDSM_X4(bh[np], sA + 2 * MAT_B + off);
                LDSM_X4(bl[np], sA + 3 * MAT_B + off);
            }
#pragma unroll
            for (int mi = 0; mi < 4; mi++)
#pragma unroll
                for (int nj = 0; nj < 4; nj++) {
                    const uint32_t* bhp = &bh[nj >> 1][(nj & 1) * 2];
                    const uint32_t* blp = &bl[nj >> 1][(nj & 1) * 2];
                    MMA_B16(c[mi][nj], ah[mi], bhp[0], bhp[1]);
                    MMA_B16(c[mi][nj], ah[mi], blp[0], blp[1]);
                    MMA_B16(c[mi][nj], al[mi], bhp[0], bhp[1]);
                }
        }
    }
#pragma unroll
    for (int mi = 0; mi < 4; mi++)
#pragma unroll
        for (int nj = 0; nj < 4; nj++) {
            const int r0 = m0 + wm * 64 + mi * 16 + (l >> 2);
            const int cb = n0 + wn * 32 + nj * 8 + (l & 3) * 2;
            *(float2*)(C + (size_t)r0 * cs + cb)       = make_float2(c[mi][nj][0], c[mi][nj][1]);
            *(float2*)(C + (size_t)(r0 + 8) * cs + cb) = make_float2(c[mi][nj][2], c[mi][nj][3]);
        }
}

__global__ void sgemm_n4(const float* __restrict__ X, const float* __restrict__ W,
                         float* __restrict__ O)
{
    const int warp = threadIdx.x >> 5, lane = threadIdx.x & 31;
    const int row = blockIdx.x * 8 + warp;
    const float* x = X + (size_t)row * DD;
    float a0 = 0.f, a1 = 0.f, a2 = 0.f, a3 = 0.f;
    for (int k = lane; k < DD; k += 32) {
        float xv = x[k];
        float4 w = *(const float4*)(W + k * 4);
        a0 += xv * w.x; a1 += xv * w.y; a2 += xv * w.z; a3 += xv * w.w;
    }
#pragma unroll
    for (int o = 16; o; o >>= 1) {
        a0 += __shfl_xor_sync(~0u, a0, o); a1 += __shfl_xor_sync(~0u, a1, o);
        a2 += __shfl_xor_sync(~0u, a2, o); a3 += __shfl_xor_sync(~0u, a3, o);
    }
    if (lane == 0) *(float4*)(O + row * 4) = make_float4(a0, a1, a2, a3);
}

__global__ void lam_kernel(const float* __restrict__ XSG, float* __restrict__ LAM)
{
    const int b = blockIdx.x >> 2, h = blockIdx.x & 3;
    const int tid = threadIdx.x;
    __shared__ float ssum[256];
    float loc[8], run = 0.f;
    const int t0 = tid * 8;
#pragma unroll
    for (int u = 0; u < 8; u++) {
        float x = XSG[(size_t)(b * TT + t0 + u) * HH + h];
        float lg = (x >= 0.f) ? -log1pf(expf(-x)) : (x - log1pf(expf(x)));
        run += lg * (1.f / 16.f);
        loc[u] = run;
    }
    ssum[tid] = run;
    __syncthreads();
    for (int off = 1; off < 256; off <<= 1) {
        float v = (tid >= off) ? ssum[tid - off] : 0.f;
        __syncthreads();
        ssum[tid] += v;
        __syncthreads();
    }
    float excl = ssum[tid] - run;
#pragma unroll
    for (int u = 0; u < 8; u++)
        LAM[(size_t)(b * HH + h) * TT + t0 + u] = expf(excl + loc[u]);
}

// reads Q (P col 0) and K (P col 1024); writes bh-major bf16 splits
__global__ void rope_split(const float* __restrict__ P, const float* __restrict__ LAM,
                           __nv_bfloat16* QH, __nv_bfloat16* QL,
                           __nv_bfloat16* KH, __nv_bfloat16* KL)
{
    const int idx = blockIdx.x * 256 + threadIdx.x;
    const int i = idx & 127, h = (idx >> 7) & 3, t = (idx >> 9) & 2047, b = idx >> 20;
    float inv = powf(10000.f, -(float)i * (1.f / 128.f));
    float sn, cs; sincosf((float)t * inv, &sn, &cs);
    const size_t src = (size_t)(b * TT + t) * PD + h * 256;
    const size_t dst = ((size_t)(b * HH + h) * TT + t) * 256;
    float lam = LAM[(size_t)(b * HH + h) * TT + t];
    float q1 = P[src + i], q2 = P[src + i + 128];
    float k1 = P[src + 1024 + i], k2 = P[src + 1024 + i + 128];
    float o0 = (q1 * cs - q2 * sn) * 0.0625f, o1 = (q2 * cs + q1 * sn) * 0.0625f;
    float o2 = (k1 * cs - k2 * sn) * lam,     o3 = (k2 * cs + k1 * sn) * lam;
    __nv_bfloat16 hh, ll;
    spl(o0, hh, ll); QH[dst + i] = hh;       QL[dst + i] = ll;
    spl(o1, hh, ll); QH[dst + i + 128] = hh; QL[dst + i + 128] = ll;
    spl(o2, hh, ll); KH[dst + i] = hh;       KL[dst + i] = ll;
    spl(o3, hh, ll); KH[dst + i + 128] = hh; KL[dst + i + 128] = ll;
}

// reads s (P col 4096); E splits row-major + transposed; ACC cumsum (bh-major)
__global__ void scan_split(const float* __restrict__ P, float* __restrict__ ACC,
                           __nv_bfloat16* EH, __nv_bfloat16* EL,
                           __nv_bfloat16* ETH, __nv_bfloat16* ETL)
{
    const int bh = blockIdx.x, b = bh >> 2, h = bh & 3;
    const int ml = threadIdx.x & 31, tc = threadIdx.x >> 5;
    const int m = blockIdx.y * 32 + ml;
    __shared__ float sums[8][33];
    const size_t src = (size_t)(b * TT) * PD + 4096 + h * 256 + m;
    const size_t dR = (size_t)bh * TT * 256 + m;
    const size_t dT = (size_t)bh * TT * 256 + (size_t)m * TT;
    float a = 0.f;
    for (int t = tc * 256; t < tc * 256 + 256; t++)
        a += expf(fminf(fmaxf(P[src + (size_t)t * PD], -32.f), 32.f));
    sums[tc][ml] = a;
    __syncthreads();
    a = 0.f;
    for (int p = 0; p < tc; p++) a += sums[p][ml];
    for (int t = tc * 256; t < tc * 256 + 256; t++) {
        float e = expf(fminf(fmaxf(P[src + (size_t)t * PD], -32.f), 32.f));
        a += e;
        ACC[dR + (size_t)t * 256] = a;
        __nv_bfloat16 hh, ll;
        spl(e, hh, ll);
        EH[dR + (size_t)t * 256] = hh; EL[dR + (size_t)t * 256] = ll;
        ETH[dT + t] = hh; ETL[dT + t] = ll;
    }
}

// reads V (P col 2048) -> VT splits (bh-major [v][t])
__global__ void vtsplit(const float* __restrict__ P, __nv_bfloat16* VTH, __nv_bfloat16* VTL)
{
    __shared__ float tile[32][33];
    const int bh = blockIdx.z, b = bh >> 2, h = bh & 3;
    const int t0 = blockIdx.x * 32, v0 = blockIdx.y * 32;
    const int tx = threadIdx.x & 31, ty = threadIdx.x >> 5;
#pragma unroll
    for (int i = 0; i < 32; i += 8)
        tile[ty + i][tx] = P[(size_t)(b * TT + t0 + ty + i) * PD + 2048 + h * 256 + v0 + tx];
    __syncthreads();
#pragma unroll
    for (int i = 0; i < 32; i += 8) {
        __nv_bfloat16 hh, ll;
        spl(tile[tx][ty + i], hh, ll);
        const size_t d = (size_t)bh * TT * 256 + (size_t)(v0 + ty + i) * TT + t0 + tx;
        VTH[d] = hh; VTL[d] = ll;
    }
}

// ---- fused attention ----
#define QSH 0
#define QSL 33792
#define YSH 67584
#define YSL 101376
#define ZSH 135168
#define ZSL 172032
#define SSH 208896
#define SSL 218112
#define ASMEM 227328
#define XSTR 264
#define ZSTR 72

__device__ __forceinline__ void ld_xy(uint32_t dH, uint32_t dL,
    const __nv_bfloat16* sH, const __nv_bfloat16* sL, int tid)
{
    const int pr = tid >> 2, ps = tid & 3;
    const __nv_bfloat16* h = sH + (size_t)pr * 256;
    const __nv_bfloat16* l = sL + (size_t)pr * 256;
#pragma unroll
    for (int s = ps; s < 32; s += 4) {
        CP_ASYNC16(dH + pr * XSTR * 2 + s * 16, h + s * 8);
        CP_ASYNC16(dL + pr * XSTR * 2 + s * 16, l + s * 8);
    }
}
__device__ __forceinline__ void ld_z(uint32_t sb,
    const __nv_bfloat16* zH, const __nv_bfloat16* zL, int tid)
{
    const __nv_bfloat16* h = zH + (size_t)tid * TT;
    const __nv_bfloat16* l = zL + (size_t)tid * TT;
#pragma unroll
    for (int s = 0; s < 8; s++) {
        CP_ASYNC16(sb + ZSH + tid * ZSTR * 2 + s * 16, h + s * 8);
        CP_ASYNC16(sb + ZSL + tid * ZSTR * 2 + s * 16, l + s * 8);
    }
}

// one causal pass: X in QS smem; Y,Z streamed; accumulates ok
__device__ __forceinline__ void stage_loop(char* sm, uint32_t sb, int qi, int tid,
    const __nv_bfloat16* YHb, const __nv_bfloat16* YLb,
    const __nv_bfloat16* ZHb, const __nv_bfloat16* ZLb, float ok[2][8][4])
{
    const int l = tid & 31, wid = tid >> 5, wm = wid >> 2, wn = wid & 3;
    const int arow = (l & 7) + ((l >> 3) & 1) * 8, acolh = (l >> 4) * 8;
    const int brow = (l & 7) + ((l >> 4) & 1) * 8, bcolh = ((l >> 3) & 1) * 8;
    ld_xy(sb + YSH, sb + YSL, YHb, YLb, tid); CP_COMMIT();
    ld_z(sb, ZHb, ZLb, tid); CP_COMMIT();
    for (int kc = 0; kc <= qi; kc++) {
        asm volatile("cp.async.wait_group 1;" ::: "memory");
        __syncthreads();
        float s4[2][2][4];
#pragma unroll
        for (int i = 0; i < 2; i++)
#pragma unroll
            for (int j = 0; j < 2; j++)
#pragma unroll
                for (int k = 0; k < 4; k++) s4[i][j][k] = 0.f;
#pragma unroll 4
        for (int ks = 0; ks < 16; ks++) {
            uint32_t ah[2][4], al[2][4], bhf[4], blf[4];
#pragma unroll
            for (int mi = 0; mi < 2; mi++) {
                const uint32_t off = (uint32_t)((wm * 32 + mi * 16 + arow) * XSTR + ks * 16 + acolh) * 2;
                LDSM_X4(ah[mi], sb + QSH + off);
                LDSM_X4(al[mi], sb + QSL + off);
            }
            const uint32_t bo = (uint32_t)((wn * 16 + brow) * XSTR + ks * 16 + bcolh) * 2;
            LDSM_X4(bhf, sb + YSH + bo);
            LDSM_X4(blf, sb + YSL + bo);
#pragma unroll
            for (int mi = 0; mi < 2; mi++)
#pragma unroll
                for (int nj = 0; nj < 2; nj++) {
                    MMA_B16(s4[mi][nj], ah[mi], bhf[nj * 2], bhf[nj * 2 + 1]);
                    MMA_B16(s4[mi][nj], ah[mi], blf[nj * 2], blf[nj * 2 + 1]);
                    MMA_B16(s4[mi][nj], al[mi], bhf[nj * 2], bhf[nj * 2 + 1]);
                }
        }
        __syncthreads();
        const bool diag = (kc == qi);
#pragma unroll
        for (int mi = 0; mi < 2; mi++)
#pragma unroll
            for (int nj = 0; nj < 2; nj++)
#pragma unroll
                for (int hf = 0; hf < 2; hf++) {
                    const int r = wm * 32 + mi * 16 + (l >> 2) + hf * 8;
                    const int c = wn * 16 + nj * 8 + (l & 3) * 2;
                    float v0 = s4[mi][nj][hf * 2], v1 = s4[mi][nj][hf * 2 + 1];
                    if (diag) { if (c > r) v0 = 0.f; if (c + 1 > r) v1 = 0.f; }
                    __nv_bfloat16 h0, l0, h1, l1;
                    spl(v0, h0, l0); spl(v1, h1, l1);
                    *(uint32_t*)(sm + SSH + (r * ZSTR + c) * 2) = pkbf(h0, h1);
                    *(uint32_t*)(sm + SSL + (r * ZSTR + c) * 2) = pkbf(l0, l1);
                }
        if (kc < qi) {
            ld_xy(sb + YSH, sb + YSL, YHb + (size_t)(kc + 1) * 64 * 256,
                  YLb + (size_t)(kc + 1) * 64 * 256, tid);
            CP_COMMIT();
        }
        if (kc == qi) asm volatile("cp.async.wait_group 0;" ::: "memory");
        else          asm volatile("cp.async.wait_group 1;" ::: "memory");
        __syncthreads();
#pragma unroll
        for (int ks = 0; ks < 4; ks++) {
            uint32_t ah[2][4], al[2][4];
#pragma unroll
            for (int mi = 0; mi < 2; mi++) {
                const uint32_t off = (uint32_t)((wm * 32 + mi * 16 + arow) * ZSTR + ks * 16 + acolh) * 2;
                LDSM_X4(ah[mi], sb + SSH + off);
                LDSM_X4(al[mi], sb + SSL + off);
            }
#pragma unroll
            for (int np = 0; np < 4; np++) {
                uint32_t bhf[4], blf[4];
                const uint32_t bo = (uint32_t)((wn * 64 + np * 16 + brow) * ZSTR + ks * 16 + bcolh) * 2;
                LDSM_X4(bhf, sb + ZSH + bo);
                LDSM_X4(blf, sb + ZSL + bo);
#pragma unroll
                for (int mi = 0; mi < 2; mi++)
#pragma unroll
                    for (int nj = 0; nj < 2; nj++) {
                        MMA_B16(ok[mi][np * 2 + nj], ah[mi], bhf[nj * 2], bhf[nj * 2 + 1]);
                        MMA_B16(ok[mi][np * 2 + nj], ah[mi], blf[nj * 2], blf[nj * 2 + 1]);
                        MMA_B16(ok[mi][np * 2 + nj], al[mi], bhf[nj * 2], bhf[nj * 2 + 1]);
                    }
            }
        }
        __syncthreads();
        if (kc < qi) { ld_z(sb, ZHb + (kc + 1) * 64, ZLb + (kc + 1) * 64, tid); CP_COMMIT(); }
    }
}

__device__ __forceinline__ void dump_ok(char* sm, float ok[2][8][4], int wm, int wn, int l)
{
    float* OKS = (float*)(sm + YSH);
#pragma unroll
    for (int mi = 0; mi < 2; mi++)
#pragma unroll
        for (int nj = 0; nj < 8; nj++)
#pragma unroll
            for (int hf = 0; hf < 2; hf++) {
                const int r = wm * 32 + mi * 16 + (l >> 2) + hf * 8;
                const int c = wn * 64 + nj * 8 + (l & 3) * 2;
                *(float2*)&OKS[r * 258 + c] = make_float2(ok[mi][nj][hf * 2], ok[mi][nj][hf * 2 + 1]);
                ok[mi][nj][hf * 2] = 0.f; ok[mi][nj][hf * 2 + 1] = 0.f;
            }
}

__global__ __launch_bounds__(256)
void attn_fused(const __nv_bfloat16* __restrict__ QH, const __nv_bfloat16* __restrict__ QL,
                const __nv_bfloat16* __restrict__ KH, const __nv_bfloat16* __restrict__ KL,
                const __nv_bfloat16* __restrict__ ETH, const __nv_bfloat16* __restrict__ ETL,
                const __nv_bfloat16* __restrict__ EH, const __nv_bfloat16* __restrict__ EL,
                const __nv_bfloat16* __restrict__ VTH, const __nv_bfloat16* __restrict__ VTL,
                const float* __restrict__ ACC, const float* __restrict__ P,
                const float* __restrict__ gnw, float* __restrict__ ACT)
{
    extern __shared__ char sm[];
    const uint32_t sb = smem_to_u32(sm);
    const int tid = threadIdx.x, l = tid & 31, wid = tid >> 5, wm = wid >> 2, wn = wid & 3;
    const int qi = gridDim.x - 1 - blockIdx.x;
    const int bh = blockIdx.y, b = bh >> 2, h = bh & 3;
    const int qBase = qi * 64;
    const size_t base = (size_t)bh * TT * 256;

    float ok[2][8][4];
#pragma unroll
    for (int i = 0; i < 2; i++)
#pragma unroll
        for (int j = 0; j < 8; j++)
#pragma unroll
            for (int k = 0; k < 4; k++) ok[i][j][k] = 0.f;

    // pass 0: X=Q, Y=K, Z=E^T
    ld_xy(sb + QSH, sb + QSL, QH + base + (size_t)qBase * 256, QL + base + (size_t)qBase * 256, tid);
    stage_loop(sm, sb, qi, tid, KH + base, KL + base, ETH + base, ETL + base, ok);

    dump_ok(sm, ok, wm, wn, l);
    __syncthreads();
    float* OKS = (float*)(sm + YSH);
#pragma unroll
    for (int i = 0; i < 8; i++) {
        const int r = wid * 8 + i, t = qBase + r;
        float v[8], acr[8], mx = -3.4e38f;
#pragma unroll
        for (int j = 0; j < 8; j++) {
            const int c = j * 32 + l;
            acr[j] = ACC[base + (size_t)t * 256 + c];
            v[j] = OKS[r * 258 + c] / acr[j];
            mx = fmaxf(mx, v[j]);
        }
#pragma unroll
        for (int o = 16; o; o >>= 1) mx = fmaxf(mx, __shfl_xor_sync(~0u, mx, o));
        float e[8], s = 0.f;
#pragma unroll
        for (int j = 0; j < 8; j++) { e[j] = expf(v[j] - mx); s += e[j]; }
#pragma unroll
        for (int o = 16; o; o >>= 1) s += __shfl_xor_sync(~0u, s, o);
        const float inv = 1.f / s;
#pragma unroll
        for (int j = 0; j < 8; j++) {
            const int c = j * 32 + l;
            __nv_bfloat16 hh, ll;
            spl(e[j] * inv / acr[j], hh, ll);
            *(__nv_bfloat16*)(sm + QSH + (r * XSTR + c) * 2) = hh;
            *(__nv_bfloat16*)(sm + QSL + (r * XSTR + c) * 2) = ll;
        }
    }
    __syncthreads();

    // pass 1: X=U (in QS smem), Y=E, Z=V^T
    stage_loop(sm, sb, qi, tid, EH + base, EL + base, VTH + base, VTL + base, ok);

    dump_ok(sm, ok, wm, wn, l);
    __syncthreads();
#pragma unroll
    for (int i = 0; i < 8; i++) {
        const int r = wid * 8 + i, t = qBase + r;
        float vv[8], ss = 0.f;
#pragma unroll
        for (int j = 0; j < 8; j++) { vv[j] = OKS[r * 258 + j * 32 + l]; ss += vv[j] * vv[j]; }
#pragma unroll
        for (int o = 16; o; o >>= 1) ss += __shfl_xor_sync(~0u, ss, o);
        const float rn = rsqrtf(ss * (1.f / 256.f) + 1e-5f);
#pragma unroll
        for (int j = 0; j < 8; j++) {
            const int c = j * 32 + l;
            float gg = P[(size_t)(b * TT + t) * PD + 3072 + h * 256 + c];
            float sig = 1.f / (1.f + expf(-gg));
            ACT[(size_t)(b * TT + t) * DD + h * 256 + c] = vv[j] * rn * gnw[c] * gg * sig;
        }
    }
}

extern "C" void kernel_launch(void* const* d_in, const int* in_sizes, int n_in,
                              void* d_out, int out_size)
{
    const float* x   = (const float*)d_in[0];
    const float* qw  = (const float*)d_in[1];
    const float* kw  = (const float*)d_in[2];
    const float* vw  = (const float*)d_in[3];
    const float* gw  = (const float*)d_in[4];
    const float* sw  = (const float*)d_in[5];
    const float* sgw = (const float*)d_in[6];
    const float* gnw = (const float*)d_in[7];
    const float* ow  = (const float*)d_in[8];
    float* out = (float*)d_out;

    float *P, *ACC, *ACT, *XSG, *LAM;
    __nv_bfloat16 *XHI, *XLO, *WHI, *WLO, *QHI, *QLO, *KHI, *KLO;
    __nv_bfloat16 *EHI, *ELO, *ETHI, *ETLO, *VTHI, *VTLO;
    cudaGetSymbolAddress((void**)&P, g_P);     cudaGetSymbolAddress((void**)&ACC, g_ACC);
    cudaGetSymbolAddress((void**)&ACT, g_ACT); cudaGetSymbolAddress((void**)&XSG, g_XSG);
    cudaGetSymbolAddress((void**)&LAM, g_LAM);
    cudaGetSymbolAddress((void**)&XHI, g_XHI); cudaGetSymbolAddress((void**)&XLO, g_XLO);
    cudaGetSymbolAddress((void**)&WHI, g_WHI); cudaGetSymbolAddress((void**)&WLO, g_WLO);
    cudaGetSymbolAddress((void**)&QHI, g_QHI); cudaGetSymbolAddress((void**)&QLO, g_QLO);
    cudaGetSymbolAddress((void**)&KHI, g_KHI); cudaGetSymbolAddress((void**)&KLO, g_KLO);
    cudaGetSymbolAddress((void**)&EHI, g_EHI); cudaGetSymbolAddress((void**)&ELO, g_ELO);
    cudaGetSymbolAddress((void**)&ETHI, g_ETHI); cudaGetSymbolAddress((void**)&ETLO, g_ETLO);
    cudaGetSymbolAddress((void**)&VTHI, g_VTHI); cudaGetSymbolAddress((void**)&VTLO, g_VTLO);

    static int done = 0;
    if (!done) {
        cudaFuncSetAttribute(mmagemm, cudaFuncAttributeMaxDynamicSharedMemorySize, GSM_TOTAL);
        cudaFuncSetAttribute(attn_fused, cudaFuncAttributeMaxDynamicSharedMemorySize, ASMEM);
        done = 1;
    }

    const dim3 wgrid(32, 32);
    const int sxg = (BT * DD / 4) / 256;

    splitx<<<sxg, 256>>>(x, XHI, XLO);
    sgemm_n4<<<BT / 8, 256>>>(x, sgw, XSG);
    wsplit<<<wgrid, 256>>>(qw, WHI, WLO, 0);
    wsplit<<<wgrid, 256>>>(kw, WHI, WLO, 1024);
    wsplit<<<wgrid, 256>>>(vw, WHI, WLO, 2048);
    wsplit<<<wgrid, 256>>>(gw, WHI, WLO, 3072);
    wsplit<<<wgrid, 256>>>(sw, WHI, WLO, 4096);
    mmagemm<<<dim3(PD / 128, BT / 128), 256, GSM_TOTAL>>>(XHI, XLO, WHI, WLO, P, PD);

    lam_kernel<<<BH, 256>>>(XSG, LAM);
    rope_split<<<(BB * TT * HH * 128) / 256, 256>>>(P, LAM, QHI, QLO, KHI, KLO);
    scan_split<<<dim3(BH, 8), 256>>>(P, ACC, EHI, ELO, ETHI, ETLO);
    vtsplit<<<dim3(TT / 32, 8, BH), 256>>>(P, VTHI, VTLO);

    attn_fused<<<dim3(TT / 64, BH), 256, ASMEM>>>(QHI, QLO, KHI, KLO, ETHI, ETLO,
                                                  EHI, ELO, VTHI, VTLO, ACC, P, gnw, ACT);

    splitx<<<sxg, 256>>>(ACT, XHI, XLO);
    wsplit<<<wgrid, 256>>>(ow, WHI, WLO, 0);
    mmagemm<<<dim3(DD / 128, BT / 128), 256, GSM_TOTAL>>>(XHI, XLO, WHI, WLO, out, DD);
}

// round 8
// speedup vs baseline: 2.5445x; 1.0479x over previous
#include <cuda_runtime.h>
#include <cuda_bf16.h>
#include <math.h>
#include <stdint.h>

#define BB 4
#define TT 2048
#define HH 4
#define DD 1024
#define PD 5120
#define BT (BB*TT)
#define BH 16

__device__ float g_P[(size_t)BT*PD], g_ACC[BT*DD], g_XSG[BT*HH], g_LAM[BH*TT];
__device__ __nv_bfloat16 g_XHI[BT*DD], g_XLO[BT*DD], g_WHI[(size_t)PD*DD], g_WLO[(size_t)PD*DD];
__device__ __nv_bfloat16 g_QHI[BT*DD], g_QLO[BT*DD], g_KHI[BT*DD], g_KLO[BT*DD];
__device__ __nv_bfloat16 g_EHI[BT*DD], g_ELO[BT*DD], g_ETHI[BT*DD], g_ETLO[BT*DD];
__device__ __nv_bfloat16 g_VTHI[BT*DD], g_VTLO[BT*DD];

__device__ __forceinline__ uint32_t smem_to_u32(const void* p) {
    uint32_t a;
    asm("{ .reg .u64 t; cvta.to.shared.u64 t, %1; cvt.u32.u64 %0, t; }" : "=r"(a) : "l"(p));
    return a;
}
#define CP_ASYNC16(d, s) asm volatile("cp.async.cg.shared.global [%0], [%1], 16;" :: "r"(d), "l"(s))
#define CP_COMMIT() asm volatile("cp.async.commit_group;" ::: "memory")
#define LDSM_X4(r, a) \
    asm volatile("ldmatrix.sync.aligned.m8n8.x4.shared.b16 {%0,%1,%2,%3}, [%4];" \
        : "=r"((r)[0]),"=r"((r)[1]),"=r"((r)[2]),"=r"((r)[3]) : "r"(a))
#define MMA_B16(c, a, b0, b1) \
    asm volatile("mma.sync.aligned.m16n8k16.row.col.f32.bf16.bf16.f32 " \
        "{%0,%1,%2,%3},{%4,%5,%6,%7},{%8,%9},{%0,%1,%2,%3};" \
        : "+f"((c)[0]),"+f"((c)[1]),"+f"((c)[2]),"+f"((c)[3]) \
        : "r"((a)[0]),"r"((a)[1]),"r"((a)[2]),"r"((a)[3]), "r"(b0),"r"(b1))
__device__ __forceinline__ void spl(float x, __nv_bfloat16& h, __nv_bfloat16& l) {
    h = __float2bfloat16(x); l = __float2bfloat16(x - __bfloat162float(h));
}
__device__ __forceinline__ uint32_t pkbf(__nv_bfloat16 a, __nv_bfloat16 b) {
    return (uint32_t)*(uint16_t*)&a | ((uint32_t)*(uint16_t*)&b << 16);
}

__global__ void splitx(const float* __restrict__ X, __nv_bfloat16* __restrict__ hi,
                       __nv_bfloat16* __restrict__ lo)
{
    const int i = blockIdx.x * 256 + threadIdx.x;
    float4 v = *(const float4*)(X + (size_t)i * 4);
    __nv_bfloat16 h[4], l[4];
    float vv[4] = {v.x, v.y, v.z, v.w};
#pragma unroll
    for (int j = 0; j < 4; j++) spl(vv[j], h[j], l[j]);
    *(uint2*)(hi + (size_t)i * 4) = *(uint2*)h;
    *(uint2*)(lo + (size_t)i * 4) = *(uint2*)l;
}

__global__ void wsplit(const float* __restrict__ W, __nv_bfloat16* __restrict__ Whi,
                       __nv_bfloat16* __restrict__ Wlo, int noff)
{
    __shared__ float t[32][33];
    const int n0 = blockIdx.x * 32, k0 = blockIdx.y * 32;
    const int tx = threadIdx.x & 31, ty = threadIdx.x >> 5;
#pragma unroll
    for (int i = 0; i < 32; i += 8)
        t[ty + i][tx] = W[(size_t)(k0 + ty + i) * DD + n0 + tx];
    __syncthreads();
#pragma unroll
    for (int i = 0; i < 32; i += 8) {
        __nv_bfloat16 h, l;
        spl(t[tx][ty + i], h, l);
        Whi[(size_t)(noff + n0 + ty + i) * DD + k0 + tx] = h;
        Wlo[(size_t)(noff + n0 + ty + i) * DD + k0 + tx] = l;
    }
}

#define KC 32
#define ASTRIDE 40
#define MAT_B (128*ASTRIDE*2)
#define STG_B (4*MAT_B)
#define GSM_TOTAL (2*STG_B)

__global__ __launch_bounds__(256)
void mmagemm(const __nv_bfloat16* __restrict__ Ahi, const __nv_bfloat16* __restrict__ Alo,
             const __nv_bfloat16* __restrict__ Bhi, const __nv_bfloat16* __restrict__ Blo,
             float* __restrict__ C, int cs)
{
    extern __shared__ char smem[];
    const uint32_t sb = smem_to_u32(smem);
    const int tid = threadIdx.x, l = tid & 31, wid = tid >> 5;
    const int wm = wid >> 2, wn = wid & 3;
    const int m0 = blockIdx.y * 128, n0 = blockIdx.x * 128;
    float c[4][4][4];
#pragma unroll
    for (int i = 0; i < 4; i++)
#pragma unroll
        for (int j = 0; j < 4; j++)
#pragma unroll
            for (int k = 0; k < 4; k++) c[i][j][k] = 0.f;
    const __nv_bfloat16* gsrc[4] = {Ahi + (size_t)m0 * DD, Alo + (size_t)m0 * DD,
                                    Bhi + (size_t)n0 * DD, Blo + (size_t)n0 * DD};
    const int prow = tid >> 2, pseg = tid & 3;
    {
#pragma unroll
        for (int u = 0; u < 2; u++)
#pragma unroll
            for (int mt = 0; mt < 4; mt++)
                CP_ASYNC16(sb + mt * MAT_B + (prow + u * 64) * 80 + pseg * 16,
                           gsrc[mt] + (size_t)(prow + u * 64) * DD + pseg * 8);
        CP_COMMIT();
    }
    const int arow = (l & 7) + ((l >> 3) & 1) * 8;
    const int acolh = (l >> 4) * 8;
    const int brow = (l & 7) + ((l >> 4) & 1) * 8;
    const int bcolh = ((l >> 3) & 1) * 8;
    for (int ch = 0; ch < DD / KC; ch++) {
        asm volatile("cp.async.wait_group 0;" ::: "memory");
        __syncthreads();
        if (ch + 1 < DD / KC) {
            const int koff = (ch + 1) * KC;
            const uint32_t dbase = sb + ((ch + 1) & 1) * STG_B;
#pragma unroll
            for (int u = 0; u < 2; u++)
#pragma unroll
                for (int mt = 0; mt < 4; mt++)
                    CP_ASYNC16(dbase + mt * MAT_B + (prow + u * 64) * 80 + pseg * 16,
                               gsrc[mt] + (size_t)(prow + u * 64) * DD + koff + pseg * 8);
            CP_COMMIT();
        }
        const uint32_t sA = sb + (ch & 1) * STG_B;
#pragma unroll
        for (int ks = 0; ks < 2; ks++) {
            uint32_t ah[4][4], al[4][4], bh[2][4], bl[2][4];
#pragma unroll
            for (int mi = 0; mi < 4; mi++) {
                const uint32_t off = (uint32_t)((wm * 64 + mi * 16 + arow) * ASTRIDE + ks * 16 + acolh) * 2;
                LDSM_X4(ah[mi], sA + off);
                LDSM_X4(al[mi], sA + MAT_B + off);
            }
#pragma unroll
            for (int np = 0; np < 2; np++) {
                const uint32_t off = (uint32_t)((wn * 32 + np * 16 + brow) * ASTRIDE + ks * 16 + bcolh) * 2;
                LDSM_X4(bh[np], sA + 2 * MAT_B + off);
                LDSM_X4(bl[np], sA + 3 * MAT_B + off);
            }
#pragma unroll
            for (int mi = 0; mi < 4; mi++)
#pragma unroll
                for (int nj = 0; nj < 4; nj++) {
                    const uint32_t* bhp = &bh[nj >> 1][(nj & 1) * 2];
                    const uint32_t* blp = &bl[nj >> 1][(nj & 1) * 2];
                    MMA_B16(c[mi][nj], ah[mi], bhp[0], bhp[1]);
                    MMA_B16(c[mi][nj], ah[mi], blp[0], blp[1]);
                    MMA_B16(c[mi][nj], al[mi], bhp[0], bhp[1]);
                }
        }
    }
#pragma unroll
    for (int mi = 0; mi < 4; mi++)
#pragma unroll
        for (int nj = 0; nj < 4; nj++) {
            const int r0 = m0 + wm * 64 + mi * 16 + (l >> 2);
            const int cb = n0 + wn * 32 + nj * 8 + (l & 3) * 2;
            *(float2*)(C + (size_t)r0 * cs + cb)       = make_float2(c[mi][nj][0], c[mi][nj][1]);
            *(float2*)(C + (size_t)(r0 + 8) * cs + cb) = make_float2(c[mi][nj][2], c[mi][nj][3]);
        }
}

__global__ void sgemm_n4(const float* __restrict__ X, const float* __restrict__ W,
                         float* __restrict__ O)
{
    const int warp = threadIdx.x >> 5, lane = threadIdx.x & 31;
    const int row = blockIdx.x * 8 + warp;
    const float* x = X + (size_t)row * DD;
    float a0 = 0.f, a1 = 0.f, a2 = 0.f, a3 = 0.f;
    for (int k = lane; k < DD; k += 32) {
        float xv = x[k];
        float4 w = *(const float4*)(W + k * 4);
        a0 += xv * w.x; a1 += xv * w.y; a2 += xv * w.z; a3 += xv * w.w;
    }
#pragma unroll
    for (int o = 16; o; o >>= 1) {
        a0 += __shfl_xor_sync(~0u, a0, o); a1 += __shfl_xor_sync(~0u, a1, o);
        a2 += __shfl_xor_sync(~0u, a2, o); a3 += __shfl_xor_sync(~0u, a3, o);
    }
    if (lane == 0) *(float4*)(O + row * 4) = make_float4(a0, a1, a2, a3);
}

__global__ void lam_kernel(const float* __restrict__ XSG, float* __restrict__ LAM)
{
    const int b = blockIdx.x >> 2, h = blockIdx.x & 3;
    const int tid = threadIdx.x;
    __shared__ float ssum[256];
    float loc[8], run = 0.f;
    const int t0 = tid * 8;
#pragma unroll
    for (int u = 0; u < 8; u++) {
        float x = XSG[(size_t)(b * TT + t0 + u) * HH + h];
        float lg = (x >= 0.f) ? -log1pf(expf(-x)) : (x - log1pf(expf(x)));
        run += lg * (1.f / 16.f);
        loc[u] = run;
    }
    ssum[tid] = run;
    __syncthreads();
    for (int off = 1; off < 256; off <<= 1) {
        float v = (tid >= off) ? ssum[tid - off] : 0.f;
        __syncthreads();
        ssum[tid] += v;
        __syncthreads();
    }
    float excl = ssum[tid] - run;
#pragma unroll
    for (int u = 0; u < 8; u++)
        LAM[(size_t)(b * HH + h) * TT + t0 + u] = expf(excl + loc[u]);
}

__global__ void rope_split(const float* __restrict__ P, const float* __restrict__ LAM,
                           __nv_bfloat16* QH, __nv_bfloat16* QL,
                           __nv_bfloat16* KH, __nv_bfloat16* KL)
{
    const int idx = blockIdx.x * 256 + threadIdx.x;
    const int i = idx & 127, h = (idx >> 7) & 3, t = (idx >> 9) & 2047, b = idx >> 20;
    float inv = powf(10000.f, -(float)i * (1.f / 128.f));
    float sn, cs; sincosf((float)t * inv, &sn, &cs);
    const size_t src = (size_t)(b * TT + t) * PD + h * 256;
    const size_t dst = ((size_t)(b * HH + h) * TT + t) * 256;
    float lam = LAM[(size_t)(b * HH + h) * TT + t];
    float q1 = P[src + i], q2 = P[src + i + 128];
    float k1 = P[src + 1024 + i], k2 = P[src + 1024 + i + 128];
    float o0 = (q1 * cs - q2 * sn) * 0.0625f, o1 = (q2 * cs + q1 * sn) * 0.0625f;
    float o2 = (k1 * cs - k2 * sn) * lam,     o3 = (k2 * cs + k1 * sn) * lam;
    __nv_bfloat16 hh, ll;
    spl(o0, hh, ll); QH[dst + i] = hh;       QL[dst + i] = ll;
    spl(o1, hh, ll); QH[dst + i + 128] = hh; QL[dst + i + 128] = ll;
    spl(o2, hh, ll); KH[dst + i] = hh;       KL[dst + i] = ll;
    spl(o3, hh, ll); KH[dst + i + 128] = hh; KL[dst + i + 128] = ll;
}

__global__ void scan_split(const float* __restrict__ P, float* __restrict__ ACC,
                           __nv_bfloat16* EH, __nv_bfloat16* EL,
                           __nv_bfloat16* ETH, __nv_bfloat16* ETL)
{
    const int bh = blockIdx.x, b = bh >> 2, h = bh & 3;
    const int ml = threadIdx.x & 31, tc = threadIdx.x >> 5;
    const int m = blockIdx.y * 32 + ml;
    __shared__ float sums[8][33];
    const size_t src = (size_t)(b * TT) * PD + 4096 + h * 256 + m;
    const size_t dR = (size_t)bh * TT * 256 + m;
    const size_t dT = (size_t)bh * TT * 256 + (size_t)m * TT;
    float a = 0.f;
    for (int t = tc * 256; t < tc * 256 + 256; t++)
        a += expf(fminf(fmaxf(P[src + (size_t)t * PD], -32.f), 32.f));
    sums[tc][ml] = a;
    __syncthreads();
    a = 0.f;
    for (int p = 0; p < tc; p++) a += sums[p][ml];
    for (int t = tc * 256; t < tc * 256 + 256; t++) {
        float e = expf(fminf(fmaxf(P[src + (size_t)t * PD], -32.f), 32.f));
        a += e;
        ACC[dR + (size_t)t * 256] = a;
        __nv_bfloat16 hh, ll;
        spl(e, hh, ll);
        EH[dR + (size_t)t * 256] = hh; EL[dR + (size_t)t * 256] = ll;
        ETH[dT + t] = hh; ETL[dT + t] = ll;
    }
}

__global__ void vtsplit(const float* __restrict__ P, __nv_bfloat16* VTH, __nv_bfloat16* VTL)
{
    __shared__ float tile[32][33];
    const int bh = blockIdx.z, b = bh >> 2, h = bh & 3;
    const int t0 = blockIdx.x * 32, v0 = blockIdx.y * 32;
    const int tx = threadIdx.x & 31, ty = threadIdx.x >> 5;
#pragma unroll
    for (int i = 0; i < 32; i += 8)
        tile[ty + i][tx] = P[(size_t)(b * TT + t0 + ty + i) * PD + 2048 + h * 256 + v0 + tx];
    __syncthreads();
#pragma unroll
    for (int i = 0; i < 32; i += 8) {
        __nv_bfloat16 hh, ll;
        spl(tile[tx][ty + i], hh, ll);
        const size_t d = (size_t)bh * TT * 256 + (size_t)(v0 + ty + i) * TT + t0 + tx;
        VTH[d] = hh; VTL[d] = ll;
    }
}

// ---- fused attention, tile-paired ----
#define QSH 0
#define QSL 33792
#define YSH 67584
#define YSL 101376
#define ZSH 135168
#define ZSL 172032
#define SSH 208896
#define SSL 218112
#define ASMEM 227328
#define XSTR 264
#define ZSTR 72

__device__ __forceinline__ void ld_xy(uint32_t dH, uint32_t dL,
    const __nv_bfloat16* sH, const __nv_bfloat16* sL, int tid)
{
    const int pr = tid >> 2, ps = tid & 3;
    const __nv_bfloat16* h = sH + (size_t)pr * 256;
    const __nv_bfloat16* l = sL + (size_t)pr * 256;
#pragma unroll
    for (int s = ps; s < 32; s += 4) {
        CP_ASYNC16(dH + pr * XSTR * 2 + s * 16, h + s * 8);
        CP_ASYNC16(dL + pr * XSTR * 2 + s * 16, l + s * 8);
    }
}
__device__ __forceinline__ void ld_z(uint32_t sb,
    const __nv_bfloat16* zH, const __nv_bfloat16* zL, int tid)
{
    const __nv_bfloat16* h = zH + (size_t)tid * TT;
    const __nv_bfloat16* l = zL + (size_t)tid * TT;
#pragma unroll
    for (int s = 0; s < 8; s++) {
        CP_ASYNC16(sb + ZSH + tid * ZSTR * 2 + s * 16, h + s * 8);
        CP_ASYNC16(sb + ZSL + tid * ZSTR * 2 + s * 16, l + s * 8);
    }
}

__device__ __forceinline__ void stage_loop(char* sm, uint32_t sb, int qi, int tid,
    const __nv_bfloat16* YHb, const __nv_bfloat16* YLb,
    const __nv_bfloat16* ZHb, const __nv_bfloat16* ZLb, float ok[2][8][4])
{
    const int l = tid & 31, wid = tid >> 5, wm = wid >> 2, wn = wid & 3;
    const int arow = (l & 7) + ((l >> 3) & 1) * 8, acolh = (l >> 4) * 8;
    const int brow = (l & 7) + ((l >> 4) & 1) * 8, bcolh = ((l >> 3) & 1) * 8;
    ld_xy(sb + YSH, sb + YSL, YHb, YLb, tid); CP_COMMIT();
    ld_z(sb, ZHb, ZLb, tid); CP_COMMIT();
    for (int kc = 0; kc <= qi; kc++) {
        asm volatile("cp.async.wait_group 1;" ::: "memory");
        __syncthreads();
        float s4[2][2][4];
#pragma unroll
        for (int i = 0; i < 2; i++)
#pragma unroll
            for (int j = 0; j < 2; j++)
#pragma unroll
                for (int k = 0; k < 4; k++) s4[i][j][k] = 0.f;
#pragma unroll 4
        for (int ks = 0; ks < 16; ks++) {
            uint32_t ah[2][4], al[2][4], bhf[4], blf[4];
#pragma unroll
            for (int mi = 0; mi < 2; mi++) {
                const uint32_t off = (uint32_t)((wm * 32 + mi * 16 + arow) * XSTR + ks * 16 + acolh) * 2;
                LDSM_X4(ah[mi], sb + QSH + off);
                LDSM_X4(al[mi], sb + QSL + off);
            }
            const uint32_t bo = (uint32_t)((wn * 16 + brow) * XSTR + ks * 16 + bcolh) * 2;
            LDSM_X4(bhf, sb + YSH + bo);
            LDSM_X4(blf, sb + YSL + bo);
#pragma unroll
            for (int mi = 0; mi < 2; mi++)
#pragma unroll
                for (int nj = 0; nj < 2; nj++) {
                    MMA_B16(s4[mi][nj], ah[mi], bhf[nj * 2], bhf[nj * 2 + 1]);
                    MMA_B16(s4[mi][nj], ah[mi], blf[nj * 2], blf[nj * 2 + 1]);
                    MMA_B16(s4[mi][nj], al[mi], bhf[nj * 2], bhf[nj * 2 + 1]);
                }
        }
        __syncthreads();
        const bool diag = (kc == qi);
#pragma unroll
        for (int mi = 0; mi < 2; mi++)
#pragma unroll
            for (int nj = 0; nj < 2; nj++)
#pragma unroll
                for (int hf = 0; hf < 2; hf++) {
                    const int r = wm * 32 + mi * 16 + (l >> 2) + hf * 8;
                    const int c = wn * 16 + nj * 8 + (l & 3) * 2;
                    float v0 = s4[mi][nj][hf * 2], v1 = s4[mi][nj][hf * 2 + 1];
                    if (diag) { if (c > r) v0 = 0.f; if (c + 1 > r) v1 = 0.f; }
                    __nv_bfloat16 h0, l0, h1, l1;
                    spl(v0, h0, l0); spl(v1, h1, l1);
                    *(uint32_t*)(sm + SSH + (r * ZSTR + c) * 2) = pkbf(h0, h1);
                    *(uint32_t*)(sm + SSL + (r * ZSTR + c) * 2) = pkbf(l0, l1);
                }
        if (kc < qi) {
            ld_xy(sb + YSH, sb + YSL, YHb + (size_t)(kc + 1) * 64 * 256,
                  YLb + (size_t)(kc + 1) * 64 * 256, tid);
            CP_COMMIT();
        }
        if (kc == qi) asm volatile("cp.async.wait_group 0;" ::: "memory");
        else          asm volatile("cp.async.wait_group 1;" ::: "memory");
        __syncthreads();
#pragma unroll
        for (int ks = 0; ks < 4; ks++) {
            uint32_t ah[2][4], al[2][4];
#pragma unroll
            for (int mi = 0; mi < 2; mi++) {
                const uint32_t off = (uint32_t)((wm * 32 + mi * 16 + arow) * ZSTR + ks * 16 + acolh) * 2;
                LDSM_X4(ah[mi], sb + SSH + off);
                LDSM_X4(al[mi], sb + SSL + off);
            }
#pragma unroll
            for (int np = 0; np < 4; np++) {
                uint32_t bhf[4], blf[4];
                const uint32_t bo = (uint32_t)((wn * 64 + np * 16 + brow) * ZSTR + ks * 16 + bcolh) * 2;
                LDSM_X4(bhf, sb + ZSH + bo);
                LDSM_X4(blf, sb + ZSL + bo);
#pragma unroll
                for (int mi = 0; mi < 2; mi++)
#pragma unroll
                    for (int nj = 0; nj < 2; nj++) {
                        MMA_B16(ok[mi][np * 2 + nj], ah[mi], bhf[nj * 2], bhf[nj * 2 + 1]);
                        MMA_B16(ok[mi][np * 2 + nj], ah[mi], blf[nj * 2], blf[nj * 2 + 1]);
                        MMA_B16(ok[mi][np * 2 + nj], al[mi], bhf[nj * 2], bhf[nj * 2 + 1]);
                    }
            }
        }
        __syncthreads();
        if (kc < qi) { ld_z(sb, ZHb + (kc + 1) * 64, ZLb + (kc + 1) * 64, tid); CP_COMMIT(); }
    }
}

__device__ __forceinline__ void dump_ok(char* sm, float ok[2][8][4], int wm, int wn, int l)
{
    float* OKS = (float*)(sm + YSH);
#pragma unroll
    for (int mi = 0; mi < 2; mi++)
#pragma unroll
        for (int nj = 0; nj < 8; nj++)
#pragma unroll
            for (int hf = 0; hf < 2; hf++) {
                const int r = wm * 32 + mi * 16 + (l >> 2) + hf * 8;
                const int c = wn * 64 + nj * 8 + (l & 3) * 2;
                *(float2*)&OKS[r * 258 + c] = make_float2(ok[mi][nj][hf * 2], ok[mi][nj][hf * 2 + 1]);
                ok[mi][nj][hf * 2] = 0.f; ok[mi][nj][hf * 2 + 1] = 0.f;
            }
}

__global__ __launch_bounds__(256)
void attn_fused(const __nv_bfloat16* __restrict__ QH, const __nv_bfloat16* __restrict__ QL,
                const __nv_bfloat16* __restrict__ KH, const __nv_bfloat16* __restrict__ KL,
                const __nv_bfloat16* __restrict__ ETH, const __nv_bfloat16* __restrict__ ETL,
                const __nv_bfloat16* __restrict__ EH, const __nv_bfloat16* __restrict__ EL,
                const __nv_bfloat16* __restrict__ VTH, const __nv_bfloat16* __restrict__ VTL,
                const float* __restrict__ ACC, const float* __restrict__ P,
                const float* __restrict__ gnw,
                __nv_bfloat16* __restrict__ AH, __nv_bfloat16* __restrict__ AL)
{
    extern __shared__ char sm[];
    const uint32_t sb = smem_to_u32(sm);
    const int tid = threadIdx.x, l = tid & 31, wid = tid >> 5, wm = wid >> 2, wn = wid & 3;
    const int nT = gridDim.x * 2;
    const int bh = blockIdx.y, b = bh >> 2, h = bh & 3;
    const size_t base = (size_t)bh * TT * 256;

    float ok[2][8][4];
#pragma unroll
    for (int i = 0; i < 2; i++)
#pragma unroll
        for (int j = 0; j < 8; j++)
#pragma unroll
            for (int k = 0; k < 4; k++) ok[i][j][k] = 0.f;

    for (int half = 0; half < 2; half++) {
        const int qi = half ? (int)blockIdx.x : (nT - 1 - (int)blockIdx.x);
        const int qBase = qi * 64;

        // pass 0: X=Q, Y=K, Z=E^T
        ld_xy(sb + QSH, sb + QSL, QH + base + (size_t)qBase * 256,
              QL + base + (size_t)qBase * 256, tid);
        stage_loop(sm, sb, qi, tid, KH + base, KL + base, ETH + base, ETL + base, ok);

        dump_ok(sm, ok, wm, wn, l);
        __syncthreads();
        float* OKS = (float*)(sm + YSH);
#pragma unroll
        for (int i = 0; i < 8; i++) {
            const int r = wid * 8 + i, t = qBase + r;
            float v[8], acr[8], mx = -3.4e38f;
#pragma unroll
            for (int j = 0; j < 8; j++) {
                const int c = j * 32 + l;
                acr[j] = ACC[base + (size_t)t * 256 + c];
                v[j] = OKS[r * 258 + c] / acr[j];
                mx = fmaxf(mx, v[j]);
            }
#pragma unroll
            for (int o = 16; o; o >>= 1) mx = fmaxf(mx, __shfl_xor_sync(~0u, mx, o));
            float e[8], s = 0.f;
#pragma unroll
            for (int j = 0; j < 8; j++) { e[j] = expf(v[j] - mx); s += e[j]; }
#pragma unroll
            for (int o = 16; o; o >>= 1) s += __shfl_xor_sync(~0u, s, o);
            const float inv = 1.f / s;
#pragma unroll
            for (int j = 0; j < 8; j++) {
                const int c = j * 32 + l;
                __nv_bfloat16 hh, ll;
                spl(e[j] * inv / acr[j], hh, ll);
                *(__nv_bfloat16*)(sm + QSH + (r * XSTR + c) * 2) = hh;
                *(__nv_bfloat16*)(sm + QSL + (r * XSTR + c) * 2) = ll;
            }
        }
        __syncthreads();

        // pass 1: X=U (in QS smem), Y=E, Z=V^T
        stage_loop(sm, sb, qi, tid, EH + base, EL + base, VTH + base, VTL + base, ok);

        dump_ok(sm, ok, wm, wn, l);
        __syncthreads();
#pragma unroll
        for (int i = 0; i < 8; i++) {
            const int r = wid * 8 + i, t = qBase + r;
            float vv[8], ss = 0.f;
#pragma unroll
            for (int j = 0; j < 8; j++) { vv[j] = OKS[r * 258 + j * 32 + l]; ss += vv[j] * vv[j]; }
#pragma unroll
            for (int o = 16; o; o >>= 1) ss += __shfl_xor_sync(~0u, ss, o);
            const float rn = rsqrtf(ss * (1.f / 256.f) + 1e-5f);
#pragma unroll
            for (int j = 0; j < 8; j++) {
                const int c = j * 32 + l;
                float gg = P[(size_t)(b * TT + t) * PD + 3072 + h * 256 + c];
                float sig = 1.f / (1.f + expf(-gg));
                float act = vv[j] * rn * gnw[c] * gg * sig;
                __nv_bfloat16 hh, ll;
                spl(act, hh, ll);
                AH[(size_t)(b * TT + t) * DD + h * 256 + c] = hh;
                AL[(size_t)(b * TT + t) * DD + h * 256 + c] = ll;
            }
        }
        __syncthreads();
    }
}

extern "C" void kernel_launch(void* const* d_in, const int* in_sizes, int n_in,
                              void* d_out, int out_size)
{
    const float* x   = (const float*)d_in[0];
    const float* qw  = (const float*)d_in[1];
    const float* kw  = (const float*)d_in[2];
    const float* vw  = (const float*)d_in[3];
    const float* gw  = (const float*)d_in[4];
    const float* sw  = (const float*)d_in[5];
    const float* sgw = (const float*)d_in[6];
    const float* gnw = (const float*)d_in[7];
    const float* ow  = (const float*)d_in[8];
    float* out = (float*)d_out;

    float *P, *ACC, *XSG, *LAM;
    __nv_bfloat16 *XHI, *XLO, *WHI, *WLO, *QHI, *QLO, *KHI, *KLO;
    __nv_bfloat16 *EHI, *ELO, *ETHI, *ETLO, *VTHI, *VTLO;
    cudaGetSymbolAddress((void**)&P, g_P);     cudaGetSymbolAddress((void**)&ACC, g_ACC);
    cudaGetSymbolAddress((void**)&XSG, g_XSG); cudaGetSymbolAddress((void**)&LAM, g_LAM);
    cudaGetSymbolAddress((void**)&XHI, g_XHI); cudaGetSymbolAddress((void**)&XLO, g_XLO);
    cudaGetSymbolAddress((void**)&WHI, g_WHI); cudaGetSymbolAddress((void**)&WLO, g_WLO);
    cudaGetSymbolAddress((void**)&QHI, g_QHI); cudaGetSymbolAddress((void**)&QLO, g_QLO);
    cudaGetSymbolAddress((void**)&KHI, g_KHI); cudaGetSymbolAddress((void**)&KLO, g_KLO);
    cudaGetSymbolAddress((void**)&EHI, g_EHI); cudaGetSymbolAddress((void**)&ELO, g_ELO);
    cudaGetSymbolAddress((void**)&ETHI, g_ETHI); cudaGetSymbolAddress((void**)&ETLO, g_ETLO);
    cudaGetSymbolAddress((void**)&VTHI, g_VTHI); cudaGetSymbolAddress((void**)&VTLO, g_VTLO);

    static int done = 0;
    if (!done) {
        cudaFuncSetAttribute(mmagemm, cudaFuncAttributeMaxDynamicSharedMemorySize, GSM_TOTAL);
        cudaFuncSetAttribute(attn_fused, cudaFuncAttributeMaxDynamicSharedMemorySize, ASMEM);
        done = 1;
    }

    const dim3 wgrid(32, 32);
    const int sxg = (BT * DD / 4) / 256;

    splitx<<<sxg, 256>>>(x, XHI, XLO);
    sgemm_n4<<<BT / 8, 256>>>(x, sgw, XSG);
    wsplit<<<wgrid, 256>>>(qw, WHI, WLO, 0);
    wsplit<<<wgrid, 256>>>(kw, WHI, WLO, 1024);
    wsplit<<<wgrid, 256>>>(vw, WHI, WLO, 2048);
    wsplit<<<wgrid, 256>>>(gw, WHI, WLO, 3072);
    wsplit<<<wgrid, 256>>>(sw, WHI, WLO, 4096);
    mmagemm<<<dim3(PD / 128, BT / 128), 256, GSM_TOTAL>>>(XHI, XLO, WHI, WLO, P, PD);

    lam_kernel<<<BH, 256>>>(XSG, LAM);
    rope_split<<<(BB * TT * HH * 128) / 256, 256>>>(P, LAM, QHI, QLO, KHI, KLO);
    scan_split<<<dim3(BH, 8), 256>>>(P, ACC, EHI, ELO, ETHI, ETLO);
    vtsplit<<<dim3(TT / 32, 8, BH), 256>>>(P, VTHI, VTLO);

    attn_fused<<<dim3(TT / 128, BH), 256, ASMEM>>>(QHI, QLO, KHI, KLO, ETHI, ETLO,
                                                   EHI, ELO, VTHI, VTLO, ACC, P, gnw,
                                                   XHI, XLO);

    wsplit<<<wgrid, 256>>>(ow, WHI, WLO, 0);
    mmagemm<<<dim3(DD / 128, BT / 128), 256, GSM_TOTAL>>>(XHI, XLO, WHI, WLO, out, DD);
}

// round 9
// speedup vs baseline: 2.7388x; 1.0763x over previous
#include <cuda_runtime.h>
#include <cuda_bf16.h>
#include <math.h>
#include <stdint.h>

#define BB 4
#define TT 2048
#define HH 4
#define DD 1024
#define PD 5120
#define BT (BB*TT)
#define BH 16

__device__ float g_P[(size_t)BT*PD], g_ACC[BT*DD], g_XSG[BT*HH], g_LAM[BH*TT];
__device__ __nv_bfloat16 g_XHI[BT*DD], g_XLO[BT*DD], g_WHI[(size_t)PD*DD], g_WLO[(size_t)PD*DD];
__device__ __nv_bfloat16 g_QHI[BT*DD], g_QLO[BT*DD], g_KHI[BT*DD], g_KLO[BT*DD];
__device__ __nv_bfloat16 g_EHI[BT*DD], g_ELO[BT*DD], g_ETHI[BT*DD], g_ETLO[BT*DD];
__device__ __nv_bfloat16 g_VTHI[BT*DD], g_VTLO[BT*DD];

__device__ __forceinline__ uint32_t smem_to_u32(const void* p) {
    uint32_t a;
    asm("{ .reg .u64 t; cvta.to.shared.u64 t, %1; cvt.u32.u64 %0, t; }" : "=r"(a) : "l"(p));
    return a;
}
#define CP_ASYNC16(d, s) asm volatile("cp.async.cg.shared.global [%0], [%1], 16;" :: "r"(d), "l"(s))
#define CP_COMMIT() asm volatile("cp.async.commit_group;" ::: "memory")
#define LDSM_X4(r, a) \
    asm volatile("ldmatrix.sync.aligned.m8n8.x4.shared.b16 {%0,%1,%2,%3}, [%4];" \
        : "=r"((r)[0]),"=r"((r)[1]),"=r"((r)[2]),"=r"((r)[3]) : "r"(a))
#define MMA_B16(c, a, b0, b1) \
    asm volatile("mma.sync.aligned.m16n8k16.row.col.f32.bf16.bf16.f32 " \
        "{%0,%1,%2,%3},{%4,%5,%6,%7},{%8,%9},{%0,%1,%2,%3};" \
        : "+f"((c)[0]),"+f"((c)[1]),"+f"((c)[2]),"+f"((c)[3]) \
        : "r"((a)[0]),"r"((a)[1]),"r"((a)[2]),"r"((a)[3]), "r"(b0),"r"(b1))
__device__ __forceinline__ void spl(float x, __nv_bfloat16& h, __nv_bfloat16& l) {
    h = __float2bfloat16(x); l = __float2bfloat16(x - __bfloat162float(h));
}
__device__ __forceinline__ uint32_t pkbf(__nv_bfloat16 a, __nv_bfloat16 b) {
    return (uint32_t)*(uint16_t*)&a | ((uint32_t)*(uint16_t*)&b << 16);
}

__global__ void splitx(const float* __restrict__ X, __nv_bfloat16* __restrict__ hi,
                       __nv_bfloat16* __restrict__ lo)
{
    const int i = blockIdx.x * 256 + threadIdx.x;
    float4 v = *(const float4*)(X + (size_t)i * 4);
    __nv_bfloat16 h[4], l[4];
    float vv[4] = {v.x, v.y, v.z, v.w};
#pragma unroll
    for (int j = 0; j < 4; j++) spl(vv[j], h[j], l[j]);
    *(uint2*)(hi + (size_t)i * 4) = *(uint2*)h;
    *(uint2*)(lo + (size_t)i * 4) = *(uint2*)l;
}

__global__ void wsplit(const float* __restrict__ W, __nv_bfloat16* __restrict__ Whi,
                       __nv_bfloat16* __restrict__ Wlo, int noff)
{
    __shared__ float t[32][33];
    const int n0 = blockIdx.x * 32, k0 = blockIdx.y * 32;
    const int tx = threadIdx.x & 31, ty = threadIdx.x >> 5;
#pragma unroll
    for (int i = 0; i < 32; i += 8)
        t[ty + i][tx] = W[(size_t)(k0 + ty + i) * DD + n0 + tx];
    __syncthreads();
#pragma unroll
    for (int i = 0; i < 32; i += 8) {
        __nv_bfloat16 h, l;
        spl(t[tx][ty + i], h, l);
        Whi[(size_t)(noff + n0 + ty + i) * DD + k0 + tx] = h;
        Wlo[(size_t)(noff + n0 + ty + i) * DD + k0 + tx] = l;
    }
}

#define KC 32
#define ASTRIDE 40
#define MAT_B (128*ASTRIDE*2)
#define STG_B (4*MAT_B)
#define GSM_TOTAL (2*STG_B)

__global__ __launch_bounds__(256)
void mmagemm(const __nv_bfloat16* __restrict__ Ahi, const __nv_bfloat16* __restrict__ Alo,
             const __nv_bfloat16* __restrict__ Bhi, const __nv_bfloat16* __restrict__ Blo,
             float* __restrict__ C, int cs)
{
    extern __shared__ char smem[];
    const uint32_t sb = smem_to_u32(smem);
    const int tid = threadIdx.x, l = tid & 31, wid = tid >> 5;
    const int wm = wid >> 2, wn = wid & 3;
    const int m0 = blockIdx.y * 128, n0 = blockIdx.x * 128;
    float c[4][4][4];
#pragma unroll
    for (int i = 0; i < 4; i++)
#pragma unroll
        for (int j = 0; j < 4; j++)
#pragma unroll
            for (int k = 0; k < 4; k++) c[i][j][k] = 0.f;
    const __nv_bfloat16* gsrc[4] = {Ahi + (size_t)m0 * DD, Alo + (size_t)m0 * DD,
                                    Bhi + (size_t)n0 * DD, Blo + (size_t)n0 * DD};
    const int prow = tid >> 2, pseg = tid & 3;
    {
#pragma unroll
        for (int u = 0; u < 2; u++)
#pragma unroll
            for (int mt = 0; mt < 4; mt++)
                CP_ASYNC16(sb + mt * MAT_B + (prow + u * 64) * 80 + pseg * 16,
                           gsrc[mt] + (size_t)(prow + u * 64) * DD + pseg * 8);
        CP_COMMIT();
    }
    const int arow = (l & 7) + ((l >> 3) & 1) * 8;
    const int acolh = (l >> 4) * 8;
    const int brow = (l & 7) + ((l >> 4) & 1) * 8;
    const int bcolh = ((l >> 3) & 1) * 8;
    for (int ch = 0; ch < DD / KC; ch++) {
        asm volatile("cp.async.wait_group 0;" ::: "memory");
        __syncthreads();
        if (ch + 1 < DD / KC) {
            const int koff = (ch + 1) * KC;
            const uint32_t dbase = sb + ((ch + 1) & 1) * STG_B;
#pragma unroll
            for (int u = 0; u < 2; u++)
#pragma unroll
                for (int mt = 0; mt < 4; mt++)
                    CP_ASYNC16(dbase + mt * MAT_B + (prow + u * 64) * 80 + pseg * 16,
                               gsrc[mt] + (size_t)(prow + u * 64) * DD + koff + pseg * 8);
            CP_COMMIT();
        }
        const uint32_t sA = sb + (ch & 1) * STG_B;
#pragma unroll
        for (int ks = 0; ks < 2; ks++) {
            uint32_t ah[4][4], al[4][4], bh[2][4], bl[2][4];
#pragma unroll
            for (int mi = 0; mi < 4; mi++) {
                const uint32_t off = (uint32_t)((wm * 64 + mi * 16 + arow) * ASTRIDE + ks * 16 + acolh) * 2;
                LDSM_X4(ah[mi], sA + off);
                LDSM_X4(al[mi], sA + MAT_B + off);
            }
#pragma unroll
            for (int np = 0; np < 2; np++) {
                const uint32_t off = (uint32_t)((wn * 32 + np * 16 + brow) * ASTRIDE + ks * 16 + bcolh) * 2;
                LDSM_X4(bh[np], sA + 2 * MAT_B + off);
                LDSM_X4(bl[np], sA + 3 * MAT_B + off);
            }
#pragma unroll
            for (int mi = 0; mi < 4; mi++)
#pragma unroll
                for (int nj = 0; nj < 4; nj++) {
                    const uint32_t* bhp = &bh[nj >> 1][(nj & 1) * 2];
                    const uint32_t* blp = &bl[nj >> 1][(nj & 1) * 2];
                    MMA_B16(c[mi][nj], ah[mi], bhp[0], bhp[1]);
                    MMA_B16(c[mi][nj], ah[mi], blp[0], blp[1]);
                    MMA_B16(c[mi][nj], al[mi], bhp[0], bhp[1]);
                }
        }
    }
#pragma unroll
    for (int mi = 0; mi < 4; mi++)
#pragma unroll
        for (int nj = 0; nj < 4; nj++) {
            const int r0 = m0 + wm * 64 + mi * 16 + (l >> 2);
            const int cb = n0 + wn * 32 + nj * 8 + (l & 3) * 2;
            *(float2*)(C + (size_t)r0 * cs + cb)       = make_float2(c[mi][nj][0], c[mi][nj][1]);
            *(float2*)(C + (size_t)(r0 + 8) * cs + cb) = make_float2(c[mi][nj][2], c[mi][nj][3]);
        }
}

__global__ void sgemm_n4(const float* __restrict__ X, const float* __restrict__ W,
                         float* __restrict__ O)
{
    const int warp = threadIdx.x >> 5, lane = threadIdx.x & 31;
    const int row = blockIdx.x * 8 + warp;
    const float* x = X + (size_t)row * DD;
    float a0 = 0.f, a1 = 0.f, a2 = 0.f, a3 = 0.f;
    for (int k = lane; k < DD; k += 32) {
        float xv = x[k];
        float4 w = *(const float4*)(W + k * 4);
        a0 += xv * w.x; a1 += xv * w.y; a2 += xv * w.z; a3 += xv * w.w;
    }
#pragma unroll
    for (int o = 16; o; o >>= 1) {
        a0 += __shfl_xor_sync(~0u, a0, o); a1 += __shfl_xor_sync(~0u, a1, o);
        a2 += __shfl_xor_sync(~0u, a2, o); a3 += __shfl_xor_sync(~0u, a3, o);
    }
    if (lane == 0) *(float4*)(O + row * 4) = make_float4(a0, a1, a2, a3);
}

__global__ void lam_kernel(const float* __restrict__ XSG, float* __restrict__ LAM)
{
    const int b = blockIdx.x >> 2, h = blockIdx.x & 3;
    const int tid = threadIdx.x;
    __shared__ float ssum[256];
    float loc[8], run = 0.f;
    const int t0 = tid * 8;
#pragma unroll
    for (int u = 0; u < 8; u++) {
        float x = XSG[(size_t)(b * TT + t0 + u) * HH + h];
        float lg = (x >= 0.f) ? -log1pf(expf(-x)) : (x - log1pf(expf(x)));
        run += lg * (1.f / 16.f);
        loc[u] = run;
    }
    ssum[tid] = run;
    __syncthreads();
    for (int off = 1; off < 256; off <<= 1) {
        float v = (tid >= off) ? ssum[tid - off] : 0.f;
        __syncthreads();
        ssum[tid] += v;
        __syncthreads();
    }
    float excl = ssum[tid] - run;
#pragma unroll
    for (int u = 0; u < 8; u++)
        LAM[(size_t)(b * HH + h) * TT + t0 + u] = expf(excl + loc[u]);
}

__global__ void rope_split(const float* __restrict__ P, const float* __restrict__ LAM,
                           __nv_bfloat16* QH, __nv_bfloat16* QL,
                           __nv_bfloat16* KH, __nv_bfloat16* KL)
{
    const int idx = blockIdx.x * 256 + threadIdx.x;
    const int i = idx & 127, h = (idx >> 7) & 3, t = (idx >> 9) & 2047, b = idx >> 20;
    float inv = powf(10000.f, -(float)i * (1.f / 128.f));
    float sn, cs; sincosf((float)t * inv, &sn, &cs);
    const size_t src = (size_t)(b * TT + t) * PD + h * 256;
    const size_t dst = ((size_t)(b * HH + h) * TT + t) * 256;
    float lam = LAM[(size_t)(b * HH + h) * TT + t];
    float q1 = P[src + i], q2 = P[src + i + 128];
    float k1 = P[src + 1024 + i], k2 = P[src + 1024 + i + 128];
    float o0 = (q1 * cs - q2 * sn) * 0.0625f, o1 = (q2 * cs + q1 * sn) * 0.0625f;
    float o2 = (k1 * cs - k2 * sn) * lam,     o3 = (k2 * cs + k1 * sn) * lam;
    __nv_bfloat16 hh, ll;
    spl(o0, hh, ll); QH[dst + i] = hh;       QL[dst + i] = ll;
    spl(o1, hh, ll); QH[dst + i + 128] = hh; QL[dst + i + 128] = ll;
    spl(o2, hh, ll); KH[dst + i] = hh;       KL[dst + i] = ll;
    spl(o3, hh, ll); KH[dst + i + 128] = hh; KL[dst + i + 128] = ll;
}

__global__ void scan_split(const float* __restrict__ P, float* __restrict__ ACC,
                           __nv_bfloat16* EH, __nv_bfloat16* EL,
                           __nv_bfloat16* ETH, __nv_bfloat16* ETL)
{
    const int bh = blockIdx.x, b = bh >> 2, h = bh & 3;
    const int ml = threadIdx.x & 31, tc = threadIdx.x >> 5;
    const int m = blockIdx.y * 32 + ml;
    __shared__ float sums[8][33];
    const size_t src = (size_t)(b * TT) * PD + 4096 + h * 256 + m;
    const size_t dR = (size_t)bh * TT * 256 + m;
    const size_t dT = (size_t)bh * TT * 256 + (size_t)m * TT;
    float a = 0.f;
    for (int t = tc * 256; t < tc * 256 + 256; t++)
        a += expf(fminf(fmaxf(P[src + (size_t)t * PD], -32.f), 32.f));
    sums[tc][ml] = a;
    __syncthreads();
    a = 0.f;
    for (int p = 0; p < tc; p++) a += sums[p][ml];
    for (int t = tc * 256; t < tc * 256 + 256; t++) {
        float e = expf(fminf(fmaxf(P[src + (size_t)t * PD], -32.f), 32.f));
        a += e;
        ACC[dR + (size_t)t * 256] = a;
        __nv_bfloat16 hh, ll;
        spl(e, hh, ll);
        EH[dR + (size_t)t * 256] = hh; EL[dR + (size_t)t * 256] = ll;
        ETH[dT + t] = hh; ETL[dT + t] = ll;
    }
}

__global__ void vtsplit(const float* __restrict__ P, __nv_bfloat16* VTH, __nv_bfloat16* VTL)
{
    __shared__ float tile[32][33];
    const int bh = blockIdx.z, b = bh >> 2, h = bh & 3;
    const int t0 = blockIdx.x * 32, v0 = blockIdx.y * 32;
    const int tx = threadIdx.x & 31, ty = threadIdx.x >> 5;
#pragma unroll
    for (int i = 0; i < 32; i += 8)
        tile[ty + i][tx] = P[(size_t)(b * TT + t0 + ty + i) * PD + 2048 + h * 256 + v0 + tx];
    __syncthreads();
#pragma unroll
    for (int i = 0; i < 32; i += 8) {
        __nv_bfloat16 hh, ll;
        spl(tile[tx][ty + i], hh, ll);
        const size_t d = (size_t)bh * TT * 256 + (size_t)(v0 + ty + i) * TT + t0 + tx;
        VTH[d] = hh; VTL[d] = ll;
    }
}

// ---- fused attention, tile-paired, 512 threads (16 warps, 4x4 warp grid) ----
#define QSH 0
#define QSL 33792
#define YSH 67584
#define YSL 101376
#define ZSH 135168
#define ZSL 172032
#define SSH 208896
#define SSL 218112
#define ASMEM 227328
#define XSTR 264
#define ZSTR 72
#define ATHR 512

__device__ __forceinline__ void ld_xy(uint32_t dH, uint32_t dL,
    const __nv_bfloat16* sH, const __nv_bfloat16* sL, int tid)
{
    const int pr = tid >> 3, ps = tid & 7;     // 64 rows x 8 threads
    const __nv_bfloat16* h = sH + (size_t)pr * 256;
    const __nv_bfloat16* l = sL + (size_t)pr * 256;
#pragma unroll
    for (int s = ps; s < 32; s += 8) {
        CP_ASYNC16(dH + pr * XSTR * 2 + s * 16, h + s * 8);
        CP_ASYNC16(dL + pr * XSTR * 2 + s * 16, l + s * 8);
    }
}
__device__ __forceinline__ void ld_z(uint32_t sb,
    const __nv_bfloat16* zH, const __nv_bfloat16* zL, int tid)
{
    const int row = tid >> 1, hf = tid & 1;    // 256 rows x 2 threads
    const __nv_bfloat16* h = zH + (size_t)row * TT;
    const __nv_bfloat16* l = zL + (size_t)row * TT;
#pragma unroll
    for (int s = hf * 4; s < hf * 4 + 4; s++) {
        CP_ASYNC16(sb + ZSH + row * ZSTR * 2 + s * 16, h + s * 8);
        CP_ASYNC16(sb + ZSL + row * ZSTR * 2 + s * 16, l + s * 8);
    }
}

__device__ __forceinline__ void stage_loop(char* sm, uint32_t sb, int qi, int tid,
    const __nv_bfloat16* YHb, const __nv_bfloat16* YLb,
    const __nv_bfloat16* ZHb, const __nv_bfloat16* ZLb, float ok[8][4])
{
    const int l = tid & 31, wid = tid >> 5, wm = wid >> 2, wn = wid & 3;
    const int arow = (l & 7) + ((l >> 3) & 1) * 8, acolh = (l >> 4) * 8;
    const int brow = (l & 7) + ((l >> 4) & 1) * 8, bcolh = ((l >> 3) & 1) * 8;
    ld_xy(sb + YSH, sb + YSL, YHb, YLb, tid); CP_COMMIT();
    ld_z(sb, ZHb, ZLb, tid); CP_COMMIT();
    for (int kc = 0; kc <= qi; kc++) {
        asm volatile("cp.async.wait_group 1;" ::: "memory");
        __syncthreads();
        // phase A: S[64x64] = X . Y^T ; warp tile 16x16
        float s4[2][4];
#pragma unroll
        for (int j = 0; j < 2; j++)
#pragma unroll
            for (int k = 0; k < 4; k++) s4[j][k] = 0.f;
#pragma unroll 4
        for (int ks = 0; ks < 16; ks++) {
            uint32_t ah[4], al[4], bhf[4], blf[4];
            const uint32_t ao = (uint32_t)((wm * 16 + arow) * XSTR + ks * 16 + acolh) * 2;
            LDSM_X4(ah, sb + QSH + ao);
            LDSM_X4(al, sb + QSL + ao);
            const uint32_t bo = (uint32_t)((wn * 16 + brow) * XSTR + ks * 16 + bcolh) * 2;
            LDSM_X4(bhf, sb + YSH + bo);
            LDSM_X4(blf, sb + YSL + bo);
#pragma unroll
            for (int nj = 0; nj < 2; nj++) {
                MMA_B16(s4[nj], ah, bhf[nj * 2], bhf[nj * 2 + 1]);
                MMA_B16(s4[nj], ah, blf[nj * 2], blf[nj * 2 + 1]);
                MMA_B16(s4[nj], al, bhf[nj * 2], bhf[nj * 2 + 1]);
            }
        }
        __syncthreads();
        const bool diag = (kc == qi);
#pragma unroll
        for (int nj = 0; nj < 2; nj++)
#pragma unroll
            for (int hf = 0; hf < 2; hf++) {
                const int r = wm * 16 + (l >> 2) + hf * 8;
                const int c = wn * 16 + nj * 8 + (l & 3) * 2;
                float v0 = s4[nj][hf * 2], v1 = s4[nj][hf * 2 + 1];
                if (diag) { if (c > r) v0 = 0.f; if (c + 1 > r) v1 = 0.f; }
                __nv_bfloat16 h0, l0, h1, l1;
                spl(v0, h0, l0); spl(v1, h1, l1);
                *(uint32_t*)(sm + SSH + (r * ZSTR + c) * 2) = pkbf(h0, h1);
                *(uint32_t*)(sm + SSL + (r * ZSTR + c) * 2) = pkbf(l0, l1);
            }
        if (kc < qi) {
            ld_xy(sb + YSH, sb + YSL, YHb + (size_t)(kc + 1) * 64 * 256,
                  YLb + (size_t)(kc + 1) * 64 * 256, tid);
            CP_COMMIT();
        }
        if (kc == qi) asm volatile("cp.async.wait_group 0;" ::: "memory");
        else          asm volatile("cp.async.wait_group 1;" ::: "memory");
        __syncthreads();
        // phase B: ok[64x256] += S . Z^T ; warp tile 16x64
#pragma unroll
        for (int ks = 0; ks < 4; ks++) {
            uint32_t ah[4], al[4];
            const uint32_t ao = (uint32_t)((wm * 16 + arow) * ZSTR + ks * 16 + acolh) * 2;
            LDSM_X4(ah, sm ? sb + SSH + ao : 0);
            LDSM_X4(al, sb + SSL + ao);
#pragma unroll
            for (int np = 0; np < 4; np++) {
                uint32_t bhf[4], blf[4];
                const uint32_t bo = (uint32_t)((wn * 64 + np * 16 + brow) * ZSTR + ks * 16 + bcolh) * 2;
                LDSM_X4(bhf, sb + ZSH + bo);
                LDSM_X4(blf, sb + ZSL + bo);
#pragma unroll
                for (int nj = 0; nj < 2; nj++) {
                    MMA_B16(ok[np * 2 + nj], ah, bhf[nj * 2], bhf[nj * 2 + 1]);
                    MMA_B16(ok[np * 2 + nj], ah, blf[nj * 2], blf[nj * 2 + 1]);
                    MMA_B16(ok[np * 2 + nj], al, bhf[nj * 2], bhf[nj * 2 + 1]);
                }
            }
        }
        __syncthreads();
        if (kc < qi) { ld_z(sb, ZHb + (kc + 1) * 64, ZLb + (kc + 1) * 64, tid); CP_COMMIT(); }
    }
}

__device__ __forceinline__ void dump_ok(char* sm, float ok[8][4], int wm, int wn, int l)
{
    float* OKS = (float*)(sm + YSH);
#pragma unroll
    for (int idx = 0; idx < 8; idx++)
#pragma unroll
        for (int hf = 0; hf < 2; hf++) {
            const int r = wm * 16 + (l >> 2) + hf * 8;
            const int c = wn * 64 + idx * 8 + (l & 3) * 2;
            *(float2*)&OKS[r * 258 + c] = make_float2(ok[idx][hf * 2], ok[idx][hf * 2 + 1]);
            ok[idx][hf * 2] = 0.f; ok[idx][hf * 2 + 1] = 0.f;
        }
}

__global__ __launch_bounds__(ATHR)
void attn_fused(const __nv_bfloat16* __restrict__ QH, const __nv_bfloat16* __restrict__ QL,
                const __nv_bfloat16* __restrict__ KH, const __nv_bfloat16* __restrict__ KL,
                const __nv_bfloat16* __restrict__ ETH, const __nv_bfloat16* __restrict__ ETL,
                const __nv_bfloat16* __restrict__ EH, const __nv_bfloat16* __restrict__ EL,
                const __nv_bfloat16* __restrict__ VTH, const __nv_bfloat16* __restrict__ VTL,
                const float* __restrict__ ACC, const float* __restrict__ P,
                const float* __restrict__ gnw,
                __nv_bfloat16* __restrict__ AH, __nv_bfloat16* __restrict__ AL)
{
    extern __shared__ char sm[];
    const uint32_t sb = smem_to_u32(sm);
    const int tid = threadIdx.x, l = tid & 31, wid = tid >> 5, wm = wid >> 2, wn = wid & 3;
    const int nT = gridDim.x * 2;
    const int bh = blockIdx.y, b = bh >> 2, h = bh & 3;
    const size_t base = (size_t)bh * TT * 256;

    float ok[8][4];
#pragma unroll
    for (int j = 0; j < 8; j++)
#pragma unroll
        for (int k = 0; k < 4; k++) ok[j][k] = 0.f;

    for (int half = 0; half < 2; half++) {
        const int qi = half ? (int)blockIdx.x : (nT - 1 - (int)blockIdx.x);
        const int qBase = qi * 64;

        // pass 0: X=Q, Y=K, Z=E^T
        ld_xy(sb + QSH, sb + QSL, QH + base + (size_t)qBase * 256,
              QL + base + (size_t)qBase * 256, tid);
        stage_loop(sm, sb, qi, tid, KH + base, KL + base, ETH + base, ETL + base, ok);

        dump_ok(sm, ok, wm, wn, l);
        __syncthreads();
        float* OKS = (float*)(sm + YSH);
#pragma unroll
        for (int i = 0; i < 4; i++) {
            const int r = wid * 4 + i, t = qBase + r;
            float v[8], acr[8], mx = -3.4e38f;
#pragma unroll
            for (int j = 0; j < 8; j++) {
                const int c = j * 32 + l;
                acr[j] = ACC[base + (size_t)t * 256 + c];
                v[j] = OKS[r * 258 + c] / acr[j];
                mx = fmaxf(mx, v[j]);
            }
#pragma unroll
            for (int o = 16; o; o >>= 1) mx = fmaxf(mx, __shfl_xor_sync(~0u, mx, o));
            float e[8], s = 0.f;
#pragma unroll
            for (int j = 0; j < 8; j++) { e[j] = expf(v[j] - mx); s += e[j]; }
#pragma unroll
            for (int o = 16; o; o >>= 1) s += __shfl_xor_sync(~0u, s, o);
            const float inv = 1.f / s;
#pragma unroll
            for (int j = 0; j < 8; j++) {
                const int c = j * 32 + l;
                __nv_bfloat16 hh, ll;
                spl(e[j] * inv / acr[j], hh, ll);
                *(__nv_bfloat16*)(sm + QSH + (r * XSTR + c) * 2) = hh;
                *(__nv_bfloat16*)(sm + QSL + (r * XSTR + c) * 2) = ll;
            }
        }
        __syncthreads();

        // pass 1: X=U (in QS smem), Y=E, Z=V^T
        stage_loop(sm, sb, qi, tid, EH + base, EL + base, VTH + base, VTL + base, ok);

        dump_ok(sm, ok, wm, wn, l);
        __syncthreads();
#pragma unroll
        for (int i = 0; i < 4; i++) {
            const int r = wid * 4 + i, t = qBase + r;
            float vv[8], ss = 0.f;
#pragma unroll
            for (int j = 0; j < 8; j++) { vv[j] = OKS[r * 258 + j * 32 + l]; ss += vv[j] * vv[j]; }
#pragma unroll
            for (int o = 16; o; o >>= 1) ss += __shfl_xor_sync(~0u, ss, o);
            const float rn = rsqrtf(ss * (1.f / 256.f) + 1e-5f);
#pragma unroll
            for (int j = 0; j < 8; j++) {
                const int c = j * 32 + l;
                float gg = P[(size_t)(b * TT + t) * PD + 3072 + h * 256 + c];
                float sig = 1.f / (1.f + expf(-gg));
                float act = vv[j] * rn * gnw[c] * gg * sig;
                __nv_bfloat16 hh, ll;
                spl(act, hh, ll);
                AH[(size_t)(b * TT + t) * DD + h * 256 + c] = hh;
                AL[(size_t)(b * TT + t) * DD + h * 256 + c] = ll;
            }
        }
        __syncthreads();
    }
}

extern "C" void kernel_launch(void* const* d_in, const int* in_sizes, int n_in,
                              void* d_out, int out_size)
{
    const float* x   = (const float*)d_in[0];
    const float* qw  = (const float*)d_in[1];
    const float* kw  = (const float*)d_in[2];
    const float* vw  = (const float*)d_in[3];
    const float* gw  = (const float*)d_in[4];
    const float* sw  = (const float*)d_in[5];
    const float* sgw = (const float*)d_in[6];
    const float* gnw = (const float*)d_in[7];
    const float* ow  = (const float*)d_in[8];
    float* out = (float*)d_out;

    float *P, *ACC, *XSG, *LAM;
    __nv_bfloat16 *XHI, *XLO, *WHI, *WLO, *QHI, *QLO, *KHI, *KLO;
    __nv_bfloat16 *EHI, *ELO, *ETHI, *ETLO, *VTHI, *VTLO;
    cudaGetSymbolAddress((void**)&P, g_P);     cudaGetSymbolAddress((void**)&ACC, g_ACC);
    cudaGetSymbolAddress((void**)&XSG, g_XSG); cudaGetSymbolAddress((void**)&LAM, g_LAM);
    cudaGetSymbolAddress((void**)&XHI, g_XHI); cudaGetSymbolAddress((void**)&XLO, g_XLO);
    cudaGetSymbolAddress((void**)&WHI, g_WHI); cudaGetSymbolAddress((void**)&WLO, g_WLO);
    cudaGetSymbolAddress((void**)&QHI, g_QHI); cudaGetSymbolAddress((void**)&QLO, g_QLO);
    cudaGetSymbolAddress((void**)&KHI, g_KHI); cudaGetSymbolAddress((void**)&KLO, g_KLO);
    cudaGetSymbolAddress((void**)&EHI, g_EHI); cudaGetSymbolAddress((void**)&ELO, g_ELO);
    cudaGetSymbolAddress((void**)&ETHI, g_ETHI); cudaGetSymbolAddress((void**)&ETLO, g_ETLO);
    cudaGetSymbolAddress((void**)&VTHI, g_VTHI); cudaGetSymbolAddress((void**)&VTLO, g_VTLO);

    static int done = 0;
    if (!done) {
        cudaFuncSetAttribute(mmagemm, cudaFuncAttributeMaxDynamicSharedMemorySize, GSM_TOTAL);
        cudaFuncSetAttribute(attn_fused, cudaFuncAttributeMaxDynamicSharedMemorySize, ASMEM);
        done = 1;
    }

    const dim3 wgrid(32, 32);
    const int sxg = (BT * DD / 4) / 256;

    splitx<<<sxg, 256>>>(x, XHI, XLO);
    sgemm_n4<<<BT / 8, 256>>>(x, sgw, XSG);
    wsplit<<<wgrid, 256>>>(qw, WHI, WLO, 0);
    wsplit<<<wgrid, 256>>>(kw, WHI, WLO, 1024);
    wsplit<<<wgrid, 256>>>(vw, WHI, WLO, 2048);
    wsplit<<<wgrid, 256>>>(gw, WHI, WLO, 3072);
    wsplit<<<wgrid, 256>>>(sw, WHI, WLO, 4096);
    mmagemm<<<dim3(PD / 128, BT / 128), 256, GSM_TOTAL>>>(XHI, XLO, WHI, WLO, P, PD);

    lam_kernel<<<BH, 256>>>(XSG, LAM);
    rope_split<<<(BB * TT * HH * 128) / 256, 256>>>(P, LAM, QHI, QLO, KHI, KLO);
    scan_split<<<dim3(BH, 8), 256>>>(P, ACC, EHI, ELO, ETHI, ETLO);
    vtsplit<<<dim3(TT / 32, 8, BH), 256>>>(P, VTHI, VTLO);

    attn_fused<<<dim3(TT / 128, BH), ATHR, ASMEM>>>(QHI, QLO, KHI, KLO, ETHI, ETLO,
                                                    EHI, ELO, VTHI, VTLO, ACC, P, gnw,
                                                    XHI, XLO);

    wsplit<<<wgrid, 256>>>(ow, WHI, WLO, 0);
    mmagemm<<<dim3(DD / 128, BT / 128), 256, GSM_TOTAL>>>(XHI, XLO, WHI, WLO, out, DD);
}

// round 10
// speedup vs baseline: 2.8909x; 1.0556x over previous
#include <cuda_runtime.h>
#include <cuda_bf16.h>
#include <math.h>
#include <stdint.h>

#define BB 4
#define TT 2048
#define HH 4
#define DD 1024
#define PD 5120
#define BT (BB*TT)
#define BH 16

__device__ float g_P[(size_t)BT*PD], g_ACC[BT*DD], g_XSG[BT*HH], g_LAM[BH*TT];
__device__ int g_ctr;
__device__ __nv_bfloat16 g_XHI[BT*DD], g_XLO[BT*DD], g_WHI[(size_t)PD*DD], g_WLO[(size_t)PD*DD];
__device__ __nv_bfloat16 g_QHI[BT*DD], g_QLO[BT*DD], g_KHI[BT*DD], g_KLO[BT*DD];
__device__ __nv_bfloat16 g_EHI[BT*DD], g_ELO[BT*DD], g_ETHI[BT*DD], g_ETLO[BT*DD];
__device__ __nv_bfloat16 g_VTHI[BT*DD], g_VTLO[BT*DD];

__device__ __forceinline__ uint32_t smem_to_u32(const void* p) {
    uint32_t a;
    asm("{ .reg .u64 t; cvta.to.shared.u64 t, %1; cvt.u32.u64 %0, t; }" : "=r"(a) : "l"(p));
    return a;
}
#define CP_ASYNC16(d, s) asm volatile("cp.async.cg.shared.global [%0], [%1], 16;" :: "r"(d), "l"(s))
#define CP_COMMIT() asm volatile("cp.async.commit_group;" ::: "memory")
#define LDSM_X4(r, a) \
    asm volatile("ldmatrix.sync.aligned.m8n8.x4.shared.b16 {%0,%1,%2,%3}, [%4];" \
        : "=r"((r)[0]),"=r"((r)[1]),"=r"((r)[2]),"=r"((r)[3]) : "r"(a))
#define MMA_B16(c, a, b0, b1) \
    asm volatile("mma.sync.aligned.m16n8k16.row.col.f32.bf16.bf16.f32 " \
        "{%0,%1,%2,%3},{%4,%5,%6,%7},{%8,%9},{%0,%1,%2,%3};" \
        : "+f"((c)[0]),"+f"((c)[1]),"+f"((c)[2]),"+f"((c)[3]) \
        : "r"((a)[0]),"r"((a)[1]),"r"((a)[2]),"r"((a)[3]), "r"(b0),"r"(b1))
__device__ __forceinline__ void spl(float x, __nv_bfloat16& h, __nv_bfloat16& l) {
    h = __float2bfloat16(x); l = __float2bfloat16(x - __bfloat162float(h));
}
__device__ __forceinline__ uint32_t pkbf(__nv_bfloat16 a, __nv_bfloat16 b) {
    return (uint32_t)*(uint16_t*)&a | ((uint32_t)*(uint16_t*)&b << 16);
}

__global__ void splitx(const float* __restrict__ X, __nv_bfloat16* __restrict__ hi,
                       __nv_bfloat16* __restrict__ lo)
{
    const int i = blockIdx.x * 256 + threadIdx.x;
    float4 v = *(const float4*)(X + (size_t)i * 4);
    __nv_bfloat16 h[4], l[4];
    float vv[4] = {v.x, v.y, v.z, v.w};
#pragma unroll
    for (int j = 0; j < 4; j++) spl(vv[j], h[j], l[j]);
    *(uint2*)(hi + (size_t)i * 4) = *(uint2*)h;
    *(uint2*)(lo + (size_t)i * 4) = *(uint2*)l;
}

__global__ void wsplit(const float* __restrict__ W, __nv_bfloat16* __restrict__ Whi,
                       __nv_bfloat16* __restrict__ Wlo, int noff)
{
    __shared__ float t[32][33];
    const int n0 = blockIdx.x * 32, k0 = blockIdx.y * 32;
    const int tx = threadIdx.x & 31, ty = threadIdx.x >> 5;
#pragma unroll
    for (int i = 0; i < 32; i += 8)
        t[ty + i][tx] = W[(size_t)(k0 + ty + i) * DD + n0 + tx];
    __syncthreads();
#pragma unroll
    for (int i = 0; i < 32; i += 8) {
        __nv_bfloat16 h, l;
        spl(t[tx][ty + i], h, l);
        Whi[(size_t)(noff + n0 + ty + i) * DD + k0 + tx] = h;
        Wlo[(size_t)(noff + n0 + ty + i) * DD + k0 + tx] = l;
    }
}

#define KC 32
#define ASTRIDE 40
#define MAT_B (128*ASTRIDE*2)
#define STG_B (4*MAT_B)
#define GSM_TOTAL (2*STG_B)

__global__ __launch_bounds__(256)
void mmagemm(const __nv_bfloat16* __restrict__ Ahi, const __nv_bfloat16* __restrict__ Alo,
             const __nv_bfloat16* __restrict__ Bhi, const __nv_bfloat16* __restrict__ Blo,
             float* __restrict__ C, int cs)
{
    extern __shared__ char smem[];
    const uint32_t sb = smem_to_u32(smem);
    const int tid = threadIdx.x, l = tid & 31, wid = tid >> 5;
    const int wm = wid >> 2, wn = wid & 3;
    const int m0 = blockIdx.y * 128, n0 = blockIdx.x * 128;
    float c[4][4][4];
#pragma unroll
    for (int i = 0; i < 4; i++)
#pragma unroll
        for (int j = 0; j < 4; j++)
#pragma unroll
            for (int k = 0; k < 4; k++) c[i][j][k] = 0.f;
    const __nv_bfloat16* gsrc[4] = {Ahi + (size_t)m0 * DD, Alo + (size_t)m0 * DD,
                                    Bhi + (size_t)n0 * DD, Blo + (size_t)n0 * DD};
    const int prow = tid >> 2, pseg = tid & 3;
    {
#pragma unroll
        for (int u = 0; u < 2; u++)
#pragma unroll
            for (int mt = 0; mt < 4; mt++)
                CP_ASYNC16(sb + mt * MAT_B + (prow + u * 64) * 80 + pseg * 16,
                           gsrc[mt] + (size_t)(prow + u * 64) * DD + pseg * 8);
        CP_COMMIT();
    }
    const int arow = (l & 7) + ((l >> 3) & 1) * 8;
    const int acolh = (l >> 4) * 8;
    const int brow = (l & 7) + ((l >> 4) & 1) * 8;
    const int bcolh = ((l >> 3) & 1) * 8;
    for (int ch = 0; ch < DD / KC; ch++) {
        asm volatile("cp.async.wait_group 0;" ::: "memory");
        __syncthreads();
        if (ch + 1 < DD / KC) {
            const int koff = (ch + 1) * KC;
            const uint32_t dbase = sb + ((ch + 1) & 1) * STG_B;
#pragma unroll
            for (int u = 0; u < 2; u++)
#pragma unroll
                for (int mt = 0; mt < 4; mt++)
                    CP_ASYNC16(dbase + mt * MAT_B + (prow + u * 64) * 80 + pseg * 16,
                               gsrc[mt] + (size_t)(prow + u * 64) * DD + koff + pseg * 8);
            CP_COMMIT();
        }
        const uint32_t sA = sb + (ch & 1) * STG_B;
#pragma unroll
        for (int ks = 0; ks < 2; ks++) {
            uint32_t ah[4][4], al[4][4], bh[2][4], bl[2][4];
#pragma unroll
            for (int mi = 0; mi < 4; mi++) {
                const uint32_t off = (uint32_t)((wm * 64 + mi * 16 + arow) * ASTRIDE + ks * 16 + acolh) * 2;
                LDSM_X4(ah[mi], sA + off);
                LDSM_X4(al[mi], sA + MAT_B + off);
            }
#pragma unroll
            for (int np = 0; np < 2; np++) {
                const uint32_t off = (uint32_t)((wn * 32 + np * 16 + brow) * ASTRIDE + ks * 16 + bcolh) * 2;
                LDSM_X4(bh[np], sA + 2 * MAT_B + off);
                LDSM_X4(bl[np], sA + 3 * MAT_B + off);
            }
#pragma unroll
            for (int mi = 0; mi < 4; mi++)
#pragma unroll
                for (int nj = 0; nj < 4; nj++) {
                    const uint32_t* bhp = &bh[nj >> 1][(nj & 1) * 2];
                    const uint32_t* blp = &bl[nj >> 1][(nj & 1) * 2];
                    MMA_B16(c[mi][nj], ah[mi], bhp[0], bhp[1]);
                    MMA_B16(c[mi][nj], ah[mi], blp[0], blp[1]);
                    MMA_B16(c[mi][nj], al[mi], bhp[0], bhp[1]);
                }
        }
    }
#pragma unroll
    for (int mi = 0; mi < 4; mi++)
#pragma unroll
        for (int nj = 0; nj < 4; nj++) {
            const int r0 = m0 + wm * 64 + mi * 16 + (l >> 2);
            const int cb = n0 + wn * 32 + nj * 8 + (l & 3) * 2;
            *(float2*)(C + (size_t)r0 * cs + cb)       = make_float2(c[mi][nj][0], c[mi][nj][1]);
            *(float2*)(C + (size_t)(r0 + 8) * cs + cb) = make_float2(c[mi][nj][2], c[mi][nj][3]);
        }
}

__global__ void sgemm_n4(const float* __restrict__ X, const float* __restrict__ W,
                         float* __restrict__ O)
{
    const int warp = threadIdx.x >> 5, lane = threadIdx.x & 31;
    const int row = blockIdx.x * 8 + warp;
    const float* x = X + (size_t)row * DD;
    float a0 = 0.f, a1 = 0.f, a2 = 0.f, a3 = 0.f;
    for (int k = lane; k < DD; k += 32) {
        float xv = x[k];
        float4 w = *(const float4*)(W + k * 4);
        a0 += xv * w.x; a1 += xv * w.y; a2 += xv * w.z; a3 += xv * w.w;
    }
#pragma unroll
    for (int o = 16; o; o >>= 1) {
        a0 += __shfl_xor_sync(~0u, a0, o); a1 += __shfl_xor_sync(~0u, a1, o);
        a2 += __shfl_xor_sync(~0u, a2, o); a3 += __shfl_xor_sync(~0u, a3, o);
    }
    if (lane == 0) *(float4*)(O + row * 4) = make_float4(a0, a1, a2, a3);
}

__global__ void lam_kernel(const float* __restrict__ XSG, float* __restrict__ LAM)
{
    const int b = blockIdx.x >> 2, h = blockIdx.x & 3;
    const int tid = threadIdx.x;
    __shared__ float ssum[256];
    float loc[8], run = 0.f;
    const int t0 = tid * 8;
#pragma unroll
    for (int u = 0; u < 8; u++) {
        float x = XSG[(size_t)(b * TT + t0 + u) * HH + h];
        float lg = (x >= 0.f) ? -log1pf(expf(-x)) : (x - log1pf(expf(x)));
        run += lg * (1.f / 16.f);
        loc[u] = run;
    }
    ssum[tid] = run;
    __syncthreads();
    for (int off = 1; off < 256; off <<= 1) {
        float v = (tid >= off) ? ssum[tid - off] : 0.f;
        __syncthreads();
        ssum[tid] += v;
        __syncthreads();
    }
    float excl = ssum[tid] - run;
#pragma unroll
    for (int u = 0; u < 8; u++)
        LAM[(size_t)(b * HH + h) * TT + t0 + u] = expf(excl + loc[u]);
}

__global__ void rope_split(const float* __restrict__ P, const float* __restrict__ LAM,
                           __nv_bfloat16* QH, __nv_bfloat16* QL,
                           __nv_bfloat16* KH, __nv_bfloat16* KL)
{
    const int idx = blockIdx.x * 256 + threadIdx.x;
    const int i = idx & 127, h = (idx >> 7) & 3, t = (idx >> 9) & 2047, b = idx >> 20;
    float inv = powf(10000.f, -(float)i * (1.f / 128.f));
    float sn, cs; sincosf((float)t * inv, &sn, &cs);
    const size_t src = (size_t)(b * TT + t) * PD + h * 256;
    const size_t dst = ((size_t)(b * HH + h) * TT + t) * 256;
    float lam = LAM[(size_t)(b * HH + h) * TT + t];
    float q1 = P[src + i], q2 = P[src + i + 128];
    float k1 = P[src + 1024 + i], k2 = P[src + 1024 + i + 128];
    float o0 = (q1 * cs - q2 * sn) * 0.0625f, o1 = (q2 * cs + q1 * sn) * 0.0625f;
    float o2 = (k1 * cs - k2 * sn) * lam,     o3 = (k2 * cs + k1 * sn) * lam;
    __nv_bfloat16 hh, ll;
    spl(o0, hh, ll); QH[dst + i] = hh;       QL[dst + i] = ll;
    spl(o1, hh, ll); QH[dst + i + 128] = hh; QL[dst + i + 128] = ll;
    spl(o2, hh, ll); KH[dst + i] = hh;       KL[dst + i] = ll;
    spl(o3, hh, ll); KH[dst + i + 128] = hh; KL[dst + i + 128] = ll;
}

__global__ void scan_split(const float* __restrict__ P, float* __restrict__ ACC,
                           __nv_bfloat16* EH, __nv_bfloat16* EL,
                           __nv_bfloat16* ETH, __nv_bfloat16* ETL)
{
    const int bh = blockIdx.x, b = bh >> 2, h = bh & 3;
    const int ml = threadIdx.x & 31, tc = threadIdx.x >> 5;
    const int m = blockIdx.y * 32 + ml;
    __shared__ float sums[8][33];
    const size_t src = (size_t)(b * TT) * PD + 4096 + h * 256 + m;
    const size_t dR = (size_t)bh * TT * 256 + m;
    const size_t dT = (size_t)bh * TT * 256 + (size_t)m * TT;
    float a = 0.f;
    for (int t = tc * 256; t < tc * 256 + 256; t++)
        a += expf(fminf(fmaxf(P[src + (size_t)t * PD], -32.f), 32.f));
    sums[tc][ml] = a;
    __syncthreads();
    a = 0.f;
    for (int p = 0; p < tc; p++) a += sums[p][ml];
    for (int t = tc * 256; t < tc * 256 + 256; t++) {
        float e = expf(fminf(fmaxf(P[src + (size_t)t * PD], -32.f), 32.f));
        a += e;
        ACC[dR + (size_t)t * 256] = a;
        __nv_bfloat16 hh, ll;
        spl(e, hh, ll);
        EH[dR + (size_t)t * 256] = hh; EL[dR + (size_t)t * 256] = ll;
        ETH[dT + t] = hh; ETL[dT + t] = ll;
    }
}

__global__ void vtsplit(const float* __restrict__ P, __nv_bfloat16* VTH, __nv_bfloat16* VTL)
{
    __shared__ float tile[32][33];
    const int bh = blockIdx.z, b = bh >> 2, h = bh & 3;
    const int t0 = blockIdx.x * 32, v0 = blockIdx.y * 32;
    const int tx = threadIdx.x & 31, ty = threadIdx.x >> 5;
#pragma unroll
    for (int i = 0; i < 32; i += 8)
        tile[ty + i][tx] = P[(size_t)(b * TT + t0 + ty + i) * PD + 2048 + h * 256 + v0 + tx];
    __syncthreads();
#pragma unroll
    for (int i = 0; i < 32; i += 8) {
        __nv_bfloat16 hh, ll;
        spl(tile[tx][ty + i], hh, ll);
        const size_t d = (size_t)bh * TT * 256 + (size_t)(v0 + ty + i) * TT + t0 + tx;
        VTH[d] = hh; VTL[d] = ll;
    }
}

// ---- fused attention: persistent work-stealing, 512 threads ----
#define QSH 0
#define QSL 33792
#define YSH 67584
#define YSL 101376
#define ZSH 135168
#define ZSL 172032
#define SSH 208896
#define SSL 218112
#define SIDX 227328
#define ASMEM 227344
#define XSTR 264
#define ZSTR 72
#define ATHR 512
#define NTILE 512

__device__ __forceinline__ void ld_xy(uint32_t dH, uint32_t dL,
    const __nv_bfloat16* sH, const __nv_bfloat16* sL, int tid)
{
    const int pr = tid >> 3, ps = tid & 7;
    const __nv_bfloat16* h = sH + (size_t)pr * 256;
    const __nv_bfloat16* l = sL + (size_t)pr * 256;
#pragma unroll
    for (int s = ps; s < 32; s += 8) {
        CP_ASYNC16(dH + pr * XSTR * 2 + s * 16, h + s * 8);
        CP_ASYNC16(dL + pr * XSTR * 2 + s * 16, l + s * 8);
    }
}
__device__ __forceinline__ void ld_z(uint32_t sb,
    const __nv_bfloat16* zH, const __nv_bfloat16* zL, int tid)
{
    const int row = tid >> 1, hf = tid & 1;
    const __nv_bfloat16* h = zH + (size_t)row * TT;
    const __nv_bfloat16* l = zL + (size_t)row * TT;
#pragma unroll
    for (int s = hf * 4; s < hf * 4 + 4; s++) {
        CP_ASYNC16(sb + ZSH + row * ZSTR * 2 + s * 16, h + s * 8);
        CP_ASYNC16(sb + ZSL + row * ZSTR * 2 + s * 16, l + s * 8);
    }
}

__device__ __forceinline__ void stage_loop(char* sm, uint32_t sb, int qi, int tid,
    const __nv_bfloat16* YHb, const __nv_bfloat16* YLb,
    const __nv_bfloat16* ZHb, const __nv_bfloat16* ZLb, float ok[8][4])
{
    const int l = tid & 31, wid = tid >> 5, wm = wid >> 2, wn = wid & 3;
    const int arow = (l & 7) + ((l >> 3) & 1) * 8, acolh = (l >> 4) * 8;
    const int brow = (l & 7) + ((l >> 4) & 1) * 8, bcolh = ((l >> 3) & 1) * 8;
    ld_xy(sb + YSH, sb + YSL, YHb, YLb, tid); CP_COMMIT();
    ld_z(sb, ZHb, ZLb, tid); CP_COMMIT();
    for (int kc = 0; kc <= qi; kc++) {
        asm volatile("cp.async.wait_group 1;" ::: "memory");
        __syncthreads();
        float s4[2][4];
#pragma unroll
        for (int j = 0; j < 2; j++)
#pragma unroll
            for (int k = 0; k < 4; k++) s4[j][k] = 0.f;
#pragma unroll 4
        for (int ks = 0; ks < 16; ks++) {
            uint32_t ah[4], al[4], bhf[4], blf[4];
            const uint32_t ao = (uint32_t)((wm * 16 + arow) * XSTR + ks * 16 + acolh) * 2;
            LDSM_X4(ah, sb + QSH + ao);
            LDSM_X4(al, sb + QSL + ao);
            const uint32_t bo = (uint32_t)((wn * 16 + brow) * XSTR + ks * 16 + bcolh) * 2;
            LDSM_X4(bhf, sb + YSH + bo);
            LDSM_X4(blf, sb + YSL + bo);
#pragma unroll
            for (int nj = 0; nj < 2; nj++) {
                MMA_B16(s4[nj], ah, bhf[nj * 2], bhf[nj * 2 + 1]);
                MMA_B16(s4[nj], ah, blf[nj * 2], blf[nj * 2 + 1]);
                MMA_B16(s4[nj], al, bhf[nj * 2], bhf[nj * 2 + 1]);
            }
        }
        __syncthreads();
        const bool diag = (kc == qi);
#pragma unroll
        for (int nj = 0; nj < 2; nj++)
#pragma unroll
            for (int hf = 0; hf < 2; hf++) {
                const int r = wm * 16 + (l >> 2) + hf * 8;
                const int c = wn * 16 + nj * 8 + (l & 3) * 2;
                float v0 = s4[nj][hf * 2], v1 = s4[nj][hf * 2 + 1];
                if (diag) { if (c > r) v0 = 0.f; if (c + 1 > r) v1 = 0.f; }
                __nv_bfloat16 h0, l0, h1, l1;
                spl(v0, h0, l0); spl(v1, h1, l1);
                *(uint32_t*)(sm + SSH + (r * ZSTR + c) * 2) = pkbf(h0, h1);
                *(uint32_t*)(sm + SSL + (r * ZSTR + c) * 2) = pkbf(l0, l1);
            }
        if (kc < qi) {
            ld_xy(sb + YSH, sb + YSL, YHb + (size_t)(kc + 1) * 64 * 256,
                  YLb + (size_t)(kc + 1) * 64 * 256, tid);
            CP_COMMIT();
        }
        if (kc == qi) asm volatile("cp.async.wait_group 0;" ::: "memory");
        else          asm volatile("cp.async.wait_group 1;" ::: "memory");
        __syncthreads();
#pragma unroll
        for (int ks = 0; ks < 4; ks++) {
            uint32_t ah[4], al[4];
            const uint32_t ao = (uint32_t)((wm * 16 + arow) * ZSTR + ks * 16 + acolh) * 2;
            LDSM_X4(ah, sb + SSH + ao);
            LDSM_X4(al, sb + SSL + ao);
#pragma unroll
            for (int np = 0; np < 4; np++) {
                uint32_t bhf[4], blf[4];
                const uint32_t bo = (uint32_t)((wn * 64 + np * 16 + brow) * ZSTR + ks * 16 + bcolh) * 2;
                LDSM_X4(bhf, sb + ZSH + bo);
                LDSM_X4(blf, sb + ZSL + bo);
#pragma unroll
                for (int nj = 0; nj < 2; nj++) {
                    MMA_B16(ok[np * 2 + nj], ah, bhf[nj * 2], bhf[nj * 2 + 1]);
                    MMA_B16(ok[np * 2 + nj], ah, blf[nj * 2], blf[nj * 2 + 1]);
                    MMA_B16(ok[np * 2 + nj], al, bhf[nj * 2], bhf[nj * 2 + 1]);
                }
            }
        }
        __syncthreads();
        if (kc < qi) { ld_z(sb, ZHb + (kc + 1) * 64, ZLb + (kc + 1) * 64, tid); CP_COMMIT(); }
    }
}

__device__ __forceinline__ void dump_ok(char* sm, float ok[8][4], int wm, int wn, int l)
{
    float* OKS = (float*)(sm + YSH);
#pragma unroll
    for (int idx = 0; idx < 8; idx++)
#pragma unroll
        for (int hf = 0; hf < 2; hf++) {
            const int r = wm * 16 + (l >> 2) + hf * 8;
            const int c = wn * 64 + idx * 8 + (l & 3) * 2;
            *(float2*)&OKS[r * 258 + c] = make_float2(ok[idx][hf * 2], ok[idx][hf * 2 + 1]);
            ok[idx][hf * 2] = 0.f; ok[idx][hf * 2 + 1] = 0.f;
        }
}

__global__ __launch_bounds__(ATHR)
void attn_fused(const __nv_bfloat16* __restrict__ QH, const __nv_bfloat16* __restrict__ QL,
                const __nv_bfloat16* __restrict__ KH, const __nv_bfloat16* __restrict__ KL,
                const __nv_bfloat16* __restrict__ ETH, const __nv_bfloat16* __restrict__ ETL,
                const __nv_bfloat16* __restrict__ EH, const __nv_bfloat16* __restrict__ EL,
                const __nv_bfloat16* __restrict__ VTH, const __nv_bfloat16* __restrict__ VTL,
                const float* __restrict__ ACC, const float* __restrict__ P,
                const float* __restrict__ gnw, int* __restrict__ ctr,
                __nv_bfloat16* __restrict__ AH, __nv_bfloat16* __restrict__ AL)
{
    extern __shared__ char sm[];
    const uint32_t sb = smem_to_u32(sm);
    const int tid = threadIdx.x, l = tid & 31, wid = tid >> 5, wm = wid >> 2, wn = wid & 3;

    float ok[8][4];
#pragma unroll
    for (int j = 0; j < 8; j++)
#pragma unroll
        for (int k = 0; k < 4; k++) ok[j][k] = 0.f;

    for (;;) {
        if (tid == 0) *(int*)(sm + SIDX) = atomicAdd(ctr, 1);
        __syncthreads();
        const int widx = *(int*)(sm + SIDX);
        __syncthreads();
        if (widx >= NTILE) break;

        const int qi = 31 - (widx >> 4);
        const int bh = widx & 15;
        const int b = bh >> 2, h = bh & 3;
        const int qBase = qi * 64;
        const size_t base = (size_t)bh * TT * 256;

        ld_xy(sb + QSH, sb + QSL, QH + base + (size_t)qBase * 256,
              QL + base + (size_t)qBase * 256, tid);
        stage_loop(sm, sb, qi, tid, KH + base, KL + base, ETH + base, ETL + base, ok);

        dump_ok(sm, ok, wm, wn, l);
        __syncthreads();
        float* OKS = (float*)(sm + YSH);
#pragma unroll
        for (int i = 0; i < 4; i++) {
            const int r = wid * 4 + i, t = qBase + r;
            float v[8], acr[8], mx = -3.4e38f;
#pragma unroll
            for (int j = 0; j < 8; j++) {
                const int c = j * 32 + l;
                acr[j] = ACC[base + (size_t)t * 256 + c];
                v[j] = OKS[r * 258 + c] / acr[j];
                mx = fmaxf(mx, v[j]);
            }
#pragma unroll
            for (int o = 16; o; o >>= 1) mx = fmaxf(mx, __shfl_xor_sync(~0u, mx, o));
            float e[8], s = 0.f;
#pragma unroll
            for (int j = 0; j < 8; j++) { e[j] = expf(v[j] - mx); s += e[j]; }
#pragma unroll
            for (int o = 16; o; o >>= 1) s += __shfl_xor_sync(~0u, s, o);
            const float inv = 1.f / s;
#pragma unroll
            for (int j = 0; j < 8; j++) {
                const int c = j * 32 + l;
                __nv_bfloat16 hh, ll;
                spl(e[j] * inv / acr[j], hh, ll);
                *(__nv_bfloat16*)(sm + QSH + (r * XSTR + c) * 2) = hh;
                *(__nv_bfloat16*)(sm + QSL + (r * XSTR + c) * 2) = ll;
            }
        }
        __syncthreads();

        stage_loop(sm, sb, qi, tid, EH + base, EL + base, VTH + base, VTL + base, ok);

        dump_ok(sm, ok, wm, wn, l);
        __syncthreads();
#pragma unroll
        for (int i = 0; i < 4; i++) {
            const int r = wid * 4 + i, t = qBase + r;
            float vv[8], ss = 0.f;
#pragma unroll
            for (int j = 0; j < 8; j++) { vv[j] = OKS[r * 258 + j * 32 + l]; ss += vv[j] * vv[j]; }
#pragma unroll
            for (int o = 16; o; o >>= 1) ss += __shfl_xor_sync(~0u, ss, o);
            const float rn = rsqrtf(ss * (1.f / 256.f) + 1e-5f);
#pragma unroll
            for (int j = 0; j < 8; j++) {
                const int c = j * 32 + l;
                float gg = P[(size_t)(b * TT + t) * PD + 3072 + h * 256 + c];
                float sig = 1.f / (1.f + expf(-gg));
                float act = vv[j] * rn * gnw[c] * gg * sig;
                __nv_bfloat16 hh, ll;
                spl(act, hh, ll);
                AH[(size_t)(b * TT + t) * DD + h * 256 + c] = hh;
                AL[(size_t)(b * TT + t) * DD + h * 256 + c] = ll;
            }
        }
        __syncthreads();
    }
}

extern "C" void kernel_launch(void* const* d_in, const int* in_sizes, int n_in,
                              void* d_out, int out_size)
{
    const float* x   = (const float*)d_in[0];
    const float* qw  = (const float*)d_in[1];
    const float* kw  = (const float*)d_in[2];
    const float* vw  = (const float*)d_in[3];
    const float* gw  = (const float*)d_in[4];
    const float* sw  = (const float*)d_in[5];
    const float* sgw = (const float*)d_in[6];
    const float* gnw = (const float*)d_in[7];
    const float* ow  = (const float*)d_in[8];
    float* out = (float*)d_out;

    float *P, *ACC, *XSG, *LAM;
    int* CTR;
    __nv_bfloat16 *XHI, *XLO, *WHI, *WLO, *QHI, *QLO, *KHI, *KLO;
    __nv_bfloat16 *EHI, *ELO, *ETHI, *ETLO, *VTHI, *VTLO;
    cudaGetSymbolAddress((void**)&P, g_P);     cudaGetSymbolAddress((void**)&ACC, g_ACC);
    cudaGetSymbolAddress((void**)&XSG, g_XSG); cudaGetSymbolAddress((void**)&LAM, g_LAM);
    cudaGetSymbolAddress((void**)&CTR, g_ctr);
    cudaGetSymbolAddress((void**)&XHI, g_XHI); cudaGetSymbolAddress((void**)&XLO, g_XLO);
    cudaGetSymbolAddress((void**)&WHI, g_WHI); cudaGetSymbolAddress((void**)&WLO, g_WLO);
    cudaGetSymbolAddress((void**)&QHI, g_QHI); cudaGetSymbolAddress((void**)&QLO, g_QLO);
    cudaGetSymbolAddress((void**)&KHI, g_KHI); cudaGetSymbolAddress((void**)&KLO, g_KLO);
    cudaGetSymbolAddress((void**)&EHI, g_EHI); cudaGetSymbolAddress((void**)&ELO, g_ELO);
    cudaGetSymbolAddress((void**)&ETHI, g_ETHI); cudaGetSymbolAddress((void**)&ETLO, g_ETLO);
    cudaGetSymbolAddress((void**)&VTHI, g_VTHI); cudaGetSymbolAddress((void**)&VTLO, g_VTLO);

    static int done = 0;
    if (!done) {
        cudaFuncSetAttribute(mmagemm, cudaFuncAttributeMaxDynamicSharedMemorySize, GSM_TOTAL);
        cudaFuncSetAttribute(attn_fused, cudaFuncAttributeMaxDynamicSharedMemorySize, ASMEM);
        done = 1;
    }

    const dim3 wgrid(32, 32);
    const int sxg = (BT * DD / 4) / 256;

    cudaMemsetAsync(CTR, 0, sizeof(int));
    splitx<<<sxg, 256>>>(x, XHI, XLO);
    sgemm_n4<<<BT / 8, 256>>>(x, sgw, XSG);
    wsplit<<<wgrid, 256>>>(qw, WHI, WLO, 0);
    wsplit<<<wgrid, 256>>>(kw, WHI, WLO, 1024);
    wsplit<<<wgrid, 256>>>(vw, WHI, WLO, 2048);
    wsplit<<<wgrid, 256>>>(gw, WHI, WLO, 3072);
    wsplit<<<wgrid, 256>>>(sw, WHI, WLO, 4096);
    mmagemm<<<dim3(PD / 128, BT / 128), 256, GSM_TOTAL>>>(XHI, XLO, WHI, WLO, P, PD);

    lam_kernel<<<BH, 256>>>(XSG, LAM);
    rope_split<<<(BB * TT * HH * 128) / 256, 256>>>(P, LAM, QHI, QLO, KHI, KLO);
    scan_split<<<dim3(BH, 8), 256>>>(P, ACC, EHI, ELO, ETHI, ETLO);
    vtsplit<<<dim3(TT / 32, 8, BH), 256>>>(P, VTHI, VTLO);

    attn_fused<<<148, ATHR, ASMEM>>>(QHI, QLO, KHI, KLO, ETHI, ETLO,
                                     EHI, ELO, VTHI, VTLO, ACC, P, gnw, CTR,
                                     XHI, XLO);

    wsplit<<<wgrid, 256>>>(ow, WHI, WLO, 0);
    mmagemm<<<dim3(DD / 128, BT / 128), 256, GSM_TOTAL>>>(XHI, XLO, WHI, WLO, out, DD);
}

// round 11
// speedup vs baseline: 3.0844x; 1.0669x over previous
#include <cuda_runtime.h>
#include <cuda_bf16.h>
#include <math.h>
#include <stdint.h>

#define BB 4
#define TT 2048
#define HH 4
#define DD 1024
#define PD 5120
#define BT (BB*TT)
#define BH 16

__device__ float g_P[(size_t)BT*PD], g_ACC[BT*DD], g_XSG[BT*HH], g_LAM[BH*TT];
__device__ int g_ctr;
__device__ __nv_bfloat16 g_XHI[BT*DD], g_XLO[BT*DD], g_WHI[(size_t)PD*DD], g_WLO[(size_t)PD*DD];
__device__ __nv_bfloat16 g_QHI[BT*DD], g_QLO[BT*DD], g_KHI[BT*DD], g_KLO[BT*DD];
__device__ __nv_bfloat16 g_EHI[BT*DD], g_ELO[BT*DD], g_ETHI[BT*DD], g_ETLO[BT*DD];
__device__ __nv_bfloat16 g_VTHI[BT*DD], g_VTLO[BT*DD];

__device__ __forceinline__ uint32_t smem_to_u32(const void* p) {
    uint32_t a;
    asm("{ .reg .u64 t; cvta.to.shared.u64 t, %1; cvt.u32.u64 %0, t; }" : "=r"(a) : "l"(p));
    return a;
}
#define CP_ASYNC16(d, s) asm volatile("cp.async.cg.shared.global [%0], [%1], 16;" :: "r"(d), "l"(s))
#define CP_COMMIT() asm volatile("cp.async.commit_group;" ::: "memory")
#define LDSM_X4(r, a) \
    asm volatile("ldmatrix.sync.aligned.m8n8.x4.shared.b16 {%0,%1,%2,%3}, [%4];" \
        : "=r"((r)[0]),"=r"((r)[1]),"=r"((r)[2]),"=r"((r)[3]) : "r"(a))
#define MMA_B16(c, a, b0, b1) \
    asm volatile("mma.sync.aligned.m16n8k16.row.col.f32.bf16.bf16.f32 " \
        "{%0,%1,%2,%3},{%4,%5,%6,%7},{%8,%9},{%0,%1,%2,%3};" \
        : "+f"((c)[0]),"+f"((c)[1]),"+f"((c)[2]),"+f"((c)[3]) \
        : "r"((a)[0]),"r"((a)[1]),"r"((a)[2]),"r"((a)[3]), "r"(b0),"r"(b1))
__device__ __forceinline__ void spl(float x, __nv_bfloat16& h, __nv_bfloat16& l) {
    h = __float2bfloat16(x); l = __float2bfloat16(x - __bfloat162float(h));
}
__device__ __forceinline__ uint32_t pkbf(__nv_bfloat16 a, __nv_bfloat16 b) {
    return (uint32_t)*(uint16_t*)&a | ((uint32_t)*(uint16_t*)&b << 16);
}

__global__ void splitx(const float* __restrict__ X, __nv_bfloat16* __restrict__ hi,
                       __nv_bfloat16* __restrict__ lo)
{
    const int i = blockIdx.x * 256 + threadIdx.x;
    float4 v = *(const float4*)(X + (size_t)i * 4);
    __nv_bfloat16 h[4], l[4];
    float vv[4] = {v.x, v.y, v.z, v.w};
#pragma unroll
    for (int j = 0; j < 4; j++) spl(vv[j], h[j], l[j]);
    *(uint2*)(hi + (size_t)i * 4) = *(uint2*)h;
    *(uint2*)(lo + (size_t)i * 4) = *(uint2*)l;
}

__global__ void wsplit(const float* __restrict__ W, __nv_bfloat16* __restrict__ Whi,
                       __nv_bfloat16* __restrict__ Wlo, int noff)
{
    __shared__ float t[32][33];
    const int n0 = blockIdx.x * 32, k0 = blockIdx.y * 32;
    const int tx = threadIdx.x & 31, ty = threadIdx.x >> 5;
#pragma unroll
    for (int i = 0; i < 32; i += 8)
        t[ty + i][tx] = W[(size_t)(k0 + ty + i) * DD + n0 + tx];
    __syncthreads();
#pragma unroll
    for (int i = 0; i < 32; i += 8) {
        __nv_bfloat16 h, l;
        spl(t[tx][ty + i], h, l);
        Whi[(size_t)(noff + n0 + ty + i) * DD + k0 + tx] = h;
        Wlo[(size_t)(noff + n0 + ty + i) * DD + k0 + tx] = l;
    }
}

#define KC 32
#define ASTRIDE 40
#define MAT_B (128*ASTRIDE*2)
#define STG_B (4*MAT_B)
#define GSM_TOTAL (2*STG_B)

__global__ __launch_bounds__(256)
void mmagemm(const __nv_bfloat16* __restrict__ Ahi, const __nv_bfloat16* __restrict__ Alo,
             const __nv_bfloat16* __restrict__ Bhi, const __nv_bfloat16* __restrict__ Blo,
             float* __restrict__ C, int cs)
{
    extern __shared__ char smem[];
    const uint32_t sb = smem_to_u32(smem);
    const int tid = threadIdx.x, l = tid & 31, wid = tid >> 5;
    const int wm = wid >> 2, wn = wid & 3;
    const int m0 = blockIdx.y * 128, n0 = blockIdx.x * 128;
    float c[4][4][4];
#pragma unroll
    for (int i = 0; i < 4; i++)
#pragma unroll
        for (int j = 0; j < 4; j++)
#pragma unroll
            for (int k = 0; k < 4; k++) c[i][j][k] = 0.f;
    const __nv_bfloat16* gsrc[4] = {Ahi + (size_t)m0 * DD, Alo + (size_t)m0 * DD,
                                    Bhi + (size_t)n0 * DD, Blo + (size_t)n0 * DD};
    const int prow = tid >> 2, pseg = tid & 3;
    {
#pragma unroll
        for (int u = 0; u < 2; u++)
#pragma unroll
            for (int mt = 0; mt < 4; mt++)
                CP_ASYNC16(sb + mt * MAT_B + (prow + u * 64) * 80 + pseg * 16,
                           gsrc[mt] + (size_t)(prow + u * 64) * DD + pseg * 8);
        CP_COMMIT();
    }
    const int arow = (l & 7) + ((l >> 3) & 1) * 8;
    const int acolh = (l >> 4) * 8;
    const int brow = (l & 7) + ((l >> 4) & 1) * 8;
    const int bcolh = ((l >> 3) & 1) * 8;
    for (int ch = 0; ch < DD / KC; ch++) {
        asm volatile("cp.async.wait_group 0;" ::: "memory");
        __syncthreads();
        if (ch + 1 < DD / KC) {
            const int koff = (ch + 1) * KC;
            const uint32_t dbase = sb + ((ch + 1) & 1) * STG_B;
#pragma unroll
            for (int u = 0; u < 2; u++)
#pragma unroll
                for (int mt = 0; mt < 4; mt++)
                    CP_ASYNC16(dbase + mt * MAT_B + (prow + u * 64) * 80 + pseg * 16,
                               gsrc[mt] + (size_t)(prow + u * 64) * DD + koff + pseg * 8);
            CP_COMMIT();
        }
        const uint32_t sA = sb + (ch & 1) * STG_B;
#pragma unroll
        for (int ks = 0; ks < 2; ks++) {
            uint32_t ah[4][4], al[4][4], bh[2][4], bl[2][4];
#pragma unroll
            for (int mi = 0; mi < 4; mi++) {
                const uint32_t off = (uint32_t)((wm * 64 + mi * 16 + arow) * ASTRIDE + ks * 16 + acolh) * 2;
                LDSM_X4(ah[mi], sA + off);
                LDSM_X4(al[mi], sA + MAT_B + off);
            }
#pragma unroll
            for (int np = 0; np < 2; np++) {
                const uint32_t off = (uint32_t)((wn * 32 + np * 16 + brow) * ASTRIDE + ks * 16 + bcolh) * 2;
                LDSM_X4(bh[np], sA + 2 * MAT_B + off);
                LDSM_X4(bl[np], sA + 3 * MAT_B + off);
            }
#pragma unroll
            for (int mi = 0; mi < 4; mi++)
#pragma unroll
                for (int nj = 0; nj < 4; nj++) {
                    const uint32_t* bhp = &bh[nj >> 1][(nj & 1) * 2];
                    const uint32_t* blp = &bl[nj >> 1][(nj & 1) * 2];
                    MMA_B16(c[mi][nj], ah[mi], bhp[0], bhp[1]);
                    MMA_B16(c[mi][nj], ah[mi], blp[0], blp[1]);
                    MMA_B16(c[mi][nj], al[mi], bhp[0], bhp[1]);
                }
        }
    }
#pragma unroll
    for (int mi = 0; mi < 4; mi++)
#pragma unroll
        for (int nj = 0; nj < 4; nj++) {
            const int r0 = m0 + wm * 64 + mi * 16 + (l >> 2);
            const int cb = n0 + wn * 32 + nj * 8 + (l & 3) * 2;
            *(float2*)(C + (size_t)r0 * cs + cb)       = make_float2(c[mi][nj][0], c[mi][nj][1]);
            *(float2*)(C + (size_t)(r0 + 8) * cs + cb) = make_float2(c[mi][nj][2], c[mi][nj][3]);
        }
}

__global__ void sgemm_n4(const float* __restrict__ X, const float* __restrict__ W,
                         float* __restrict__ O)
{
    const int warp = threadIdx.x >> 5, lane = threadIdx.x & 31;
    const int row = blockIdx.x * 8 + warp;
    const float* x = X + (size_t)row * DD;
    float a0 = 0.f, a1 = 0.f, a2 = 0.f, a3 = 0.f;
    for (int k = lane; k < DD; k += 32) {
        float xv = x[k];
        float4 w = *(const float4*)(W + k * 4);
        a0 += xv * w.x; a1 += xv * w.y; a2 += xv * w.z; a3 += xv * w.w;
    }
#pragma unroll
    for (int o = 16; o; o >>= 1) {
        a0 += __shfl_xor_sync(~0u, a0, o); a1 += __shfl_xor_sync(~0u, a1, o);
        a2 += __shfl_xor_sync(~0u, a2, o); a3 += __shfl_xor_sync(~0u, a3, o);
    }
    if (lane == 0) *(float4*)(O + row * 4) = make_float4(a0, a1, a2, a3);
}

__global__ void lam_kernel(const float* __restrict__ XSG, float* __restrict__ LAM)
{
    const int b = blockIdx.x >> 2, h = blockIdx.x & 3;
    const int tid = threadIdx.x;
    __shared__ float ssum[256];
    float loc[8], run = 0.f;
    const int t0 = tid * 8;
#pragma unroll
    for (int u = 0; u < 8; u++) {
        float x = XSG[(size_t)(b * TT + t0 + u) * HH + h];
        float lg = (x >= 0.f) ? -log1pf(expf(-x)) : (x - log1pf(expf(x)));
        run += lg * (1.f / 16.f);
        loc[u] = run;
    }
    ssum[tid] = run;
    __syncthreads();
    for (int off = 1; off < 256; off <<= 1) {
        float v = (tid >= off) ? ssum[tid - off] : 0.f;
        __syncthreads();
        ssum[tid] += v;
        __syncthreads();
    }
    float excl = ssum[tid] - run;
#pragma unroll
    for (int u = 0; u < 8; u++)
        LAM[(size_t)(b * HH + h) * TT + t0 + u] = expf(excl + loc[u]);
}

// ---- merged prep: scan (blocks 0..127, long-pole first), rope, vtsplit ----
#define PREP_SCAN 128
#define PREP_ROPE (PREP_SCAN + 16384)
#define PREP_VT   (PREP_ROPE + 8192)

__global__ __launch_bounds__(256)
void prep_all(const float* __restrict__ P, const float* __restrict__ LAM,
              float* __restrict__ ACC,
              __nv_bfloat16* EH, __nv_bfloat16* EL,
              __nv_bfloat16* ETH, __nv_bfloat16* ETL,
              __nv_bfloat16* QH, __nv_bfloat16* QL,
              __nv_bfloat16* KH, __nv_bfloat16* KL,
              __nv_bfloat16* VTH, __nv_bfloat16* VTL)
{
    const int bid = blockIdx.x;
    if (bid < PREP_SCAN) {
        // ---- scan: E = exp(clip(s)), ACC cumsum, E row-major + transposed splits ----
        __shared__ float sums[8][33];
        __shared__ uint16_t tph[8][32][33], tpl[8][32][33];
        const int bh = bid & 15, b = bh >> 2, h = bh & 3;
        const int ml = threadIdx.x & 31, tc = threadIdx.x >> 5;
        const int m0 = (bid >> 4) * 32;
        const int m = m0 + ml;
        const size_t src = (size_t)(b * TT) * PD + 4096 + h * 256 + m;
        const size_t dR = (size_t)bh * TT * 256 + m;
        const size_t dTb = (size_t)bh * TT * 256;
        float a = 0.f;
        for (int t = tc * 256; t < tc * 256 + 256; t++)
            a += expf(fminf(fmaxf(P[src + (size_t)t * PD], -32.f), 32.f));
        sums[tc][ml] = a;
        __syncthreads();
        a = 0.f;
        for (int p = 0; p < tc; p++) a += sums[p][ml];
        for (int seg = 0; seg < 8; seg++) {
            const int tb = tc * 256 + seg * 32;
#pragma unroll 4
            for (int u = 0; u < 32; u++) {
                const int t = tb + u;
                float e = expf(fminf(fmaxf(P[src + (size_t)t * PD], -32.f), 32.f));
                a += e;
                ACC[dR + (size_t)t * 256] = a;
                __nv_bfloat16 hh, ll;
                spl(e, hh, ll);
                EH[dR + (size_t)t * 256] = hh; EL[dR + (size_t)t * 256] = ll;
                tph[tc][u][ml] = *(uint16_t*)&hh;
                tpl[tc][u][ml] = *(uint16_t*)&ll;
            }
            __syncwarp();
#pragma unroll 4
            for (int mm = 0; mm < 32; mm++) {
                const size_t d = dTb + (size_t)(m0 + mm) * TT + tb + ml;
                uint16_t vh = tph[tc][ml][mm], vl = tpl[tc][ml][mm];
                ETH[d] = *(__nv_bfloat16*)&vh;
                ETL[d] = *(__nv_bfloat16*)&vl;
            }
            __syncwarp();
        }
    } else if (bid < PREP_ROPE) {
        // ---- rope + decay: Q,K bf16 splits, bh-major ----
        const int idx = (bid - PREP_SCAN) * 256 + threadIdx.x;
        const int i = idx & 127, h = (idx >> 7) & 3, t = (idx >> 9) & 2047, b = idx >> 20;
        float inv = powf(10000.f, -(float)i * (1.f / 128.f));
        float sn, cs; sincosf((float)t * inv, &sn, &cs);
        const size_t src = (size_t)(b * TT + t) * PD + h * 256;
        const size_t dst = ((size_t)(b * HH + h) * TT + t) * 256;
        float lam = LAM[(size_t)(b * HH + h) * TT + t];
        float q1 = P[src + i], q2 = P[src + i + 128];
        float k1 = P[src + 1024 + i], k2 = P[src + 1024 + i + 128];
        float o0 = (q1 * cs - q2 * sn) * 0.0625f, o1 = (q2 * cs + q1 * sn) * 0.0625f;
        float o2 = (k1 * cs - k2 * sn) * lam,     o3 = (k2 * cs + k1 * sn) * lam;
        __nv_bfloat16 hh, ll;
        spl(o0, hh, ll); QH[dst + i] = hh;       QL[dst + i] = ll;
        spl(o1, hh, ll); QH[dst + i + 128] = hh; QL[dst + i + 128] = ll;
        spl(o2, hh, ll); KH[dst + i] = hh;       KL[dst + i] = ll;
        spl(o3, hh, ll); KH[dst + i + 128] = hh; KL[dst + i + 128] = ll;
    } else {
        // ---- V transpose split ----
        __shared__ float tile[32][33];
        const int id = bid - PREP_ROPE;
        const int t0 = (id & 63) * 32, v0 = ((id >> 6) & 7) * 32, bh = id >> 9;
        const int b = bh >> 2, h = bh & 3;
        const int tx = threadIdx.x & 31, ty = threadIdx.x >> 5;
#pragma unroll
        for (int i = 0; i < 32; i += 8)
            tile[ty + i][tx] = P[(size_t)(b * TT + t0 + ty + i) * PD + 2048 + h * 256 + v0 + tx];
        __syncthreads();
#pragma unroll
        for (int i = 0; i < 32; i += 8) {
            __nv_bfloat16 hh, ll;
            spl(tile[tx][ty + i], hh, ll);
            const size_t d = (size_t)bh * TT * 256 + (size_t)(v0 + ty + i) * TT + t0 + tx;
            VTH[d] = hh; VTL[d] = ll;
        }
    }
}

// ---- fused attention: persistent work-stealing, 512 threads ----
#define QSH 0
#define QSL 33792
#define YSH 67584
#define YSL 101376
#define ZSH 135168
#define ZSL 172032
#define SSH 208896
#define SSL 218112
#define SIDX 227328
#define ASMEM 227344
#define XSTR 264
#define ZSTR 72
#define ATHR 512
#define NTILE 512

__device__ __forceinline__ void ld_xy(uint32_t dH, uint32_t dL,
    const __nv_bfloat16* sH, const __nv_bfloat16* sL, int tid)
{
    const int pr = tid >> 3, ps = tid & 7;
    const __nv_bfloat16* h = sH + (size_t)pr * 256;
    const __nv_bfloat16* l = sL + (size_t)pr * 256;
#pragma unroll
    for (int s = ps; s < 32; s += 8) {
        CP_ASYNC16(dH + pr * XSTR * 2 + s * 16, h + s * 8);
        CP_ASYNC16(dL + pr * XSTR * 2 + s * 16, l + s * 8);
    }
}
__device__ __forceinline__ void ld_z(uint32_t sb,
    const __nv_bfloat16* zH, const __nv_bfloat16* zL, int tid)
{
    const int row = tid >> 1, hf = tid & 1;
    const __nv_bfloat16* h = zH + (size_t)row * TT;
    const __nv_bfloat16* l = zL + (size_t)row * TT;
#pragma unroll
    for (int s = hf * 4; s < hf * 4 + 4; s++) {
        CP_ASYNC16(sb + ZSH + row * ZSTR * 2 + s * 16, h + s * 8);
        CP_ASYNC16(sb + ZSL + row * ZSTR * 2 + s * 16, l + s * 8);
    }
}

__device__ __forceinline__ void stage_loop(char* sm, uint32_t sb, int qi, int tid,
    const __nv_bfloat16* YHb, const __nv_bfloat16* YLb,
    const __nv_bfloat16* ZHb, const __nv_bfloat16* ZLb, float ok[8][4])
{
    const int l = tid & 31, wid = tid >> 5, wm = wid >> 2, wn = wid & 3;
    const int arow = (l & 7) + ((l >> 3) & 1) * 8, acolh = (l >> 4) * 8;
    const int brow = (l & 7) + ((l >> 4) & 1) * 8, bcolh = ((l >> 3) & 1) * 8;
    ld_xy(sb + YSH, sb + YSL, YHb, YLb, tid); CP_COMMIT();
    ld_z(sb, ZHb, ZLb, tid); CP_COMMIT();
    for (int kc = 0; kc <= qi; kc++) {
        asm volatile("cp.async.wait_group 1;" ::: "memory");
        __syncthreads();
        float s4[2][4];
#pragma unroll
        for (int j = 0; j < 2; j++)
#pragma unroll
            for (int k = 0; k < 4; k++) s4[j][k] = 0.f;
#pragma unroll 4
        for (int ks = 0; ks < 16; ks++) {
            uint32_t ah[4], al[4], bhf[4], blf[4];
            const uint32_t ao = (uint32_t)((wm * 16 + arow) * XSTR + ks * 16 + acolh) * 2;
            LDSM_X4(ah, sb + QSH + ao);
            LDSM_X4(al, sb + QSL + ao);
            const uint32_t bo = (uint32_t)((wn * 16 + brow) * XSTR + ks * 16 + bcolh) * 2;
            LDSM_X4(bhf, sb + YSH + bo);
            LDSM_X4(blf, sb + YSL + bo);
#pragma unroll
            for (int nj = 0; nj < 2; nj++) {
                MMA_B16(s4[nj], ah, bhf[nj * 2], bhf[nj * 2 + 1]);
                MMA_B16(s4[nj], ah, blf[nj * 2], blf[nj * 2 + 1]);
                MMA_B16(s4[nj], al, bhf[nj * 2], bhf[nj * 2 + 1]);
            }
        }
        __syncthreads();
        const bool diag = (kc == qi);
#pragma unroll
        for (int nj = 0; nj < 2; nj++)
#pragma unroll
            for (int hf = 0; hf < 2; hf++) {
                const int r = wm * 16 + (l >> 2) + hf * 8;
                const int c = wn * 16 + nj * 8 + (l & 3) * 2;
                float v0 = s4[nj][hf * 2], v1 = s4[nj][hf * 2 + 1];
                if (diag) { if (c > r) v0 = 0.f; if (c + 1 > r) v1 = 0.f; }
                __nv_bfloat16 h0, l0, h1, l1;
                spl(v0, h0, l0); spl(v1, h1, l1);
                *(uint32_t*)(sm + SSH + (r * ZSTR + c) * 2) = pkbf(h0, h1);
                *(uint32_t*)(sm + SSL + (r * ZSTR + c) * 2) = pkbf(l0, l1);
            }
        if (kc < qi) {
            ld_xy(sb + YSH, sb + YSL, YHb + (size_t)(kc + 1) * 64 * 256,
                  YLb + (size_t)(kc + 1) * 64 * 256, tid);
            CP_COMMIT();
        }
        if (kc == qi) asm volatile("cp.async.wait_group 0;" ::: "memory");
        else          asm volatile("cp.async.wait_group 1;" ::: "memory");
        __syncthreads();
#pragma unroll
        for (int ks = 0; ks < 4; ks++) {
            uint32_t ah[4], al[4];
            const uint32_t ao = (uint32_t)((wm * 16 + arow) * ZSTR + ks * 16 + acolh) * 2;
            LDSM_X4(ah, sb + SSH + ao);
            LDSM_X4(al, sb + SSL + ao);
#pragma unroll
            for (int np = 0; np < 4; np++) {
                uint32_t bhf[4], blf[4];
                const uint32_t bo = (uint32_t)((wn * 64 + np * 16 + brow) * ZSTR + ks * 16 + bcolh) * 2;
                LDSM_X4(bhf, sb + ZSH + bo);
                LDSM_X4(blf, sb + ZSL + bo);
#pragma unroll
                for (int nj = 0; nj < 2; nj++) {
                    MMA_B16(ok[np * 2 + nj], ah, bhf[nj * 2], bhf[nj * 2 + 1]);
                    MMA_B16(ok[np * 2 + nj], ah, blf[nj * 2], blf[nj * 2 + 1]);
                    MMA_B16(ok[np * 2 + nj], al, bhf[nj * 2], bhf[nj * 2 + 1]);
                }
            }
        }
        __syncthreads();
        if (kc < qi) { ld_z(sb, ZHb + (kc + 1) * 64, ZLb + (kc + 1) * 64, tid); CP_COMMIT(); }
    }
}

__device__ __forceinline__ void dump_ok(char* sm, float ok[8][4], int wm, int wn, int l)
{
    float* OKS = (float*)(sm + YSH);
#pragma unroll
    for (int idx = 0; idx < 8; idx++)
#pragma unroll
        for (int hf = 0; hf < 2; hf++) {
            const int r = wm * 16 + (l >> 2) + hf * 8;
            const int c = wn * 64 + idx * 8 + (l & 3) * 2;
            *(float2*)&OKS[r * 258 + c] = make_float2(ok[idx][hf * 2], ok[idx][hf * 2 + 1]);
            ok[idx][hf * 2] = 0.f; ok[idx][hf * 2 + 1] = 0.f;
        }
}

__global__ __launch_bounds__(ATHR)
void attn_fused(const __nv_bfloat16* __restrict__ QH, const __nv_bfloat16* __restrict__ QL,
                const __nv_bfloat16* __restrict__ KH, const __nv_bfloat16* __restrict__ KL,
                const __nv_bfloat16* __restrict__ ETH, const __nv_bfloat16* __restrict__ ETL,
                const __nv_bfloat16* __restrict__ EH, const __nv_bfloat16* __restrict__ EL,
                const __nv_bfloat16* __restrict__ VTH, const __nv_bfloat16* __restrict__ VTL,
                const float* __restrict__ ACC, const float* __restrict__ P,
                const float* __restrict__ gnw, int* __restrict__ ctr,
                __nv_bfloat16* __restrict__ AH, __nv_bfloat16* __restrict__ AL)
{
    extern __shared__ char sm[];
    const uint32_t sb = smem_to_u32(sm);
    const int tid = threadIdx.x, l = tid & 31, wid = tid >> 5, wm = wid >> 2, wn = wid & 3;

    float ok[8][4];
#pragma unroll
    for (int j = 0; j < 8; j++)
#pragma unroll
        for (int k = 0; k < 4; k++) ok[j][k] = 0.f;

    for (;;) {
        if (tid == 0) *(int*)(sm + SIDX) = atomicAdd(ctr, 1);
        __syncthreads();
        const int widx = *(int*)(sm + SIDX);
        __syncthreads();
        if (widx >= NTILE) break;

        const int qi = 31 - (widx >> 4);
        const int bh = widx & 15;
        const int b = bh >> 2, h = bh & 3;
        const int qBase = qi * 64;
        const size_t base = (size_t)bh * TT * 256;

        ld_xy(sb + QSH, sb + QSL, QH + base + (size_t)qBase * 256,
              QL + base + (size_t)qBase * 256, tid);
        stage_loop(sm, sb, qi, tid, KH + base, KL + base, ETH + base, ETL + base, ok);

        dump_ok(sm, ok, wm, wn, l);
        __syncthreads();
        float* OKS = (float*)(sm + YSH);
#pragma unroll
        for (int i = 0; i < 4; i++) {
            const int r = wid * 4 + i, t = qBase + r;
            float v[8], acr[8], mx = -3.4e38f;
#pragma unroll
            for (int j = 0; j < 8; j++) {
                const int c = j * 32 + l;
                acr[j] = ACC[base + (size_t)t * 256 + c];
                v[j] = OKS[r * 258 + c] / acr[j];
                mx = fmaxf(mx, v[j]);
            }
#pragma unroll
            for (int o = 16; o; o >>= 1) mx = fmaxf(mx, __shfl_xor_sync(~0u, mx, o));
            float e[8], s = 0.f;
#pragma unroll
            for (int j = 0; j < 8; j++) { e[j] = expf(v[j] - mx); s += e[j]; }
#pragma unroll
            for (int o = 16; o; o >>= 1) s += __shfl_xor_sync(~0u, s, o);
            const float inv = 1.f / s;
#pragma unroll
            for (int j = 0; j < 8; j++) {
                const int c = j * 32 + l;
                __nv_bfloat16 hh, ll;
                spl(e[j] * inv / acr[j], hh, ll);
                *(__nv_bfloat16*)(sm + QSH + (r * XSTR + c) * 2) = hh;
                *(__nv_bfloat16*)(sm + QSL + (r * XSTR + c) * 2) = ll;
            }
        }
        __syncthreads();

        stage_loop(sm, sb, qi, tid, EH + base, EL + base, VTH + base, VTL + base, ok);

        dump_ok(sm, ok, wm, wn, l);
        __syncthreads();
#pragma unroll
        for (int i = 0; i < 4; i++) {
            const int r = wid * 4 + i, t = qBase + r;
            float vv[8], ss = 0.f;
#pragma unroll
            for (int j = 0; j < 8; j++) { vv[j] = OKS[r * 258 + j * 32 + l]; ss += vv[j] * vv[j]; }
#pragma unroll
            for (int o = 16; o; o >>= 1) ss += __shfl_xor_sync(~0u, ss, o);
            const float rn = rsqrtf(ss * (1.f / 256.f) + 1e-5f);
#pragma unroll
            for (int j = 0; j < 8; j++) {
                const int c = j * 32 + l;
                float gg = P[(size_t)(b * TT + t) * PD + 3072 + h * 256 + c];
                float sig = 1.f / (1.f + expf(-gg));
                float act = vv[j] * rn * gnw[c] * gg * sig;
                __nv_bfloat16 hh, ll;
                spl(act, hh, ll);
                AH[(size_t)(b * TT + t) * DD + h * 256 + c] = hh;
                AL[(size_t)(b * TT + t) * DD + h * 256 + c] = ll;
            }
        }
        __syncthreads();
    }
}

extern "C" void kernel_launch(void* const* d_in, const int* in_sizes, int n_in,
                              void* d_out, int out_size)
{
    const float* x   = (const float*)d_in[0];
    const float* qw  = (const float*)d_in[1];
    const float* kw  = (const float*)d_in[2];
    const float* vw  = (const float*)d_in[3];
    const float* gw  = (const float*)d_in[4];
    const float* sw  = (const float*)d_in[5];
    const float* sgw = (const float*)d_in[6];
    const float* gnw = (const float*)d_in[7];
    const float* ow  = (const float*)d_in[8];
    float* out = (float*)d_out;

    float *P, *ACC, *XSG, *LAM;
    int* CTR;
    __nv_bfloat16 *XHI, *XLO, *WHI, *WLO, *QHI, *QLO, *KHI, *KLO;
    __nv_bfloat16 *EHI, *ELO, *ETHI, *ETLO, *VTHI, *VTLO;
    cudaGetSymbolAddress((void**)&P, g_P);     cudaGetSymbolAddress((void**)&ACC, g_ACC);
    cudaGetSymbolAddress((void**)&XSG, g_XSG); cudaGetSymbolAddress((void**)&LAM, g_LAM);
    cudaGetSymbolAddress((void**)&CTR, g_ctr);
    cudaGetSymbolAddress((void**)&XHI, g_XHI); cudaGetSymbolAddress((void**)&XLO, g_XLO);
    cudaGetSymbolAddress((void**)&WHI, g_WHI); cudaGetSymbolAddress((void**)&WLO, g_WLO);
    cudaGetSymbolAddress((void**)&QHI, g_QHI); cudaGetSymbolAddress((void**)&QLO, g_QLO);
    cudaGetSymbolAddress((void**)&KHI, g_KHI); cudaGetSymbolAddress((void**)&KLO, g_KLO);
    cudaGetSymbolAddress((void**)&EHI, g_EHI); cudaGetSymbolAddress((void**)&ELO, g_ELO);
    cudaGetSymbolAddress((void**)&ETHI, g_ETHI); cudaGetSymbolAddress((void**)&ETLO, g_ETLO);
    cudaGetSymbolAddress((void**)&VTHI, g_VTHI); cudaGetSymbolAddress((void**)&VTLO, g_VTLO);

    static int done = 0;
    if (!done) {
        cudaFuncSetAttribute(mmagemm, cudaFuncAttributeMaxDynamicSharedMemorySize, GSM_TOTAL);
        cudaFuncSetAttribute(attn_fused, cudaFuncAttributeMaxDynamicSharedMemorySize, ASMEM);
        done = 1;
    }

    const dim3 wgrid(32, 32);
    const int sxg = (BT * DD / 4) / 256;

    cudaMemsetAsync(CTR, 0, sizeof(int));
    splitx<<<sxg, 256>>>(x, XHI, XLO);
    sgemm_n4<<<BT / 8, 256>>>(x, sgw, XSG);
    lam_kernel<<<BH, 256>>>(XSG, LAM);
    wsplit<<<wgrid, 256>>>(qw, WHI, WLO, 0);
    wsplit<<<wgrid, 256>>>(kw, WHI, WLO, 1024);
    wsplit<<<wgrid, 256>>>(vw, WHI, WLO, 2048);
    wsplit<<<wgrid, 256>>>(gw, WHI, WLO, 3072);
    wsplit<<<wgrid, 256>>>(sw, WHI, WLO, 4096);
    mmagemm<<<dim3(PD / 128, BT / 128), 256, GSM_TOTAL>>>(XHI, XLO, WHI, WLO, P, PD);

    prep_all<<<PREP_VT, 256>>>(P, LAM, ACC, EHI, ELO, ETHI, ETLO,
                               QHI, QLO, KHI, KLO, VTHI, VTLO);

    attn_fused<<<148, ATHR, ASMEM>>>(QHI, QLO, KHI, KLO, ETHI, ETLO,
                                     EHI, ELO, VTHI, VTLO, ACC, P, gnw, CTR,
                                     XHI, XLO);

    wsplit<<<wgrid, 256>>>(ow, WHI, WLO, 0);
    mmagemm<<<dim3(DD / 128, BT / 128), 256, GSM_TOTAL>>>(XHI, XLO, WHI, WLO, out, DD);
}

// round 12
// speedup vs baseline: 3.1746x; 1.0292x over previous
#include <cuda_runtime.h>
#include <cuda_bf16.h>
#include <math.h>
#include <stdint.h>

#define BB 4
#define TT 2048
#define HH 4
#define DD 1024
#define PD 5120
#define BT (BB*TT)
#define BH 16

__device__ float g_P[(size_t)BT*PD], g_ACC[BT*DD], g_XSG[BT*HH], g_LAM[BH*TT];
__device__ int g_ctr;
__device__ __nv_bfloat16 g_XHI[BT*DD], g_XLO[BT*DD], g_WHI[(size_t)PD*DD], g_WLO[(size_t)PD*DD];
__device__ __nv_bfloat16 g_QHI[BT*DD], g_QLO[BT*DD], g_KHI[BT*DD], g_KLO[BT*DD];
__device__ __nv_bfloat16 g_EHI[BT*DD], g_ELO[BT*DD], g_ETHI[BT*DD], g_ETLO[BT*DD];
__device__ __nv_bfloat16 g_VTHI[BT*DD], g_VTLO[BT*DD];

__device__ __forceinline__ uint32_t smem_to_u32(const void* p) {
    uint32_t a;
    asm("{ .reg .u64 t; cvta.to.shared.u64 t, %1; cvt.u32.u64 %0, t; }" : "=r"(a) : "l"(p));
    return a;
}
#define CP_ASYNC16(d, s) asm volatile("cp.async.cg.shared.global [%0], [%1], 16;" :: "r"(d), "l"(s))
#define CP_COMMIT() asm volatile("cp.async.commit_group;" ::: "memory")
#define LDSM_X4(r, a) \
    asm volatile("ldmatrix.sync.aligned.m8n8.x4.shared.b16 {%0,%1,%2,%3}, [%4];" \
        : "=r"((r)[0]),"=r"((r)[1]),"=r"((r)[2]),"=r"((r)[3]) : "r"(a))
#define MMA_B16(c, a, b0, b1) \
    asm volatile("mma.sync.aligned.m16n8k16.row.col.f32.bf16.bf16.f32 " \
        "{%0,%1,%2,%3},{%4,%5,%6,%7},{%8,%9},{%0,%1,%2,%3};" \
        : "+f"((c)[0]),"+f"((c)[1]),"+f"((c)[2]),"+f"((c)[3]) \
        : "r"((a)[0]),"r"((a)[1]),"r"((a)[2]),"r"((a)[3]), "r"(b0),"r"(b1))
__device__ __forceinline__ void spl(float x, __nv_bfloat16& h, __nv_bfloat16& l) {
    h = __float2bfloat16(x); l = __float2bfloat16(x - __bfloat162float(h));
}
__device__ __forceinline__ uint32_t pkbf(__nv_bfloat16 a, __nv_bfloat16 b) {
    return (uint32_t)*(uint16_t*)&a | ((uint32_t)*(uint16_t*)&b << 16);
}

__global__ void splitx(const float* __restrict__ X, __nv_bfloat16* __restrict__ hi,
                       __nv_bfloat16* __restrict__ lo)
{
    const int i = blockIdx.x * 256 + threadIdx.x;
    float4 v = *(const float4*)(X + (size_t)i * 4);
    __nv_bfloat16 h[4], l[4];
    float vv[4] = {v.x, v.y, v.z, v.w};
#pragma unroll
    for (int j = 0; j < 4; j++) spl(vv[j], h[j], l[j]);
    *(uint2*)(hi + (size_t)i * 4) = *(uint2*)h;
    *(uint2*)(lo + (size_t)i * 4) = *(uint2*)l;
}

__global__ void wsplit(const float* __restrict__ W, __nv_bfloat16* __restrict__ Whi,
                       __nv_bfloat16* __restrict__ Wlo, int noff)
{
    __shared__ float t[32][33];
    const int n0 = blockIdx.x * 32, k0 = blockIdx.y * 32;
    const int tx = threadIdx.x & 31, ty = threadIdx.x >> 5;
#pragma unroll
    for (int i = 0; i < 32; i += 8)
        t[ty + i][tx] = W[(size_t)(k0 + ty + i) * DD + n0 + tx];
    __syncthreads();
#pragma unroll
    for (int i = 0; i < 32; i += 8) {
        __nv_bfloat16 h, l;
        spl(t[tx][ty + i], h, l);
        Whi[(size_t)(noff + n0 + ty + i) * DD + k0 + tx] = h;
        Wlo[(size_t)(noff + n0 + ty + i) * DD + k0 + tx] = l;
    }
}

#define KC 32
#define ASTRIDE 40
#define MAT_B (128*ASTRIDE*2)
#define STG_B (4*MAT_B)
#define GSM_TOTAL (2*STG_B)

// 128 threads, 4 warps in 2x2 grid, warp tile 64x64
__global__ __launch_bounds__(128)
void mmagemm(const __nv_bfloat16* __restrict__ Ahi, const __nv_bfloat16* __restrict__ Alo,
             const __nv_bfloat16* __restrict__ Bhi, const __nv_bfloat16* __restrict__ Blo,
             float* __restrict__ C, int cs)
{
    extern __shared__ char smem[];
    const uint32_t sb = smem_to_u32(smem);
    const int tid = threadIdx.x, l = tid & 31, wid = tid >> 5;
    const int wm = wid >> 1, wn = wid & 1;
    const int m0 = blockIdx.y * 128, n0 = blockIdx.x * 128;
    float c[4][8][4];
#pragma unroll
    for (int i = 0; i < 4; i++)
#pragma unroll
        for (int j = 0; j < 8; j++)
#pragma unroll
            for (int k = 0; k < 4; k++) c[i][j][k] = 0.f;
    const __nv_bfloat16* gsrc[4] = {Ahi + (size_t)m0 * DD, Alo + (size_t)m0 * DD,
                                    Bhi + (size_t)n0 * DD, Blo + (size_t)n0 * DD};
    const int prow = tid >> 2, pseg = tid & 3;     // 32 rows x 4 segs
    {
#pragma unroll
        for (int u = 0; u < 4; u++)
#pragma unroll
            for (int mt = 0; mt < 4; mt++)
                CP_ASYNC16(sb + mt * MAT_B + (prow + u * 32) * 80 + pseg * 16,
                           gsrc[mt] + (size_t)(prow + u * 32) * DD + pseg * 8);
        CP_COMMIT();
    }
    const int arow = (l & 7) + ((l >> 3) & 1) * 8;
    const int acolh = (l >> 4) * 8;
    const int brow = (l & 7) + ((l >> 4) & 1) * 8;
    const int bcolh = ((l >> 3) & 1) * 8;
    for (int ch = 0; ch < DD / KC; ch++) {
        asm volatile("cp.async.wait_group 0;" ::: "memory");
        __syncthreads();
        if (ch + 1 < DD / KC) {
            const int koff = (ch + 1) * KC;
            const uint32_t dbase = sb + ((ch + 1) & 1) * STG_B;
#pragma unroll
            for (int u = 0; u < 4; u++)
#pragma unroll
                for (int mt = 0; mt < 4; mt++)
                    CP_ASYNC16(dbase + mt * MAT_B + (prow + u * 32) * 80 + pseg * 16,
                               gsrc[mt] + (size_t)(prow + u * 32) * DD + koff + pseg * 8);
            CP_COMMIT();
        }
        const uint32_t sA = sb + (ch & 1) * STG_B;
#pragma unroll
        for (int ks = 0; ks < 2; ks++) {
            uint32_t ah[4][4], al[4][4];
#pragma unroll
            for (int mi = 0; mi < 4; mi++) {
                const uint32_t off = (uint32_t)((wm * 64 + mi * 16 + arow) * ASTRIDE + ks * 16 + acolh) * 2;
                LDSM_X4(ah[mi], sA + off);
                LDSM_X4(al[mi], sA + MAT_B + off);
            }
#pragma unroll
            for (int np = 0; np < 4; np++) {
                uint32_t bh[4], bl[4];
                const uint32_t off = (uint32_t)((wn * 64 + np * 16 + brow) * ASTRIDE + ks * 16 + bcolh) * 2;
                LDSM_X4(bh, sA + 2 * MAT_B + off);
                LDSM_X4(bl, sA + 3 * MAT_B + off);
#pragma unroll
                for (int mi = 0; mi < 4; mi++)
#pragma unroll
                    for (int nj = 0; nj < 2; nj++) {
                        MMA_B16(c[mi][np * 2 + nj], ah[mi], bh[nj * 2], bh[nj * 2 + 1]);
                        MMA_B16(c[mi][np * 2 + nj], ah[mi], bl[nj * 2], bl[nj * 2 + 1]);
                        MMA_B16(c[mi][np * 2 + nj], al[mi], bh[nj * 2], bh[nj * 2 + 1]);
                    }
            }
        }
    }
#pragma unroll
    for (int mi = 0; mi < 4; mi++)
#pragma unroll
        for (int nj = 0; nj < 8; nj++) {
            const int r0 = m0 + wm * 64 + mi * 16 + (l >> 2);
            const int cb = n0 + wn * 64 + nj * 8 + (l & 3) * 2;
            *(float2*)(C + (size_t)r0 * cs + cb)       = make_float2(c[mi][nj][0], c[mi][nj][1]);
            *(float2*)(C + (size_t)(r0 + 8) * cs + cb) = make_float2(c[mi][nj][2], c[mi][nj][3]);
        }
}

__global__ void sgemm_n4(const float* __restrict__ X, const float* __restrict__ W,
                         float* __restrict__ O)
{
    const int warp = threadIdx.x >> 5, lane = threadIdx.x & 31;
    const int row = blockIdx.x * 8 + warp;
    const float* x = X + (size_t)row * DD;
    float a0 = 0.f, a1 = 0.f, a2 = 0.f, a3 = 0.f;
    for (int k = lane; k < DD; k += 32) {
        float xv = x[k];
        float4 w = *(const float4*)(W + k * 4);
        a0 += xv * w.x; a1 += xv * w.y; a2 += xv * w.z; a3 += xv * w.w;
    }
#pragma unroll
    for (int o = 16; o; o >>= 1) {
        a0 += __shfl_xor_sync(~0u, a0, o); a1 += __shfl_xor_sync(~0u, a1, o);
        a2 += __shfl_xor_sync(~0u, a2, o); a3 += __shfl_xor_sync(~0u, a3, o);
    }
    if (lane == 0) *(float4*)(O + row * 4) = make_float4(a0, a1, a2, a3);
}

__global__ void lam_kernel(const float* __restrict__ XSG, float* __restrict__ LAM)
{
    const int b = blockIdx.x >> 2, h = blockIdx.x & 3;
    const int tid = threadIdx.x;
    __shared__ float ssum[256];
    float loc[8], run = 0.f;
    const int t0 = tid * 8;
#pragma unroll
    for (int u = 0; u < 8; u++) {
        float x = XSG[(size_t)(b * TT + t0 + u) * HH + h];
        float lg = (x >= 0.f) ? -log1pf(expf(-x)) : (x - log1pf(expf(x)));
        run += lg * (1.f / 16.f);
        loc[u] = run;
    }
    ssum[tid] = run;
    __syncthreads();
    for (int off = 1; off < 256; off <<= 1) {
        float v = (tid >= off) ? ssum[tid - off] : 0.f;
        __syncthreads();
        ssum[tid] += v;
        __syncthreads();
    }
    float excl = ssum[tid] - run;
#pragma unroll
    for (int u = 0; u < 8; u++)
        LAM[(size_t)(b * HH + h) * TT + t0 + u] = expf(excl + loc[u]);
}

#define PREP_SCAN 128
#define PREP_ROPE (PREP_SCAN + 16384)
#define PREP_VT   (PREP_ROPE + 8192)

__global__ __launch_bounds__(256)
void prep_all(const float* __restrict__ P, const float* __restrict__ LAM,
              float* __restrict__ ACC,
              __nv_bfloat16* EH, __nv_bfloat16* EL,
              __nv_bfloat16* ETH, __nv_bfloat16* ETL,
              __nv_bfloat16* QH, __nv_bfloat16* QL,
              __nv_bfloat16* KH, __nv_bfloat16* KL,
              __nv_bfloat16* VTH, __nv_bfloat16* VTL)
{
    const int bid = blockIdx.x;
    if (bid < PREP_SCAN) {
        __shared__ float sums[8][33];
        __shared__ uint16_t tph[8][32][33], tpl[8][32][33];
        const int bh = bid & 15, b = bh >> 2, h = bh & 3;
        const int ml = threadIdx.x & 31, tc = threadIdx.x >> 5;
        const int m0 = (bid >> 4) * 32;
        const int m = m0 + ml;
        const size_t src = (size_t)(b * TT) * PD + 4096 + h * 256 + m;
        const size_t dR = (size_t)bh * TT * 256 + m;
        const size_t dTb = (size_t)bh * TT * 256;
        float a = 0.f;
        for (int t = tc * 256; t < tc * 256 + 256; t++)
            a += expf(fminf(fmaxf(P[src + (size_t)t * PD], -32.f), 32.f));
        sums[tc][ml] = a;
        __syncthreads();
        a = 0.f;
        for (int p = 0; p < tc; p++) a += sums[p][ml];
        for (int seg = 0; seg < 8; seg++) {
            const int tb = tc * 256 + seg * 32;
#pragma unroll 4
            for (int u = 0; u < 32; u++) {
                const int t = tb + u;
                float e = expf(fminf(fmaxf(P[src + (size_t)t * PD], -32.f), 32.f));
                a += e;
                ACC[dR + (size_t)t * 256] = a;
                __nv_bfloat16 hh, ll;
                spl(e, hh, ll);
                EH[dR + (size_t)t * 256] = hh; EL[dR + (size_t)t * 256] = ll;
                tph[tc][u][ml] = *(uint16_t*)&hh;
                tpl[tc][u][ml] = *(uint16_t*)&ll;
            }
            __syncwarp();
#pragma unroll 4
            for (int mm = 0; mm < 32; mm++) {
                const size_t d = dTb + (size_t)(m0 + mm) * TT + tb + ml;
                uint16_t vh = tph[tc][ml][mm], vl = tpl[tc][ml][mm];
                ETH[d] = *(__nv_bfloat16*)&vh;
                ETL[d] = *(__nv_bfloat16*)&vl;
            }
            __syncwarp();
        }
    } else if (bid < PREP_ROPE) {
        const int idx = (bid - PREP_SCAN) * 256 + threadIdx.x;
        const int i = idx & 127, h = (idx >> 7) & 3, t = (idx >> 9) & 2047, b = idx >> 20;
        float inv = powf(10000.f, -(float)i * (1.f / 128.f));
        float sn, cs; sincosf((float)t * inv, &sn, &cs);
        const size_t src = (size_t)(b * TT + t) * PD + h * 256;
        const size_t dst = ((size_t)(b * HH + h) * TT + t) * 256;
        float lam = LAM[(size_t)(b * HH + h) * TT + t];
        float q1 = P[src + i], q2 = P[src + i + 128];
        float k1 = P[src + 1024 + i], k2 = P[src + 1024 + i + 128];
        float o0 = (q1 * cs - q2 * sn) * 0.0625f, o1 = (q2 * cs + q1 * sn) * 0.0625f;
        float o2 = (k1 * cs - k2 * sn) * lam,     o3 = (k2 * cs + k1 * sn) * lam;
        __nv_bfloat16 hh, ll;
        spl(o0, hh, ll); QH[dst + i] = hh;       QL[dst + i] = ll;
        spl(o1, hh, ll); QH[dst + i + 128] = hh; QL[dst + i + 128] = ll;
        spl(o2, hh, ll); KH[dst + i] = hh;       KL[dst + i] = ll;
        spl(o3, hh, ll); KH[dst + i + 128] = hh; KL[dst + i + 128] = ll;
    } else {
        __shared__ float tile[32][33];
        const int id = bid - PREP_ROPE;
        const int t0 = (id & 63) * 32, v0 = ((id >> 6) & 7) * 32, bh = id >> 9;
        const int b = bh >> 2, h = bh & 3;
        const int tx = threadIdx.x & 31, ty = threadIdx.x >> 5;
#pragma unroll
        for (int i = 0; i < 32; i += 8)
            tile[ty + i][tx] = P[(size_t)(b * TT + t0 + ty + i) * PD + 2048 + h * 256 + v0 + tx];
        __syncthreads();
#pragma unroll
        for (int i = 0; i < 32; i += 8) {
            __nv_bfloat16 hh, ll;
            spl(tile[tx][ty + i], hh, ll);
            const size_t d = (size_t)bh * TT * 256 + (size_t)(v0 + ty + i) * TT + t0 + tx;
            VTH[d] = hh; VTL[d] = ll;
        }
    }
}

// ---- fused attention: persistent work-stealing, 512 threads ----
#define QSH 0
#define QSL 33792
#define YSH 67584
#define YSL 101376
#define ZSH 135168
#define ZSL 172032
#define SSH 208896
#define SSL 218112
#define SIDX 227328
#define ASMEM 227344
#define XSTR 264
#define ZSTR 72
#define ATHR 512
#define NTILE 512

__device__ __forceinline__ void ld_xy(uint32_t dH, uint32_t dL,
    const __nv_bfloat16* sH, const __nv_bfloat16* sL, int tid)
{
    const int pr = tid >> 3, ps = tid & 7;
    const __nv_bfloat16* h = sH + (size_t)pr * 256;
    const __nv_bfloat16* l = sL + (size_t)pr * 256;
#pragma unroll
    for (int s = ps; s < 32; s += 8) {
        CP_ASYNC16(dH + pr * XSTR * 2 + s * 16, h + s * 8);
        CP_ASYNC16(dL + pr * XSTR * 2 + s * 16, l + s * 8);
    }
}
__device__ __forceinline__ void ld_z(uint32_t sb,
    const __nv_bfloat16* zH, const __nv_bfloat16* zL, int tid)
{
    const int row = tid >> 1, hf = tid & 1;
    const __nv_bfloat16* h = zH + (size_t)row * TT;
    const __nv_bfloat16* l = zL + (size_t)row * TT;
#pragma unroll
    for (int s = hf * 4; s < hf * 4 + 4; s++) {
        CP_ASYNC16(sb + ZSH + row * ZSTR * 2 + s * 16, h + s * 8);
        CP_ASYNC16(sb + ZSL + row * ZSTR * 2 + s * 16, l + s * 8);
    }
}

__device__ __forceinline__ void stage_loop(char* sm, uint32_t sb, int qi, int tid,
    const __nv_bfloat16* YHb, const __nv_bfloat16* YLb,
    const __nv_bfloat16* ZHb, const __nv_bfloat16* ZLb, float ok[8][4])
{
    const int l = tid & 31, wid = tid >> 5, wm = wid >> 2, wn = wid & 3;
    const int arow = (l & 7) + ((l >> 3) & 1) * 8, acolh = (l >> 4) * 8;
    const int brow = (l & 7) + ((l >> 4) & 1) * 8, bcolh = ((l >> 3) & 1) * 8;
    ld_xy(sb + YSH, sb + YSL, YHb, YLb, tid); CP_COMMIT();
    ld_z(sb, ZHb, ZLb, tid); CP_COMMIT();
    for (int kc = 0; kc <= qi; kc++) {
        asm volatile("cp.async.wait_group 1;" ::: "memory");
        __syncthreads();
        float s4[2][4];
#pragma unroll
        for (int j = 0; j < 2; j++)
#pragma unroll
            for (int k = 0; k < 4; k++) s4[j][k] = 0.f;
#pragma unroll 4
        for (int ks = 0; ks < 16; ks++) {
            uint32_t ah[4], al[4], bhf[4], blf[4];
            const uint32_t ao = (uint32_t)((wm * 16 + arow) * XSTR + ks * 16 + acolh) * 2;
            LDSM_X4(ah, sb + QSH + ao);
            LDSM_X4(al, sb + QSL + ao);
            const uint32_t bo = (uint32_t)((wn * 16 + brow) * XSTR + ks * 16 + bcolh) * 2;
            LDSM_X4(bhf, sb + YSH + bo);
            LDSM_X4(blf, sb + YSL + bo);
#pragma unroll
            for (int nj = 0; nj < 2; nj++) {
                MMA_B16(s4[nj], ah, bhf[nj * 2], bhf[nj * 2 + 1]);
                MMA_B16(s4[nj], ah, blf[nj * 2], blf[nj * 2 + 1]);
                MMA_B16(s4[nj], al, bhf[nj * 2], bhf[nj * 2 + 1]);
            }
        }
        __syncthreads();
        const bool diag = (kc == qi);
#pragma unroll
        for (int nj = 0; nj < 2; nj++)
#pragma unroll
            for (int hf = 0; hf < 2; hf++) {
                const int r = wm * 16 + (l >> 2) + hf * 8;
                const int c = wn * 16 + nj * 8 + (l & 3) * 2;
                float v0 = s4[nj][hf * 2], v1 = s4[nj][hf * 2 + 1];
                if (diag) { if (c > r) v0 = 0.f; if (c + 1 > r) v1 = 0.f; }
                __nv_bfloat16 h0, l0, h1, l1;
                spl(v0, h0, l0); spl(v1, h1, l1);
                *(uint32_t*)(sm + SSH + (r * ZSTR + c) * 2) = pkbf(h0, h1);
                *(uint32_t*)(sm + SSL + (r * ZSTR + c) * 2) = pkbf(l0, l1);
            }
        if (kc < qi) {
            ld_xy(sb + YSH, sb + YSL, YHb + (size_t)(kc + 1) * 64 * 256,
                  YLb + (size_t)(kc + 1) * 64 * 256, tid);
            CP_COMMIT();
        }
        if (kc == qi) asm volatile("cp.async.wait_group 0;" ::: "memory");
        else          asm volatile("cp.async.wait_group 1;" ::: "memory");
        __syncthreads();
#pragma unroll
        for (int ks = 0; ks < 4; ks++) {
            uint32_t ah[4], al[4];
            const uint32_t ao = (uint32_t)((wm * 16 + arow) * ZSTR + ks * 16 + acolh) * 2;
            LDSM_X4(ah, sb + SSH + ao);
            LDSM_X4(al, sb + SSL + ao);
#pragma unroll
            for (int np = 0; np < 4; np++) {
                uint32_t bhf[4], blf[4];
                const uint32_t bo = (uint32_t)((wn * 64 + np * 16 + brow) * ZSTR + ks * 16 + bcolh) * 2;
                LDSM_X4(bhf, sb + ZSH + bo);
                LDSM_X4(blf, sb + ZSL + bo);
#pragma unroll
                for (int nj = 0; nj < 2; nj++) {
                    MMA_B16(ok[np * 2 + nj], ah, bhf[nj * 2], bhf[nj * 2 + 1]);
                    MMA_B16(ok[np * 2 + nj], ah, blf[nj * 2], blf[nj * 2 + 1]);
                    MMA_B16(ok[np * 2 + nj], al, bhf[nj * 2], bhf[nj * 2 + 1]);
                }
            }
        }
        __syncthreads();
        if (kc < qi) { ld_z(sb, ZHb + (kc + 1) * 64, ZLb + (kc + 1) * 64, tid); CP_COMMIT(); }
    }
}

__device__ __forceinline__ void dump_ok(char* sm, float ok[8][4], int wm, int wn, int l)
{
    float* OKS = (float*)(sm + YSH);
#pragma unroll
    for (int idx = 0; idx < 8; idx++)
#pragma unroll
        for (int hf = 0; hf < 2; hf++) {
            const int r = wm * 16 + (l >> 2) + hf * 8;
            const int c = wn * 64 + idx * 8 + (l & 3) * 2;
            *(float2*)&OKS[r * 258 + c] = make_float2(ok[idx][hf * 2], ok[idx][hf * 2 + 1]);
            ok[idx][hf * 2] = 0.f; ok[idx][hf * 2 + 1] = 0.f;
        }
}

__global__ __launch_bounds__(ATHR)
void attn_fused(const __nv_bfloat16* __restrict__ QH, const __nv_bfloat16* __restrict__ QL,
                const __nv_bfloat16* __restrict__ KH, const __nv_bfloat16* __restrict__ KL,
                const __nv_bfloat16* __restrict__ ETH, const __nv_bfloat16* __restrict__ ETL,
                const __nv_bfloat16* __restrict__ EH, const __nv_bfloat16* __restrict__ EL,
                const __nv_bfloat16* __restrict__ VTH, const __nv_bfloat16* __restrict__ VTL,
                const float* __restrict__ ACC, const float* __restrict__ P,
                const float* __restrict__ gnw, int* __restrict__ ctr,
                __nv_bfloat16* __restrict__ AH, __nv_bfloat16* __restrict__ AL)
{
    extern __shared__ char sm[];
    const uint32_t sb = smem_to_u32(sm);
    const int tid = threadIdx.x, l = tid & 31, wid = tid >> 5, wm = wid >> 2, wn = wid & 3;

    float ok[8][4];
#pragma unroll
    for (int j = 0; j < 8; j++)
#pragma unroll
        for (int k = 0; k < 4; k++) ok[j][k] = 0.f;

    for (;;) {
        if (tid == 0) *(int*)(sm + SIDX) = atomicAdd(ctr, 1);
        __syncthreads();
        const int widx = *(int*)(sm + SIDX);
        __syncthreads();
        if (widx >= NTILE) break;

        const int qi = 31 - (widx >> 4);
        const int bh = widx & 15;
        const int b = bh >> 2, h = bh & 3;
        const int qBase = qi * 64;
        const size_t base = (size_t)bh * TT * 256;

        ld_xy(sb + QSH, sb + QSL, QH + base + (size_t)qBase * 256,
              QL + base + (size_t)qBase * 256, tid);
        stage_loop(sm, sb, qi, tid, KH + base, KL + base, ETH + base, ETL + base, ok);

        dump_ok(sm, ok, wm, wn, l);
        __syncthreads();
        float* OKS = (float*)(sm + YSH);
#pragma unroll
        for (int i = 0; i < 4; i++) {
            const int r = wid * 4 + i, t = qBase + r;
            float v[8], acr[8], mx = -3.4e38f;
#pragma unroll
            for (int j = 0; j < 8; j++) {
                const int c = j * 32 + l;
                acr[j] = ACC[base + (size_t)t * 256 + c];
                v[j] = OKS[r * 258 + c] / acr[j];
                mx = fmaxf(mx, v[j]);
            }
#pragma unroll
            for (int o = 16; o; o >>= 1) mx = fmaxf(mx, __shfl_xor_sync(~0u, mx, o));
            float e[8], s = 0.f;
#pragma unroll
            for (int j = 0; j < 8; j++) { e[j] = expf(v[j] - mx); s += e[j]; }
#pragma unroll
            for (int o = 16; o; o >>= 1) s += __shfl_xor_sync(~0u, s, o);
            const float inv = 1.f / s;
#pragma unroll
            for (int j = 0; j < 8; j++) {
                const int c = j * 32 + l;
                __nv_bfloat16 hh, ll;
                spl(e[j] * inv / acr[j], hh, ll);
                *(__nv_bfloat16*)(sm + QSH + (r * XSTR + c) * 2) = hh;
                *(__nv_bfloat16*)(sm + QSL + (r * XSTR + c) * 2) = ll;
            }
        }
        __syncthreads();

        stage_loop(sm, sb, qi, tid, EH + base, EL + base, VTH + base, VTL + base, ok);

        dump_ok(sm, ok, wm, wn, l);
        __syncthreads();
#pragma unroll
        for (int i = 0; i < 4; i++) {
            const int r = wid * 4 + i, t = qBase + r;
            float vv[8], ss = 0.f;
#pragma unroll
            for (int j = 0; j < 8; j++) { vv[j] = OKS[r * 258 + j * 32 + l]; ss += vv[j] * vv[j]; }
#pragma unroll
            for (int o = 16; o; o >>= 1) ss += __shfl_xor_sync(~0u, ss, o);
            const float rn = rsqrtf(ss * (1.f / 256.f) + 1e-5f);
#pragma unroll
            for (int j = 0; j < 8; j++) {
                const int c = j * 32 + l;
                float gg = P[(size_t)(b * TT + t) * PD + 3072 + h * 256 + c];
                float sig = 1.f / (1.f + expf(-gg));
                float act = vv[j] * rn * gnw[c] * gg * sig;
                __nv_bfloat16 hh, ll;
                spl(act, hh, ll);
                AH[(size_t)(b * TT + t) * DD + h * 256 + c] = hh;
                AL[(size_t)(b * TT + t) * DD + h * 256 + c] = ll;
            }
        }
        __syncthreads();
    }
}

extern "C" void kernel_launch(void* const* d_in, const int* in_sizes, int n_in,
                              void* d_out, int out_size)
{
    const float* x   = (const float*)d_in[0];
    const float* qw  = (const float*)d_in[1];
    const float* kw  = (const float*)d_in[2];
    const float* vw  = (const float*)d_in[3];
    const float* gw  = (const float*)d_in[4];
    const float* sw  = (const float*)d_in[5];
    const float* sgw = (const float*)d_in[6];
    const float* gnw = (const float*)d_in[7];
    const float* ow  = (const float*)d_in[8];
    float* out = (float*)d_out;

    float *P, *ACC, *XSG, *LAM;
    int* CTR;
    __nv_bfloat16 *XHI, *XLO, *WHI, *WLO, *QHI, *QLO, *KHI, *KLO;
    __nv_bfloat16 *EHI, *ELO, *ETHI, *ETLO, *VTHI, *VTLO;
    cudaGetSymbolAddress((void**)&P, g_P);     cudaGetSymbolAddress((void**)&ACC, g_ACC);
    cudaGetSymbolAddress((void**)&XSG, g_XSG); cudaGetSymbolAddress((void**)&LAM, g_LAM);
    cudaGetSymbolAddress((void**)&CTR, g_ctr);
    cudaGetSymbolAddress((void**)&XHI, g_XHI); cudaGetSymbolAddress((void**)&XLO, g_XLO);
    cudaGetSymbolAddress((void**)&WHI, g_WHI); cudaGetSymbolAddress((void**)&WLO, g_WLO);
    cudaGetSymbolAddress((void**)&QHI, g_QHI); cudaGetSymbolAddress((void**)&QLO, g_QLO);
    cudaGetSymbolAddress((void**)&KHI, g_KHI); cudaGetSymbolAddress((void**)&KLO, g_KLO);
    cudaGetSymbolAddress((void**)&EHI, g_EHI); cudaGetSymbolAddress((void**)&ELO, g_ELO);
    cudaGetSymbolAddress((void**)&ETHI, g_ETHI); cudaGetSymbolAddress((void**)&ETLO, g_ETLO);
    cudaGetSymbolAddress((void**)&VTHI, g_VTHI); cudaGetSymbolAddress((void**)&VTLO, g_VTLO);

    static int done = 0;
    if (!done) {
        cudaFuncSetAttribute(mmagemm, cudaFuncAttributeMaxDynamicSharedMemorySize, GSM_TOTAL);
        cudaFuncSetAttribute(attn_fused, cudaFuncAttributeMaxDynamicSharedMemorySize, ASMEM);
        done = 1;
    }

    const dim3 wgrid(32, 32);
    const int sxg = (BT * DD / 4) / 256;

    cudaMemsetAsync(CTR, 0, sizeof(int));
    splitx<<<sxg, 256>>>(x, XHI, XLO);
    sgemm_n4<<<BT / 8, 256>>>(x, sgw, XSG);
    lam_kernel<<<BH, 256>>>(XSG, LAM);
    wsplit<<<wgrid, 256>>>(qw, WHI, WLO, 0);
    wsplit<<<wgrid, 256>>>(kw, WHI, WLO, 1024);
    wsplit<<<wgrid, 256>>>(vw, WHI, WLO, 2048);
    wsplit<<<wgrid, 256>>>(gw, WHI, WLO, 3072);
    wsplit<<<wgrid, 256>>>(sw, WHI, WLO, 4096);
    mmagemm<<<dim3(PD / 128, BT / 128), 128, GSM_TOTAL>>>(XHI, XLO, WHI, WLO, P, PD);

    prep_all<<<PREP_VT, 256>>>(P, LAM, ACC, EHI, ELO, ETHI, ETLO,
                               QHI, QLO, KHI, KLO, VTHI, VTLO);

    attn_fused<<<148, ATHR, ASMEM>>>(QHI, QLO, KHI, KLO, ETHI, ETLO,
                                     EHI, ELO, VTHI, VTLO, ACC, P, gnw, CTR,
                                     XHI, XLO);

    wsplit<<<wgrid, 256>>>(ow, WHI, WLO, 0);
    mmagemm<<<dim3(DD / 128, BT / 128), 128, GSM_TOTAL>>>(XHI, XLO, WHI, WLO, out, DD);
}